// round 1
// baseline (speedup 1.0000x reference)
#include <cuda_runtime.h>

// Problem constants
#define BB   32
#define SRC  1024
#define SEQ  128
#define CTX  5
#define DM   512
#define KPY  (CTX*DM)   // 2560

// Scratch (no allocations allowed -> device globals)
__device__ float g_xe[(size_t)BB*SRC*DM];   // 64 MB : gathered source embeddings
__device__ float g_py[(size_t)BB*SEQ*DM];   //  8 MB : projected target context

// ---------------------------------------------------------------------------
// Kernel 1: gather xe[b, s, :] = F_emb[x[b,s], :]
// grid = B*SRC blocks, 128 threads, float4 per thread (512 floats/row)
// ---------------------------------------------------------------------------
__global__ void gather_xe_kernel(const int* __restrict__ x,
                                 const float* __restrict__ F) {
    int row = blockIdx.x;                 // b*SRC + i
    int tok = __ldg(&x[row]);
    const float4* src = (const float4*)(F + (size_t)tok * DM);
    float4* dst = (float4*)(g_xe + (size_t)row * DM);
    dst[threadIdx.x] = __ldg(&src[threadIdx.x]);
}

// ---------------------------------------------------------------------------
// Kernel 2: py = yce @ P_w + P_b
//   M = B*SEQ = 4096, K = 2560, N = 512
//   A[m,k] gathered on the fly: tok = yc[m*5 + k/512]; G_emb[tok, k%512]
// 128x128 tile, BK=8, 256 threads, 8x8 micro-tile
// ---------------------------------------------------------------------------
__global__ void gemm_py_kernel(const int* __restrict__ yc,
                               const float* __restrict__ G,
                               const float* __restrict__ Pw,
                               const float* __restrict__ Pb) {
    __shared__ float As[8][128];
    __shared__ float Bs[8][128];

    const int m0 = blockIdx.y * 128;          // 32 tiles over M=4096
    const int n0 = blockIdx.x * 128;          // 4 tiles over N=512
    const int tid = threadIdx.x;

    const int rowb = (tid >> 4) * 8;          // 0..120
    const int colb = (tid & 15) * 8;          // 0..120

    // A loader: row = tid/2 in tile, 4 consecutive k per thread
    const int la_row = tid >> 1;
    const int la_k   = (tid & 1) * 4;
    // B loader: k = tid/32, n = (tid%32)*4
    const int lb_k = tid >> 5;
    const int lb_n = (tid & 31) * 4;

    float acc[8][8];
#pragma unroll
    for (int i = 0; i < 8; i++)
#pragma unroll
        for (int j = 0; j < 8; j++) acc[i][j] = 0.f;

    for (int k0 = 0; k0 < KPY; k0 += 8) {
        // ---- load A tile (gathered) ----
        {
            const int m  = m0 + la_row;
            const int kk = k0 + la_k;               // 4 consecutive k, same 512-chunk
            const int c    = kk >> 9;               // context slot
            const int koff = kk & 511;
            const int tok = __ldg(&yc[m * CTX + c]);
            float4 av = __ldg((const float4*)(G + (size_t)tok * DM + koff));
            As[la_k + 0][la_row] = av.x;
            As[la_k + 1][la_row] = av.y;
            As[la_k + 2][la_row] = av.z;
            As[la_k + 3][la_row] = av.w;
        }
        // ---- load B tile (P_w is [K, N] row-major, n-contiguous) ----
        {
            float4 bv = __ldg((const float4*)(Pw + (size_t)(k0 + lb_k) * DM + n0 + lb_n));
            *(float4*)&Bs[lb_k][lb_n] = bv;
        }
        __syncthreads();

#pragma unroll
        for (int k = 0; k < 8; k++) {
            float a[8], b[8];
#pragma unroll
            for (int i = 0; i < 8; i++) a[i] = As[k][rowb + i];
#pragma unroll
            for (int j = 0; j < 8; j++) b[j] = Bs[k][colb + j];
#pragma unroll
            for (int i = 0; i < 8; i++)
#pragma unroll
                for (int j = 0; j < 8; j++) acc[i][j] += a[i] * b[j];
        }
        __syncthreads();
    }

    // epilogue: + bias, write g_py
#pragma unroll
    for (int i = 0; i < 8; i++) {
        const int m = m0 + rowb + i;
#pragma unroll
        for (int j = 0; j < 8; j++) {
            const int n = n0 + colb + j;
            g_py[(size_t)m * DM + n] = acc[i][j] + __ldg(&Pb[n]);
        }
    }
}

// ---------------------------------------------------------------------------
// Kernel 3: logits (pre-softmax, pre-mask), per batch:
//   C[s, x] = sum_d py[b,s,d] * xe[b,x,d]   (NT: both K-contiguous)
//   M = 128 (one tile), N = 1024 (8 tiles), K = 512
// writes into d_out's "a" region
// ---------------------------------------------------------------------------
__global__ void gemm_logits_kernel(float* __restrict__ a_out) {
    __shared__ float As[8][128];
    __shared__ float Bs[8][128];

    const int b  = blockIdx.y;
    const int n0 = blockIdx.x * 128;
    const int tid = threadIdx.x;

    const float* A  = g_py + (size_t)b * SEQ * DM;   // [128, 512]
    const float* Bm = g_xe + (size_t)b * SRC * DM;   // [1024, 512]

    const int rowb = (tid >> 4) * 8;
    const int colb = (tid & 15) * 8;
    const int la_row = tid >> 1;
    const int la_k   = (tid & 1) * 4;

    float acc[8][8];
#pragma unroll
    for (int i = 0; i < 8; i++)
#pragma unroll
        for (int j = 0; j < 8; j++) acc[i][j] = 0.f;

    for (int k0 = 0; k0 < DM; k0 += 8) {
        {
            float4 av = *(const float4*)(A + (size_t)la_row * DM + k0 + la_k);
            As[la_k + 0][la_row] = av.x;
            As[la_k + 1][la_row] = av.y;
            As[la_k + 2][la_row] = av.z;
            As[la_k + 3][la_row] = av.w;
            float4 bv = *(const float4*)(Bm + (size_t)(n0 + la_row) * DM + k0 + la_k);
            Bs[la_k + 0][la_row] = bv.x;
            Bs[la_k + 1][la_row] = bv.y;
            Bs[la_k + 2][la_row] = bv.z;
            Bs[la_k + 3][la_row] = bv.w;
        }
        __syncthreads();
#pragma unroll
        for (int k = 0; k < 8; k++) {
            float a[8], bb[8];
#pragma unroll
            for (int i = 0; i < 8; i++) a[i] = As[k][rowb + i];
#pragma unroll
            for (int j = 0; j < 8; j++) bb[j] = Bs[k][colb + j];
#pragma unroll
            for (int i = 0; i < 8; i++)
#pragma unroll
                for (int j = 0; j < 8; j++) acc[i][j] += a[i] * bb[j];
        }
        __syncthreads();
    }

    float* C = a_out + (size_t)b * SEQ * SRC;
#pragma unroll
    for (int i = 0; i < 8; i++) {
        const int s = rowb + i;
#pragma unroll
        for (int j = 0; j < 8; j++) {
            const int xcol = n0 + colb + j;
            C[(size_t)s * SRC + xcol] = acc[i][j];
        }
    }
}

// ---------------------------------------------------------------------------
// Kernel 4: masked softmax in-place over SRC=1024 per (b, s) row
// grid = B*SEQ, 256 threads, 4 elements each
// ---------------------------------------------------------------------------
__global__ void softmax_mask_kernel(float* __restrict__ a,
                                    const int* __restrict__ x) {
    const int row = blockIdx.x;          // b*SEQ + s
    const int b = row / SEQ;
    float* p = a + (size_t)row * SRC;
    const int* xb = x + b * SRC;
    const int t = threadIdx.x;

    float v[4];
    float mx = -1e30f;
#pragma unroll
    for (int i = 0; i < 4; i++) {
        const int col = t + i * 256;
        float val = p[col];
        if (__ldg(&xb[col]) == 0) val -= 1e9f;
        v[i] = val;
        mx = fmaxf(mx, val);
    }
    __shared__ float red[256];
    red[t] = mx; __syncthreads();
#pragma unroll
    for (int s = 128; s > 0; s >>= 1) {
        if (t < s) red[t] = fmaxf(red[t], red[t + s]);
        __syncthreads();
    }
    mx = red[0]; __syncthreads();

    float sum = 0.f;
#pragma unroll
    for (int i = 0; i < 4; i++) { v[i] = __expf(v[i] - mx); sum += v[i]; }
    red[t] = sum; __syncthreads();
#pragma unroll
    for (int s = 128; s > 0; s >>= 1) {
        if (t < s) red[t] += red[t + s];
        __syncthreads();
    }
    const float inv = 1.0f / red[0];
#pragma unroll
    for (int i = 0; i < 4; i++) p[t + i * 256] = v[i] * inv;
}

// ---------------------------------------------------------------------------
// Kernel 5: out[b, s, d] = sum_x a[b,s,x] * xe[b,x,d]   (NN)
//   M = 128 (1 tile), N = 512 (4 tiles), K = 1024
// ---------------------------------------------------------------------------
__global__ void gemm_out_kernel(const float* __restrict__ a_in,
                                float* __restrict__ out) {
    __shared__ float As[8][128];
    __shared__ float Bs[8][128];

    const int b  = blockIdx.y;
    const int n0 = blockIdx.x * 128;
    const int tid = threadIdx.x;

    const float* A  = a_in + (size_t)b * SEQ * SRC;   // [128, 1024] k-contig
    const float* Bm = g_xe + (size_t)b * SRC * DM;    // [1024, 512] n-contig

    const int rowb = (tid >> 4) * 8;
    const int colb = (tid & 15) * 8;
    const int la_row = tid >> 1;
    const int la_k   = (tid & 1) * 4;
    const int lb_k = tid >> 5;
    const int lb_n = (tid & 31) * 4;

    float acc[8][8];
#pragma unroll
    for (int i = 0; i < 8; i++)
#pragma unroll
        for (int j = 0; j < 8; j++) acc[i][j] = 0.f;

    for (int k0 = 0; k0 < SRC; k0 += 8) {
        {
            float4 av = *(const float4*)(A + (size_t)la_row * SRC + k0 + la_k);
            As[la_k + 0][la_row] = av.x;
            As[la_k + 1][la_row] = av.y;
            As[la_k + 2][la_row] = av.z;
            As[la_k + 3][la_row] = av.w;
            float4 bv = *(const float4*)(Bm + (size_t)(k0 + lb_k) * DM + n0 + lb_n);
            *(float4*)&Bs[lb_k][lb_n] = bv;
        }
        __syncthreads();
#pragma unroll
        for (int k = 0; k < 8; k++) {
            float a[8], bb[8];
#pragma unroll
            for (int i = 0; i < 8; i++) a[i] = As[k][rowb + i];
#pragma unroll
            for (int j = 0; j < 8; j++) bb[j] = Bs[k][colb + j];
#pragma unroll
            for (int i = 0; i < 8; i++)
#pragma unroll
                for (int j = 0; j < 8; j++) acc[i][j] += a[i] * bb[j];
        }
        __syncthreads();
    }

    float* C = out + (size_t)b * SEQ * DM;
#pragma unroll
    for (int i = 0; i < 8; i++) {
        const int s = rowb + i;
#pragma unroll
        for (int j = 0; j < 8; j++) {
            const int d = n0 + colb + j;
            C[(size_t)s * DM + d] = acc[i][j];
        }
    }
}

// ---------------------------------------------------------------------------
extern "C" void kernel_launch(void* const* d_in, const int* in_sizes, int n_in,
                              void* d_out, int out_size) {
    const int*   x   = (const int*)  d_in[0];   // [32, 1024]
    const int*   yc  = (const int*)  d_in[1];   // [32, 640]
    const float* F   = (const float*)d_in[2];   // [32000, 512]
    const float* G   = (const float*)d_in[3];   // [32000, 512]
    const float* Pw  = (const float*)d_in[4];   // [2560, 512]
    const float* Pb  = (const float*)d_in[5];   // [512]

    float* out   = (float*)d_out;                       // [32,128,512]
    float* a_out = out + (size_t)BB * SEQ * DM;         // [32,128,1024]

    gather_xe_kernel<<<BB * SRC, 128>>>(x, F);
    gemm_py_kernel<<<dim3(DM / 128, (BB * SEQ) / 128), 256>>>(yc, G, Pw, Pb);
    gemm_logits_kernel<<<dim3(SRC / 128, BB), 256>>>(a_out);
    softmax_mask_kernel<<<BB * SEQ, 256>>>(a_out, x);
    gemm_out_kernel<<<dim3(DM / 128, BB), 256>>>(a_out, out);
}

// round 2
// speedup vs baseline: 1.3846x; 1.3846x over previous
#include <cuda_runtime.h>

// Problem constants
#define BB   32
#define SRC  1024
#define SEQ  128
#define CTX  5
#define DM   512
#define KPY  (CTX*DM)   // 2560
#define BK   16

// Scratch (no allocations allowed -> device globals)
__device__ float g_xe[(size_t)BB*SRC*DM];   // 64 MB : gathered source embeddings
__device__ float g_py[(size_t)BB*SEQ*DM];   //  8 MB : projected target context

// ---------------------------------------------------------------------------
// Kernel 1: gather xe[b, s, :] = F_emb[x[b,s], :]
// ---------------------------------------------------------------------------
__global__ void gather_xe_kernel(const int* __restrict__ x,
                                 const float* __restrict__ F) {
    int row = blockIdx.x;                 // b*SRC + i
    int tok = __ldg(&x[row]);
    const float4* src = (const float4*)(F + (size_t)tok * DM);
    float4* dst = (float4*)(g_xe + (size_t)row * DM);
    dst[threadIdx.x] = __ldg(&src[threadIdx.x]);
}

// ---------------------------------------------------------------------------
// Packed-f32x2 inner product tile: 8x8 per thread as 8x4 packed u64 accs.
// One k-slab = BK=16 steps from double-buffered smem.
// ---------------------------------------------------------------------------
__device__ __forceinline__ void fma_tile(const float (*__restrict__ As)[128],
                                         const float (*__restrict__ Bs)[128],
                                         int rowb, int colb,
                                         unsigned long long acc[8][4]) {
#pragma unroll
    for (int k = 0; k < BK; k++) {
        float4 av0 = *(const float4*)&As[k][rowb];
        float4 av1 = *(const float4*)&As[k][rowb + 4];
        ulonglong2 bv0 = *(const ulonglong2*)&Bs[k][colb];
        ulonglong2 bv1 = *(const ulonglong2*)&Bs[k][colb + 4];
        unsigned long long b2[4] = {bv0.x, bv0.y, bv1.x, bv1.y};
        float a[8] = {av0.x, av0.y, av0.z, av0.w, av1.x, av1.y, av1.z, av1.w};
#pragma unroll
        for (int i = 0; i < 8; i++) {
            unsigned long long a2;
            asm("mov.b64 %0, {%1, %1};" : "=l"(a2) : "r"(__float_as_uint(a[i])));
#pragma unroll
            for (int j = 0; j < 4; j++)
                asm("fma.rn.f32x2 %0, %1, %2, %0;"
                    : "+l"(acc[i][j]) : "l"(a2), "l"(b2[j]));
        }
    }
}

// ---------------------------------------------------------------------------
// Kernel 2: py = yce @ P_w + P_b   (M=4096, K=2560, N=512)
//   A gathered on the fly from G_emb via yc tokens.
// ---------------------------------------------------------------------------
__global__ __launch_bounds__(256, 2)
void gemm_py_kernel(const int* __restrict__ yc,
                    const float* __restrict__ G,
                    const float* __restrict__ Pw,
                    const float* __restrict__ Pb) {
    __shared__ __align__(16) float As[2][BK][128];
    __shared__ __align__(16) float Bs[2][BK][128];

    const int m0 = blockIdx.y * 128;
    const int n0 = blockIdx.x * 128;
    const int tid = threadIdx.x;

    const int rowb = (tid >> 4) * 8;
    const int colb = (tid & 15) * 8;
    const int la_row = tid >> 1;            // 0..127
    const int la_k   = (tid & 1) * 8;       // {0,8}
    const int lb_k   = tid >> 4;            // 0..15
    const int lb_n   = (tid & 15) * 8;      // 0..120

    unsigned long long acc[8][4];
#pragma unroll
    for (int i = 0; i < 8; i++)
#pragma unroll
        for (int j = 0; j < 4; j++) acc[i][j] = 0ull;

    float4 pa0, pa1, pb0, pb1;

    // --- prefetch helpers (inline) ---
    const int m_g = m0 + la_row;
#define PY_LOAD(K0)                                                             \
    {                                                                           \
        int kk = (K0) + la_k;                                                   \
        int c = kk >> 9, koff = kk & 511;                                       \
        int tok = __ldg(&yc[m_g * CTX + c]);                                    \
        const float* p = G + (size_t)tok * DM + koff;                           \
        pa0 = __ldg((const float4*)p);                                          \
        pa1 = __ldg((const float4*)(p + 4));                                    \
        const float* q = Pw + (size_t)((K0) + lb_k) * DM + n0 + lb_n;           \
        pb0 = __ldg((const float4*)q);                                          \
        pb1 = __ldg((const float4*)(q + 4));                                    \
    }
#define PY_STORE(BUF)                                                           \
    {                                                                           \
        As[BUF][la_k + 0][la_row] = pa0.x; As[BUF][la_k + 1][la_row] = pa0.y;   \
        As[BUF][la_k + 2][la_row] = pa0.z; As[BUF][la_k + 3][la_row] = pa0.w;   \
        As[BUF][la_k + 4][la_row] = pa1.x; As[BUF][la_k + 5][la_row] = pa1.y;   \
        As[BUF][la_k + 6][la_row] = pa1.z; As[BUF][la_k + 7][la_row] = pa1.w;   \
        *(float4*)&Bs[BUF][lb_k][lb_n]     = pb0;                               \
        *(float4*)&Bs[BUF][lb_k][lb_n + 4] = pb1;                               \
    }

    PY_LOAD(0); PY_STORE(0);
    __syncthreads();
    int buf = 0;
    for (int k0 = BK; k0 < KPY; k0 += BK) {
        PY_LOAD(k0);
        fma_tile(As[buf], Bs[buf], rowb, colb, acc);
        PY_STORE(buf ^ 1);
        __syncthreads();
        buf ^= 1;
    }
    fma_tile(As[buf], Bs[buf], rowb, colb, acc);

    // epilogue: + bias
    float4 bias0 = __ldg((const float4*)(Pb + n0 + colb));
    float4 bias1 = __ldg((const float4*)(Pb + n0 + colb + 4));
#pragma unroll
    for (int i = 0; i < 8; i++) {
        const int m = m0 + rowb + i;
        float2 r0 = *(float2*)&acc[i][0];
        float2 r1 = *(float2*)&acc[i][1];
        float2 r2 = *(float2*)&acc[i][2];
        float2 r3 = *(float2*)&acc[i][3];
        float4 w0 = make_float4(r0.x + bias0.x, r0.y + bias0.y,
                                r1.x + bias0.z, r1.y + bias0.w);
        float4 w1 = make_float4(r2.x + bias1.x, r2.y + bias1.y,
                                r3.x + bias1.z, r3.y + bias1.w);
        *(float4*)&g_py[(size_t)m * DM + n0 + colb]     = w0;
        *(float4*)&g_py[(size_t)m * DM + n0 + colb + 4] = w1;
    }
#undef PY_LOAD
#undef PY_STORE
}

// ---------------------------------------------------------------------------
// Kernel 3: logits C[s,x] = sum_d py[b,s,d]*xe[b,x,d]  (NT, K=512)
// ---------------------------------------------------------------------------
__global__ __launch_bounds__(256, 2)
void gemm_logits_kernel(float* __restrict__ a_out) {
    __shared__ __align__(16) float As[2][BK][128];
    __shared__ __align__(16) float Bs[2][BK][128];

    const int b  = blockIdx.y;
    const int n0 = blockIdx.x * 128;
    const int tid = threadIdx.x;

    const float* A  = g_py + (size_t)b * SEQ * DM;
    const float* Bm = g_xe + (size_t)b * SRC * DM;

    const int rowb = (tid >> 4) * 8;
    const int colb = (tid & 15) * 8;
    const int la_row = tid >> 1;
    const int la_k   = (tid & 1) * 8;

    unsigned long long acc[8][4];
#pragma unroll
    for (int i = 0; i < 8; i++)
#pragma unroll
        for (int j = 0; j < 4; j++) acc[i][j] = 0ull;

    float4 pa0, pa1, pb0, pb1;
#define LG_LOAD(K0)                                                             \
    {                                                                           \
        const float* p = A + (size_t)la_row * DM + (K0) + la_k;                 \
        pa0 = *(const float4*)p; pa1 = *(const float4*)(p + 4);                 \
        const float* q = Bm + (size_t)(n0 + la_row) * DM + (K0) + la_k;         \
        pb0 = *(const float4*)q; pb1 = *(const float4*)(q + 4);                 \
    }
#define LG_STORE(BUF)                                                           \
    {                                                                           \
        As[BUF][la_k + 0][la_row] = pa0.x; As[BUF][la_k + 1][la_row] = pa0.y;   \
        As[BUF][la_k + 2][la_row] = pa0.z; As[BUF][la_k + 3][la_row] = pa0.w;   \
        As[BUF][la_k + 4][la_row] = pa1.x; As[BUF][la_k + 5][la_row] = pa1.y;   \
        As[BUF][la_k + 6][la_row] = pa1.z; As[BUF][la_k + 7][la_row] = pa1.w;   \
        Bs[BUF][la_k + 0][la_row] = pb0.x; Bs[BUF][la_k + 1][la_row] = pb0.y;   \
        Bs[BUF][la_k + 2][la_row] = pb0.z; Bs[BUF][la_k + 3][la_row] = pb0.w;   \
        Bs[BUF][la_k + 4][la_row] = pb1.x; Bs[BUF][la_k + 5][la_row] = pb1.y;   \
        Bs[BUF][la_k + 6][la_row] = pb1.z; Bs[BUF][la_k + 7][la_row] = pb1.w;   \
    }

    LG_LOAD(0); LG_STORE(0);
    __syncthreads();
    int buf = 0;
    for (int k0 = BK; k0 < DM; k0 += BK) {
        LG_LOAD(k0);
        fma_tile(As[buf], Bs[buf], rowb, colb, acc);
        LG_STORE(buf ^ 1);
        __syncthreads();
        buf ^= 1;
    }
    fma_tile(As[buf], Bs[buf], rowb, colb, acc);

    float* C = a_out + (size_t)b * SEQ * SRC;
#pragma unroll
    for (int i = 0; i < 8; i++) {
        const int s = rowb + i;
        float2 r0 = *(float2*)&acc[i][0];
        float2 r1 = *(float2*)&acc[i][1];
        float2 r2 = *(float2*)&acc[i][2];
        float2 r3 = *(float2*)&acc[i][3];
        *(float4*)&C[(size_t)s * SRC + n0 + colb]     = make_float4(r0.x, r0.y, r1.x, r1.y);
        *(float4*)&C[(size_t)s * SRC + n0 + colb + 4] = make_float4(r2.x, r2.y, r3.x, r3.y);
    }
#undef LG_LOAD
#undef LG_STORE
}

// ---------------------------------------------------------------------------
// Kernel 4: masked softmax in-place over SRC=1024 per (b,s) row
// ---------------------------------------------------------------------------
__global__ void softmax_mask_kernel(float* __restrict__ a,
                                    const int* __restrict__ x) {
    const int row = blockIdx.x;          // b*SEQ + s
    const int b = row / SEQ;
    float* p = a + (size_t)row * SRC;
    const int* xb = x + b * SRC;
    const int t = threadIdx.x;

    float v[4];
    float mx = -1e30f;
#pragma unroll
    for (int i = 0; i < 4; i++) {
        const int col = t + i * 256;
        float val = p[col];
        if (__ldg(&xb[col]) == 0) val -= 1e9f;
        v[i] = val;
        mx = fmaxf(mx, val);
    }
    __shared__ float red[256];
    red[t] = mx; __syncthreads();
#pragma unroll
    for (int s = 128; s > 0; s >>= 1) {
        if (t < s) red[t] = fmaxf(red[t], red[t + s]);
        __syncthreads();
    }
    mx = red[0]; __syncthreads();

    float sum = 0.f;
#pragma unroll
    for (int i = 0; i < 4; i++) { v[i] = __expf(v[i] - mx); sum += v[i]; }
    red[t] = sum; __syncthreads();
#pragma unroll
    for (int s = 128; s > 0; s >>= 1) {
        if (t < s) red[t] += red[t + s];
        __syncthreads();
    }
    const float inv = 1.0f / red[0];
#pragma unroll
    for (int i = 0; i < 4; i++) p[t + i * 256] = v[i] * inv;
}

// ---------------------------------------------------------------------------
// Kernel 5: out[b,s,d] = sum_x a[b,s,x]*xe[b,x,d]  (NN, K=1024)
// ---------------------------------------------------------------------------
__global__ __launch_bounds__(256, 2)
void gemm_out_kernel(const float* __restrict__ a_in,
                     float* __restrict__ out) {
    __shared__ __align__(16) float As[2][BK][128];
    __shared__ __align__(16) float Bs[2][BK][128];

    const int b  = blockIdx.y;
    const int n0 = blockIdx.x * 128;
    const int tid = threadIdx.x;

    const float* A  = a_in + (size_t)b * SEQ * SRC;   // [128,1024] k-contig
    const float* Bm = g_xe + (size_t)b * SRC * DM;    // [1024,512] n-contig

    const int rowb = (tid >> 4) * 8;
    const int colb = (tid & 15) * 8;
    const int la_row = tid >> 1;
    const int la_k   = (tid & 1) * 8;
    const int lb_k   = tid >> 4;
    const int lb_n   = (tid & 15) * 8;

    unsigned long long acc[8][4];
#pragma unroll
    for (int i = 0; i < 8; i++)
#pragma unroll
        for (int j = 0; j < 4; j++) acc[i][j] = 0ull;

    float4 pa0, pa1, pb0, pb1;
#define OU_LOAD(K0)                                                             \
    {                                                                           \
        const float* p = A + (size_t)la_row * SRC + (K0) + la_k;                \
        pa0 = *(const float4*)p; pa1 = *(const float4*)(p + 4);                 \
        const float* q = Bm + (size_t)((K0) + lb_k) * DM + n0 + lb_n;           \
        pb0 = *(const float4*)q; pb1 = *(const float4*)(q + 4);                 \
    }
#define OU_STORE(BUF)                                                           \
    {                                                                           \
        As[BUF][la_k + 0][la_row] = pa0.x; As[BUF][la_k + 1][la_row] = pa0.y;   \
        As[BUF][la_k + 2][la_row] = pa0.z; As[BUF][la_k + 3][la_row] = pa0.w;   \
        As[BUF][la_k + 4][la_row] = pa1.x; As[BUF][la_k + 5][la_row] = pa1.y;   \
        As[BUF][la_k + 6][la_row] = pa1.z; As[BUF][la_k + 7][la_row] = pa1.w;   \
        *(float4*)&Bs[BUF][lb_k][lb_n]     = pb0;                               \
        *(float4*)&Bs[BUF][lb_k][lb_n + 4] = pb1;                               \
    }

    OU_LOAD(0); OU_STORE(0);
    __syncthreads();
    int buf = 0;
    for (int k0 = BK; k0 < SRC; k0 += BK) {
        OU_LOAD(k0);
        fma_tile(As[buf], Bs[buf], rowb, colb, acc);
        OU_STORE(buf ^ 1);
        __syncthreads();
        buf ^= 1;
    }
    fma_tile(As[buf], Bs[buf], rowb, colb, acc);

    float* C = out + (size_t)b * SEQ * DM;
#pragma unroll
    for (int i = 0; i < 8; i++) {
        const int s = rowb + i;
        float2 r0 = *(float2*)&acc[i][0];
        float2 r1 = *(float2*)&acc[i][1];
        float2 r2 = *(float2*)&acc[i][2];
        float2 r3 = *(float2*)&acc[i][3];
        *(float4*)&C[(size_t)s * DM + n0 + colb]     = make_float4(r0.x, r0.y, r1.x, r1.y);
        *(float4*)&C[(size_t)s * DM + n0 + colb + 4] = make_float4(r2.x, r2.y, r3.x, r3.y);
    }
#undef OU_LOAD
#undef OU_STORE
}

// ---------------------------------------------------------------------------
extern "C" void kernel_launch(void* const* d_in, const int* in_sizes, int n_in,
                              void* d_out, int out_size) {
    const int*   x   = (const int*)  d_in[0];   // [32, 1024]
    const int*   yc  = (const int*)  d_in[1];   // [32, 640]
    const float* F   = (const float*)d_in[2];   // [32000, 512]
    const float* G   = (const float*)d_in[3];   // [32000, 512]
    const float* Pw  = (const float*)d_in[4];   // [2560, 512]
    const float* Pb  = (const float*)d_in[5];   // [512]

    float* out   = (float*)d_out;                       // [32,128,512]
    float* a_out = out + (size_t)BB * SEQ * DM;         // [32,128,1024]

    gather_xe_kernel<<<BB * SRC, 128>>>(x, F);
    gemm_py_kernel<<<dim3(DM / 128, (BB * SEQ) / 128), 256>>>(yc, G, Pw, Pb);
    gemm_logits_kernel<<<dim3(SRC / 128, BB), 256>>>(a_out);
    softmax_mask_kernel<<<BB * SEQ, 256>>>(a_out, x);
    gemm_out_kernel<<<dim3(DM / 128, BB), 256>>>(a_out, out);
}

// round 4
// speedup vs baseline: 2.1542x; 1.5558x over previous
#include <cuda_runtime.h>
#include <cuda_bf16.h>
#include <cstdint>

// Problem constants
#define BB   32
#define SRC  1024
#define SEQ  128
#define CTX  5
#define DM   512
#define KPY  (CTX*DM)   // 2560

// ---------------------------------------------------------------------------
// Scratch (device globals; no allocations allowed)
// ---------------------------------------------------------------------------
__device__ __nv_bfloat16 g_xe_hi [(size_t)BB*SRC*DM];
__device__ __nv_bfloat16 g_xe_lo [(size_t)BB*SRC*DM];
__device__ __nv_bfloat16 g_xeT_hi[(size_t)BB*DM*SRC];
__device__ __nv_bfloat16 g_xeT_lo[(size_t)BB*DM*SRC];
__device__ __nv_bfloat16 g_yce_hi[(size_t)BB*SEQ*KPY];
__device__ __nv_bfloat16 g_yce_lo[(size_t)BB*SEQ*KPY];
__device__ __nv_bfloat16 g_pwt_hi[(size_t)DM*KPY];
__device__ __nv_bfloat16 g_pwt_lo[(size_t)DM*KPY];
__device__ float         g_py    [(size_t)BB*SEQ*DM];
__device__ __nv_bfloat16 g_py_hi [(size_t)BB*SEQ*DM];
__device__ __nv_bfloat16 g_py_lo [(size_t)BB*SEQ*DM];
__device__ __nv_bfloat16 g_a_hi  [(size_t)BB*SEQ*SRC];
__device__ __nv_bfloat16 g_a_lo  [(size_t)BB*SEQ*SRC];

// ---------------------------------------------------------------------------
// Helpers
// ---------------------------------------------------------------------------
__device__ __forceinline__ uint32_t smem_to_u32(const void* p) {
    uint32_t a;
    asm("{ .reg .u64 t; cvta.to.shared.u64 t, %1; cvt.u32.u64 %0, t; }"
        : "=r"(a) : "l"(p));
    return a;
}

#define CP_ASYNC16(dst, src) \
    asm volatile("cp.async.cg.shared.global [%0], [%1], 16;" \
                 :: "r"(dst), "l"(src) : "memory")
#define CP_COMMIT() asm volatile("cp.async.commit_group;" ::: "memory")
#define CP_WAIT(N)  asm volatile("cp.async.wait_group %0;" :: "n"(N) : "memory")

__device__ __forceinline__ void ldsm_x4(uint32_t r[4], uint32_t addr) {
    asm volatile("ldmatrix.sync.aligned.m8n8.x4.shared.b16 {%0,%1,%2,%3}, [%4];"
                 : "=r"(r[0]), "=r"(r[1]), "=r"(r[2]), "=r"(r[3]) : "r"(addr));
}

__device__ __forceinline__ void mma16816(float c[4],
                                         uint32_t a0, uint32_t a1, uint32_t a2, uint32_t a3,
                                         uint32_t b0, uint32_t b1) {
    asm volatile("mma.sync.aligned.m16n8k16.row.col.f32.bf16.bf16.f32 "
                 "{%0,%1,%2,%3}, {%4,%5,%6,%7}, {%8,%9}, {%0,%1,%2,%3};"
                 : "+f"(c[0]), "+f"(c[1]), "+f"(c[2]), "+f"(c[3])
                 : "r"(a0), "r"(a1), "r"(a2), "r"(a3), "r"(b0), "r"(b1));
}

// fp32 -> (bf16 hi, bf16 lo) split
__device__ __forceinline__ void split2(float v, unsigned short& h, unsigned short& l) {
    __nv_bfloat16 hb = __float2bfloat16(v);
    __nv_bfloat16 lb = __float2bfloat16(v - __bfloat162float(hb));
    h = __bfloat16_as_ushort(hb);
    l = __bfloat16_as_ushort(lb);
}

// ---------------------------------------------------------------------------
// Prep kernel: gather + split xe (row = b*SRC + i, 64 threads x 8 floats)
// ---------------------------------------------------------------------------
__global__ void gather_split_xe(const int* __restrict__ x, const float* __restrict__ F) {
    const int row = blockIdx.x;
    const int tok = __ldg(&x[row]);
    const int t = threadIdx.x;
    const float4* src = (const float4*)(F + (size_t)tok * DM);
    float4 a = __ldg(&src[t * 2]);
    float4 b = __ldg(&src[t * 2 + 1]);
    float v[8] = {a.x, a.y, a.z, a.w, b.x, b.y, b.z, b.w};
    union { unsigned short us[8]; uint4 u; } H, L;
#pragma unroll
    for (int i = 0; i < 8; i++) split2(v[i], H.us[i], L.us[i]);
    *(uint4*)(g_xe_hi + (size_t)row * DM + t * 8) = H.u;
    *(uint4*)(g_xe_lo + (size_t)row * DM + t * 8) = L.u;
}

// ---------------------------------------------------------------------------
// Prep kernel: transpose xe -> xeT (per batch), 64x64 tiles, hi then lo
// ---------------------------------------------------------------------------
__global__ void transpose_xe_kernel() {
    __shared__ unsigned short s[64][66];
    const int x0 = blockIdx.x * 64;
    const int d0 = blockIdx.y * 64;
    const int b  = blockIdx.z;
    const int tx = threadIdx.x & 31, ty = threadIdx.x >> 5;

    const unsigned short* in[2]  = {(const unsigned short*)g_xe_hi  + (size_t)b * SRC * DM,
                                    (const unsigned short*)g_xe_lo  + (size_t)b * SRC * DM};
    unsigned short* outp[2]      = {(unsigned short*)g_xeT_hi + (size_t)b * DM * SRC,
                                    (unsigned short*)g_xeT_lo + (size_t)b * DM * SRC};
#pragma unroll
    for (int a = 0; a < 2; a++) {
#pragma unroll
        for (int i = 0; i < 8; i++) {
            const int r = ty + i * 8;                       // local x
            unsigned v = *(const unsigned*)(in[a] + (size_t)(x0 + r) * DM + d0 + tx * 2);
            s[r][tx * 2]     = (unsigned short)(v & 0xffff);
            s[r][tx * 2 + 1] = (unsigned short)(v >> 16);
        }
        __syncthreads();
#pragma unroll
        for (int i = 0; i < 8; i++) {
            const int dr = ty + i * 8;                      // local d
            unsigned v = (unsigned)s[tx * 2][dr] | ((unsigned)s[tx * 2 + 1][dr] << 16);
            *(unsigned*)(outp[a] + (size_t)(d0 + dr) * SRC + x0 + tx * 2) = v;
        }
        __syncthreads();
    }
}

// ---------------------------------------------------------------------------
// Prep kernel: gather + split yce  (grid = (4096, 5), 64 threads)
// ---------------------------------------------------------------------------
__global__ void gather_split_yce(const int* __restrict__ yc, const float* __restrict__ G) {
    const int m = blockIdx.x;
    const int c = blockIdx.y;
    const int tok = __ldg(&yc[m * CTX + c]);
    const int t = threadIdx.x;
    const float4* src = (const float4*)(G + (size_t)tok * DM);
    float4 a = __ldg(&src[t * 2]);
    float4 b = __ldg(&src[t * 2 + 1]);
    float v[8] = {a.x, a.y, a.z, a.w, b.x, b.y, b.z, b.w};
    union { unsigned short us[8]; uint4 u; } H, L;
#pragma unroll
    for (int i = 0; i < 8; i++) split2(v[i], H.us[i], L.us[i]);
    const size_t off = (size_t)m * KPY + c * DM + t * 8;
    *(uint4*)(g_yce_hi + off) = H.u;
    *(uint4*)(g_yce_lo + off) = L.u;
}

// ---------------------------------------------------------------------------
// Prep kernel: transpose + split P_w [2560,512] -> PwT hi/lo [512][2560]
// ---------------------------------------------------------------------------
__global__ void split_pwt_kernel(const float* __restrict__ Pw) {
    __shared__ float s[64][65];
    const int k0 = blockIdx.x * 64;
    const int n0 = blockIdx.y * 64;
    const int tx = threadIdx.x & 31, ty = threadIdx.x >> 5;
#pragma unroll
    for (int i = 0; i < 8; i++) {
        const int r = ty + i * 8;                           // local k
        float2 v = *(const float2*)(Pw + (size_t)(k0 + r) * DM + n0 + tx * 2);
        s[r][tx * 2] = v.x; s[r][tx * 2 + 1] = v.y;
    }
    __syncthreads();
#pragma unroll
    for (int i = 0; i < 8; i++) {
        const int nr = ty + i * 8;                          // local n
        float v0 = s[tx * 2][nr], v1 = s[tx * 2 + 1][nr];
        unsigned short h0, l0, h1, l1;
        split2(v0, h0, l0); split2(v1, h1, l1);
        const size_t off = (size_t)(n0 + nr) * KPY + k0 + tx * 2;
        *(unsigned*)((unsigned short*)g_pwt_hi + off) = (unsigned)h0 | ((unsigned)h1 << 16);
        *(unsigned*)((unsigned short*)g_pwt_lo + off) = (unsigned)l0 | ((unsigned)l1 << 16);
    }
}

// ---------------------------------------------------------------------------
// Prep kernels: split fp32 rows -> hi/lo bf16 (py: 512/row, a: 1024/row)
// ---------------------------------------------------------------------------
__global__ void split_py_kernel() {
    const int row = blockIdx.x; const int t = threadIdx.x;   // 64 thr
    const float4* src = (const float4*)(g_py + (size_t)row * DM);
    float4 a = src[t * 2], b = src[t * 2 + 1];
    float v[8] = {a.x, a.y, a.z, a.w, b.x, b.y, b.z, b.w};
    union { unsigned short us[8]; uint4 u; } H, L;
#pragma unroll
    for (int i = 0; i < 8; i++) split2(v[i], H.us[i], L.us[i]);
    *(uint4*)(g_py_hi + (size_t)row * DM + t * 8) = H.u;
    *(uint4*)(g_py_lo + (size_t)row * DM + t * 8) = L.u;
}

__global__ void split_a_kernel(const float* __restrict__ a_in) {
    const int row = blockIdx.x; const int t = threadIdx.x;   // 128 thr
    const float4* src = (const float4*)(a_in + (size_t)row * SRC);
    float4 a = src[t * 2], b = src[t * 2 + 1];
    float v[8] = {a.x, a.y, a.z, a.w, b.x, b.y, b.z, b.w};
    union { unsigned short us[8]; uint4 u; } H, L;
#pragma unroll
    for (int i = 0; i < 8; i++) split2(v[i], H.us[i], L.us[i]);
    *(uint4*)(g_a_hi + (size_t)row * SRC + t * 8) = H.u;
    *(uint4*)(g_a_lo + (size_t)row * SRC + t * 8) = L.u;
}

// ---------------------------------------------------------------------------
// mma.sync GEMM:  C[M,N] = sum_k A'[m,k'] * B'[n,k']  (NT, both K-major)
// A' = [Ahi | Ahi | Alo], B' = [Bhi | Blo | Bhi] along K' = 3K.
// CTA tile 128x128, BK=32, 8 warps (2m x 4n), warp tile 64x32, m16n8k16.
// Smem: padded row stride 40 halves (80B) -> conflict-free ldmatrix.
// ---------------------------------------------------------------------------
#define SROW 40                 // padded smem row stride in halves
#define ATILE_B (128 * SROW * 2)   // 10240 bytes
#define BUF_B   (2 * ATILE_B)      // 20480 bytes per buffer

__global__ __launch_bounds__(256)
void mma_gemm_kernel(const __nv_bfloat16* __restrict__ Ahi, const __nv_bfloat16* __restrict__ Alo,
                     size_t strideA, int lda,
                     const __nv_bfloat16* __restrict__ Bhi, const __nv_bfloat16* __restrict__ Blo,
                     size_t strideB, int ldb,
                     float* __restrict__ C, size_t strideC, int ldc,
                     const float* __restrict__ bias, int K) {
    __shared__ __align__(16) unsigned char sm[2 * BUF_B];
    const uint32_t s_base = smem_to_u32(sm);
    const uint32_t sA = s_base;
    const uint32_t sB = s_base + ATILE_B;

    const int tid  = threadIdx.x;
    const int lane = tid & 31;
    const int wid  = tid >> 5;
    const int wm   = wid & 1;       // 0..1 -> m offset 0/64
    const int wn   = wid >> 1;      // 0..3 -> n offset 0/32/64/96
    const int quad = lane >> 3;
    const int l8   = lane & 7;

    const int m0 = blockIdx.y * 128;
    const int n0 = blockIdx.x * 128;
    const size_t bz = blockIdx.z;
    const __nv_bfloat16* Ah = Ahi + bz * strideA + (size_t)m0 * lda;
    const __nv_bfloat16* Al = Alo + bz * strideA + (size_t)m0 * lda;
    const __nv_bfloat16* Bh = Bhi + bz * strideB + (size_t)n0 * ldb;
    const __nv_bfloat16* Bl = Blo + bz * strideB + (size_t)n0 * ldb;

    // loader mapping: 256 threads cover 128 rows x 4 16B-chunks, x2 halves
    const int lrow   = tid >> 2;       // 0..63
    const int lchunk = tid & 3;        // 0..3 (8 halves each)

    // ldmatrix base addresses (buf 0)
    const uint32_t a_addr0 = sA + ((uint32_t)(wm * 64 + (quad & 1) * 8 + l8) * SROW
                                   + (quad >> 1) * 8) * 2;
    const uint32_t b_addr0 = sB + ((uint32_t)(wn * 32 + (quad >> 1) * 8 + l8) * SROW
                                   + (quad & 1) * 8) * 2;

    float acc[4][4][4];
#pragma unroll
    for (int i = 0; i < 4; i++)
#pragma unroll
        for (int j = 0; j < 4; j++)
#pragma unroll
            for (int r = 0; r < 4; r++) acc[i][j][r] = 0.f;

    const int NC = 3 * K / 32;

    auto load_tiles = [&](int buf, int cidx) {
        const int kp   = cidx * 32;
        const int seg  = kp / K;
        const int koff = kp - seg * K;
        const __nv_bfloat16* Ap = (seg < 2 ? Ah : Al) + koff;
        const __nv_bfloat16* Bp = (seg == 1 ? Bl : Bh) + koff;
        const uint32_t bo = (uint32_t)buf * BUF_B;
#pragma unroll
        for (int h = 0; h < 2; h++) {
            const int r = lrow + h * 64;
            CP_ASYNC16(sA + bo + ((uint32_t)r * SROW + lchunk * 8) * 2,
                       Ap + (size_t)r * lda + lchunk * 8);
            CP_ASYNC16(sB + bo + ((uint32_t)r * SROW + lchunk * 8) * 2,
                       Bp + (size_t)r * ldb + lchunk * 8);
        }
    };

    load_tiles(0, 0);
    CP_COMMIT();

    int buf = 0;
    for (int cidx = 0; cidx < NC; cidx++) {
        if (cidx + 1 < NC) {
            load_tiles(buf ^ 1, cidx + 1);
            CP_COMMIT();
            CP_WAIT(1);
        } else {
            CP_WAIT(0);
        }
        __syncthreads();

        const uint32_t bo = (uint32_t)buf * BUF_B;
#pragma unroll
        for (int ks = 0; ks < 2; ks++) {
            uint32_t afr[4][4];
#pragma unroll
            for (int mt = 0; mt < 4; mt++)
                ldsm_x4(afr[mt], a_addr0 + bo + mt * (16 * SROW * 2) + ks * 32);
            uint32_t bfr[2][4];
#pragma unroll
            for (int p = 0; p < 2; p++)
                ldsm_x4(bfr[p], b_addr0 + bo + p * (16 * SROW * 2) + ks * 32);
#pragma unroll
            for (int mt = 0; mt < 4; mt++)
#pragma unroll
                for (int nt = 0; nt < 4; nt++)
                    mma16816(acc[mt][nt],
                             afr[mt][0], afr[mt][1], afr[mt][2], afr[mt][3],
                             bfr[nt >> 1][(nt & 1) * 2], bfr[nt >> 1][(nt & 1) * 2 + 1]);
        }
        __syncthreads();
        buf ^= 1;
    }

    // epilogue
    float* Cb = C + bz * strideC;
    const int mb = m0 + wm * 64;
    const int nb = n0 + wn * 32;
#pragma unroll
    for (int mt = 0; mt < 4; mt++) {
#pragma unroll
        for (int nt = 0; nt < 4; nt++) {
            const int r  = mb + mt * 16 + (lane >> 2);
            const int cc = nb + nt * 8 + (lane & 3) * 2;
            float bx = 0.f, by = 0.f;
            if (bias) { bx = __ldg(&bias[cc]); by = __ldg(&bias[cc + 1]); }
            *(float2*)&Cb[(size_t)r * ldc + cc] =
                make_float2(acc[mt][nt][0] + bx, acc[mt][nt][1] + by);
            *(float2*)&Cb[(size_t)(r + 8) * ldc + cc] =
                make_float2(acc[mt][nt][2] + bx, acc[mt][nt][3] + by);
        }
    }
}

// ---------------------------------------------------------------------------
// Masked softmax in-place over SRC=1024 per (b,s) row
// ---------------------------------------------------------------------------
__global__ void softmax_mask_kernel(float* __restrict__ a,
                                    const int* __restrict__ x) {
    const int row = blockIdx.x;          // b*SEQ + s
    const int b = row / SEQ;
    float* p = a + (size_t)row * SRC;
    const int* xb = x + b * SRC;
    const int t = threadIdx.x;

    float v[4];
    float mx = -1e30f;
#pragma unroll
    for (int i = 0; i < 4; i++) {
        const int col = t + i * 256;
        float val = p[col];
        if (__ldg(&xb[col]) == 0) val -= 1e9f;
        v[i] = val;
        mx = fmaxf(mx, val);
    }
    __shared__ float red[256];
    red[t] = mx; __syncthreads();
#pragma unroll
    for (int s = 128; s > 0; s >>= 1) {
        if (t < s) red[t] = fmaxf(red[t], red[t + s]);
        __syncthreads();
    }
    mx = red[0]; __syncthreads();

    float sum = 0.f;
#pragma unroll
    for (int i = 0; i < 4; i++) { v[i] = __expf(v[i] - mx); sum += v[i]; }
    red[t] = sum; __syncthreads();
#pragma unroll
    for (int s = 128; s > 0; s >>= 1) {
        if (t < s) red[t] += red[t + s];
        __syncthreads();
    }
    const float inv = 1.0f / red[0];
#pragma unroll
    for (int i = 0; i < 4; i++) p[t + i * 256] = v[i] * inv;
}

// ---------------------------------------------------------------------------
extern "C" void kernel_launch(void* const* d_in, const int* in_sizes, int n_in,
                              void* d_out, int out_size) {
    const int*   x   = (const int*)  d_in[0];   // [32, 1024]
    const int*   yc  = (const int*)  d_in[1];   // [32, 640]
    const float* F   = (const float*)d_in[2];   // [32000, 512]
    const float* G   = (const float*)d_in[3];   // [32000, 512]
    const float* Pw  = (const float*)d_in[4];   // [2560, 512]
    const float* Pb  = (const float*)d_in[5];   // [512]

    float* out   = (float*)d_out;                       // [32,128,512]
    float* a_out = out + (size_t)BB * SEQ * DM;         // [32,128,1024]

    // resolve device-global addresses (host side; graph-safe)
    __nv_bfloat16 *xe_hi, *xe_lo, *xeT_hi, *xeT_lo, *yce_hi, *yce_lo,
                  *pwt_hi, *pwt_lo, *py_hi, *py_lo, *a_hi, *a_lo;
    float* py;
    cudaGetSymbolAddress((void**)&xe_hi,  g_xe_hi);
    cudaGetSymbolAddress((void**)&xe_lo,  g_xe_lo);
    cudaGetSymbolAddress((void**)&xeT_hi, g_xeT_hi);
    cudaGetSymbolAddress((void**)&xeT_lo, g_xeT_lo);
    cudaGetSymbolAddress((void**)&yce_hi, g_yce_hi);
    cudaGetSymbolAddress((void**)&yce_lo, g_yce_lo);
    cudaGetSymbolAddress((void**)&pwt_hi, g_pwt_hi);
    cudaGetSymbolAddress((void**)&pwt_lo, g_pwt_lo);
    cudaGetSymbolAddress((void**)&py,     g_py);
    cudaGetSymbolAddress((void**)&py_hi,  g_py_hi);
    cudaGetSymbolAddress((void**)&py_lo,  g_py_lo);
    cudaGetSymbolAddress((void**)&a_hi,   g_a_hi);
    cudaGetSymbolAddress((void**)&a_lo,   g_a_lo);

    // 1) gather + split source embeddings
    gather_split_xe<<<BB * SRC, 64>>>(x, F);
    // 2) transpose xe -> xeT (for out-GEMM B operand)
    transpose_xe_kernel<<<dim3(SRC / 64, DM / 64, BB), 256>>>();
    // 3) gather + split target-context embeddings
    gather_split_yce<<<dim3(BB * SEQ, CTX), 64>>>(yc, G);
    // 4) transpose + split P_w
    split_pwt_kernel<<<dim3(KPY / 64, DM / 64), 256>>>(Pw);
    // 5) py = yce @ P_w + P_b      M=4096, N=512, K=2560
    mma_gemm_kernel<<<dim3(DM / 128, (BB * SEQ) / 128, 1), 256>>>(
        yce_hi, yce_lo, 0, KPY,
        pwt_hi, pwt_lo, 0, KPY,
        py, 0, DM, Pb, KPY);
    // 6) split py
    split_py_kernel<<<BB * SEQ, 64>>>();
    // 7) logits a[b,s,x] = py[b,s,:] . xe[b,x,:]   M=128, N=1024, K=512 (batched)
    mma_gemm_kernel<<<dim3(SRC / 128, 1, BB), 256>>>(
        py_hi, py_lo, (size_t)SEQ * DM, DM,
        xe_hi, xe_lo, (size_t)SRC * DM, DM,
        a_out, (size_t)SEQ * SRC, SRC, nullptr, DM);
    // 8) masked softmax
    softmax_mask_kernel<<<BB * SEQ, 256>>>(a_out, x);
    // 9) split a
    split_a_kernel<<<BB * SEQ, 128>>>(a_out);
    // 10) out[b,s,d] = a[b,s,:] . xeT[b,d,:]       M=128, N=512, K=1024 (batched)
    mma_gemm_kernel<<<dim3(DM / 128, 1, BB), 256>>>(
        a_hi, a_lo, (size_t)SEQ * SRC, SRC,
        xeT_hi, xeT_lo, (size_t)DM * SRC, SRC,
        out, (size_t)SEQ * DM, DM, nullptr, SRC);
}

// round 5
// speedup vs baseline: 2.3834x; 1.1064x over previous
#include <cuda_runtime.h>
#include <cuda_bf16.h>
#include <cstdint>

// Problem constants
#define BB   32
#define SRC  1024
#define SEQ  128
#define CTX  5
#define DM   512
#define KPY  (CTX*DM)   // 2560

// ---------------------------------------------------------------------------
// Scratch (device globals; no allocations allowed)
// ---------------------------------------------------------------------------
__device__ __nv_bfloat16 g_xe_hi [(size_t)BB*SRC*DM];
__device__ __nv_bfloat16 g_xe_lo [(size_t)BB*SRC*DM];
__device__ __nv_bfloat16 g_yce_hi[(size_t)BB*SEQ*KPY];
__device__ __nv_bfloat16 g_yce_lo[(size_t)BB*SEQ*KPY];
__device__ __nv_bfloat16 g_pwt_hi[(size_t)DM*KPY];
__device__ __nv_bfloat16 g_pwt_lo[(size_t)DM*KPY];
__device__ __nv_bfloat16 g_py_hi [(size_t)BB*SEQ*DM];
__device__ __nv_bfloat16 g_py_lo [(size_t)BB*SEQ*DM];
__device__ __nv_bfloat16 g_a_hi  [(size_t)BB*SEQ*SRC];
__device__ __nv_bfloat16 g_a_lo  [(size_t)BB*SEQ*SRC];

// ---------------------------------------------------------------------------
// Helpers
// ---------------------------------------------------------------------------
__device__ __forceinline__ uint32_t smem_to_u32(const void* p) {
    uint32_t a;
    asm("{ .reg .u64 t; cvta.to.shared.u64 t, %1; cvt.u32.u64 %0, t; }"
        : "=r"(a) : "l"(p));
    return a;
}

#define CP_ASYNC16(dst, src) \
    asm volatile("cp.async.cg.shared.global [%0], [%1], 16;" \
                 :: "r"(dst), "l"(src) : "memory")
#define CP_COMMIT() asm volatile("cp.async.commit_group;" ::: "memory")
#define CP_WAIT(N)  asm volatile("cp.async.wait_group %0;" :: "n"(N) : "memory")

__device__ __forceinline__ void ldsm_x4(uint32_t r[4], uint32_t addr) {
    asm volatile("ldmatrix.sync.aligned.m8n8.x4.shared.b16 {%0,%1,%2,%3}, [%4];"
                 : "=r"(r[0]), "=r"(r[1]), "=r"(r[2]), "=r"(r[3]) : "r"(addr));
}
__device__ __forceinline__ void ldsm_x4_trans(uint32_t r[4], uint32_t addr) {
    asm volatile("ldmatrix.sync.aligned.m8n8.x4.trans.shared.b16 {%0,%1,%2,%3}, [%4];"
                 : "=r"(r[0]), "=r"(r[1]), "=r"(r[2]), "=r"(r[3]) : "r"(addr));
}

__device__ __forceinline__ void mma16816(float c[4],
                                         uint32_t a0, uint32_t a1, uint32_t a2, uint32_t a3,
                                         uint32_t b0, uint32_t b1) {
    asm volatile("mma.sync.aligned.m16n8k16.row.col.f32.bf16.bf16.f32 "
                 "{%0,%1,%2,%3}, {%4,%5,%6,%7}, {%8,%9}, {%0,%1,%2,%3};"
                 : "+f"(c[0]), "+f"(c[1]), "+f"(c[2]), "+f"(c[3])
                 : "r"(a0), "r"(a1), "r"(a2), "r"(a3), "r"(b0), "r"(b1));
}

// fp32 -> (bf16 hi, bf16 lo) split
__device__ __forceinline__ void split2(float v, unsigned short& h, unsigned short& l) {
    __nv_bfloat16 hb = __float2bfloat16(v);
    __nv_bfloat16 lb = __float2bfloat16(v - __bfloat162float(hb));
    h = __bfloat16_as_ushort(hb);
    l = __bfloat16_as_ushort(lb);
}

// ---------------------------------------------------------------------------
// Prep: gather + split xe (row = b*SRC + i)
// ---------------------------------------------------------------------------
__global__ void gather_split_xe(const int* __restrict__ x, const float* __restrict__ F) {
    const int row = blockIdx.x;
    const int tok = __ldg(&x[row]);
    const int t = threadIdx.x;
    const float4* src = (const float4*)(F + (size_t)tok * DM);
    float4 a = __ldg(&src[t * 2]);
    float4 b = __ldg(&src[t * 2 + 1]);
    float v[8] = {a.x, a.y, a.z, a.w, b.x, b.y, b.z, b.w};
    union { unsigned short us[8]; uint4 u; } H, L;
#pragma unroll
    for (int i = 0; i < 8; i++) split2(v[i], H.us[i], L.us[i]);
    *(uint4*)(g_xe_hi + (size_t)row * DM + t * 8) = H.u;
    *(uint4*)(g_xe_lo + (size_t)row * DM + t * 8) = L.u;
}

// ---------------------------------------------------------------------------
// Prep: gather + split yce  (grid = (4096, 5), 64 threads)
// ---------------------------------------------------------------------------
__global__ void gather_split_yce(const int* __restrict__ yc, const float* __restrict__ G) {
    const int m = blockIdx.x;
    const int c = blockIdx.y;
    const int tok = __ldg(&yc[m * CTX + c]);
    const int t = threadIdx.x;
    const float4* src = (const float4*)(G + (size_t)tok * DM);
    float4 a = __ldg(&src[t * 2]);
    float4 b = __ldg(&src[t * 2 + 1]);
    float v[8] = {a.x, a.y, a.z, a.w, b.x, b.y, b.z, b.w};
    union { unsigned short us[8]; uint4 u; } H, L;
#pragma unroll
    for (int i = 0; i < 8; i++) split2(v[i], H.us[i], L.us[i]);
    const size_t off = (size_t)m * KPY + c * DM + t * 8;
    *(uint4*)(g_yce_hi + off) = H.u;
    *(uint4*)(g_yce_lo + off) = L.u;
}

// ---------------------------------------------------------------------------
// Prep: transpose + split P_w [2560,512] -> PwT hi/lo [512][2560]
// ---------------------------------------------------------------------------
__global__ void split_pwt_kernel(const float* __restrict__ Pw) {
    __shared__ float s[64][65];
    const int k0 = blockIdx.x * 64;
    const int n0 = blockIdx.y * 64;
    const int tx = threadIdx.x & 31, ty = threadIdx.x >> 5;
#pragma unroll
    for (int i = 0; i < 8; i++) {
        const int r = ty + i * 8;                           // local k
        float2 v = *(const float2*)(Pw + (size_t)(k0 + r) * DM + n0 + tx * 2);
        s[r][tx * 2] = v.x; s[r][tx * 2 + 1] = v.y;
    }
    __syncthreads();
#pragma unroll
    for (int i = 0; i < 8; i++) {
        const int nr = ty + i * 8;                          // local n
        float v0 = s[tx * 2][nr], v1 = s[tx * 2 + 1][nr];
        unsigned short h0, l0, h1, l1;
        split2(v0, h0, l0); split2(v1, h1, l1);
        const size_t off = (size_t)(n0 + nr) * KPY + k0 + tx * 2;
        *(unsigned*)((unsigned short*)g_pwt_hi + off) = (unsigned)h0 | ((unsigned)h1 << 16);
        *(unsigned*)((unsigned short*)g_pwt_lo + off) = (unsigned)l0 | ((unsigned)l1 << 16);
    }
}

// ---------------------------------------------------------------------------
// mma.sync GEMM, virtual K' = 3K: A' = [Ahi|Ahi|Alo], B' = [Bhi|Blo|Bhi].
// CTA tile 128x128, BK=32, 8 warps (2m x 4n), warp tile 64x32, m16n8k16.
// TRANSB=false: B is K-major [n][k] (NT).  TRANSB=true: B is [k][n] n-contig.
// SPLITOUT=false: write fp32 C (+bias).   SPLITOUT=true: write bf16 hi/lo (+bias).
// ---------------------------------------------------------------------------
#define SROW 40                    // A smem row stride (halves)
#define BROW 136                   // trans-B smem row stride (halves)
#define ATILE_B (128 * SROW * 2)   // 10240
#define BTILE_NT (128 * SROW * 2)  // 10240
#define BTILE_TR (32 * BROW * 2)   // 8704

template<bool TRANSB, bool SPLITOUT>
__global__ __launch_bounds__(256)
void mma_gemm_kernel(const __nv_bfloat16* __restrict__ Ahi, const __nv_bfloat16* __restrict__ Alo,
                     size_t strideA, int lda,
                     const __nv_bfloat16* __restrict__ Bhi, const __nv_bfloat16* __restrict__ Blo,
                     size_t strideB, int ldb,
                     float* __restrict__ C,
                     __nv_bfloat16* __restrict__ Chi, __nv_bfloat16* __restrict__ Clo,
                     size_t strideC, int ldc,
                     const float* __restrict__ bias, int K) {
    constexpr int BTILE = TRANSB ? BTILE_TR : BTILE_NT;
    constexpr int BUF   = ATILE_B + BTILE;
    __shared__ __align__(16) unsigned char smbuf[2 * BUF];
    const uint32_t s_base = smem_to_u32(smbuf);
    const uint32_t sA = s_base;
    const uint32_t sB = s_base + ATILE_B;

    const int tid  = threadIdx.x;
    const int lane = tid & 31;
    const int wid  = tid >> 5;
    const int wm   = wid & 1;       // m offset 0/64
    const int wn   = wid >> 1;      // n offset 0/32/64/96
    const int quad = lane >> 3;
    const int l8   = lane & 7;

    const int m0 = blockIdx.y * 128;
    const int n0 = blockIdx.x * 128;
    const size_t bz = blockIdx.z;
    const __nv_bfloat16* Ah = Ahi + bz * strideA + (size_t)m0 * lda;
    const __nv_bfloat16* Al = Alo + bz * strideA + (size_t)m0 * lda;
    const __nv_bfloat16* Bh;
    const __nv_bfloat16* Bl;
    if (TRANSB) { Bh = Bhi + bz * strideB + n0; Bl = Blo + bz * strideB + n0; }
    else        { Bh = Bhi + bz * strideB + (size_t)n0 * ldb;
                  Bl = Blo + bz * strideB + (size_t)n0 * ldb; }

    // A loader: 256 threads -> 128 rows x 4 chunks(16B), x2
    const int lrow   = tid >> 2;
    const int lchunk = tid & 3;
    // trans-B loader: 32 rows x 16 chunks(16B), x2
    const int tb_row = tid >> 4;    // 0..15
    const int tb_ch  = tid & 15;    // 0..15

    // ldmatrix base addresses (buf 0)
    const uint32_t a_addr0 = sA + ((uint32_t)(wm * 64 + (quad & 1) * 8 + l8) * SROW
                                   + (quad >> 1) * 8) * 2;
    const uint32_t b_addr_nt = sB + ((uint32_t)(wn * 32 + (quad >> 1) * 8 + l8) * SROW
                                     + (quad & 1) * 8) * 2;
    const uint32_t b_addr_tr = sB + ((uint32_t)((quad & 1) * 8 + l8) * BROW
                                     + wn * 32 + (quad >> 1) * 8) * 2;

    float acc[4][4][4];
#pragma unroll
    for (int i = 0; i < 4; i++)
#pragma unroll
        for (int j = 0; j < 4; j++)
#pragma unroll
            for (int r = 0; r < 4; r++) acc[i][j][r] = 0.f;

    const int NC = 3 * K / 32;

    auto load_tiles = [&](int buf, int cidx) {
        const int kp   = cidx * 32;
        const int seg  = kp / K;
        const int koff = kp - seg * K;
        const __nv_bfloat16* Ap = (seg < 2 ? Ah : Al) + koff;
        const uint32_t bo = (uint32_t)buf * BUF;
#pragma unroll
        for (int h = 0; h < 2; h++) {
            const int r = lrow + h * 64;
            CP_ASYNC16(sA + bo + ((uint32_t)r * SROW + lchunk * 8) * 2,
                       Ap + (size_t)r * lda + lchunk * 8);
        }
        if (TRANSB) {
            const __nv_bfloat16* Bp = (seg == 1 ? Bl : Bh) + (size_t)koff * ldb;
#pragma unroll
            for (int h = 0; h < 2; h++) {
                const int r = tb_row + h * 16;
                CP_ASYNC16(sB + bo + ((uint32_t)r * BROW + tb_ch * 8) * 2,
                           Bp + (size_t)r * ldb + tb_ch * 8);
            }
        } else {
            const __nv_bfloat16* Bp = (seg == 1 ? Bl : Bh) + koff;
#pragma unroll
            for (int h = 0; h < 2; h++) {
                const int r = lrow + h * 64;
                CP_ASYNC16(sB + bo + ((uint32_t)r * SROW + lchunk * 8) * 2,
                           Bp + (size_t)r * ldb + lchunk * 8);
            }
        }
    };

    load_tiles(0, 0);
    CP_COMMIT();

    int buf = 0;
    for (int cidx = 0; cidx < NC; cidx++) {
        if (cidx + 1 < NC) {
            load_tiles(buf ^ 1, cidx + 1);
            CP_COMMIT();
            CP_WAIT(1);
        } else {
            CP_WAIT(0);
        }
        __syncthreads();

        const uint32_t bo = (uint32_t)buf * BUF;
#pragma unroll
        for (int ks = 0; ks < 2; ks++) {
            uint32_t afr[4][4];
#pragma unroll
            for (int mt = 0; mt < 4; mt++)
                ldsm_x4(afr[mt], a_addr0 + bo + mt * (16 * SROW * 2) + ks * 32);
            uint32_t bfr[2][4];
            if (TRANSB) {
#pragma unroll
                for (int p = 0; p < 2; p++)
                    ldsm_x4_trans(bfr[p], b_addr_tr + bo + ks * (16 * BROW * 2) + p * 32);
            } else {
#pragma unroll
                for (int p = 0; p < 2; p++)
                    ldsm_x4(bfr[p], b_addr_nt + bo + p * (16 * SROW * 2) + ks * 32);
            }
#pragma unroll
            for (int mt = 0; mt < 4; mt++)
#pragma unroll
                for (int nt = 0; nt < 4; nt++)
                    mma16816(acc[mt][nt],
                             afr[mt][0], afr[mt][1], afr[mt][2], afr[mt][3],
                             bfr[nt >> 1][(nt & 1) * 2], bfr[nt >> 1][(nt & 1) * 2 + 1]);
        }
        __syncthreads();
        buf ^= 1;
    }

    // epilogue
    const int mb = m0 + wm * 64;
    const int nb = n0 + wn * 32;
#pragma unroll
    for (int mt = 0; mt < 4; mt++) {
#pragma unroll
        for (int nt = 0; nt < 4; nt++) {
            const int r  = mb + mt * 16 + (lane >> 2);
            const int cc = nb + nt * 8 + (lane & 3) * 2;
            float bx = 0.f, by = 0.f;
            if (bias) { bx = __ldg(&bias[cc]); by = __ldg(&bias[cc + 1]); }
            float v00 = acc[mt][nt][0] + bx, v01 = acc[mt][nt][1] + by;
            float v10 = acc[mt][nt][2] + bx, v11 = acc[mt][nt][3] + by;
            if (SPLITOUT) {
                unsigned short h0, l0, h1, l1;
                split2(v00, h0, l0); split2(v01, h1, l1);
                *(ushort2*)&Chi[bz * strideC + (size_t)r * ldc + cc] = make_ushort2(h0, h1);
                *(ushort2*)&Clo[bz * strideC + (size_t)r * ldc + cc] = make_ushort2(l0, l1);
                split2(v10, h0, l0); split2(v11, h1, l1);
                *(ushort2*)&Chi[bz * strideC + (size_t)(r + 8) * ldc + cc] = make_ushort2(h0, h1);
                *(ushort2*)&Clo[bz * strideC + (size_t)(r + 8) * ldc + cc] = make_ushort2(l0, l1);
            } else {
                float* Cb = C + bz * strideC;
                *(float2*)&Cb[(size_t)r * ldc + cc]       = make_float2(v00, v01);
                *(float2*)&Cb[(size_t)(r + 8) * ldc + cc] = make_float2(v10, v11);
            }
        }
    }
}

// ---------------------------------------------------------------------------
// Masked softmax in-place + fused bf16 hi/lo split
// ---------------------------------------------------------------------------
__global__ void softmax_mask_split(float* __restrict__ a,
                                   const int* __restrict__ x) {
    const int row = blockIdx.x;          // b*SEQ + s
    const int b = row / SEQ;
    float* p = a + (size_t)row * SRC;
    const int* xb = x + b * SRC;
    const int t = threadIdx.x;

    float v[4];
    float mx = -1e30f;
#pragma unroll
    for (int i = 0; i < 4; i++) {
        const int col = t + i * 256;
        float val = p[col];
        if (__ldg(&xb[col]) == 0) val -= 1e9f;
        v[i] = val;
        mx = fmaxf(mx, val);
    }
    __shared__ float red[256];
    red[t] = mx; __syncthreads();
#pragma unroll
    for (int s = 128; s > 0; s >>= 1) {
        if (t < s) red[t] = fmaxf(red[t], red[t + s]);
        __syncthreads();
    }
    mx = red[0]; __syncthreads();

    float sum = 0.f;
#pragma unroll
    for (int i = 0; i < 4; i++) { v[i] = __expf(v[i] - mx); sum += v[i]; }
    red[t] = sum; __syncthreads();
#pragma unroll
    for (int s = 128; s > 0; s >>= 1) {
        if (t < s) red[t] += red[t + s];
        __syncthreads();
    }
    const float inv = 1.0f / red[0];
    unsigned short* ah = (unsigned short*)g_a_hi + (size_t)row * SRC;
    unsigned short* al = (unsigned short*)g_a_lo + (size_t)row * SRC;
#pragma unroll
    for (int i = 0; i < 4; i++) {
        const int col = t + i * 256;
        const float val = v[i] * inv;
        p[col] = val;
        unsigned short h, l;
        split2(val, h, l);
        ah[col] = h; al[col] = l;
    }
}

// ---------------------------------------------------------------------------
extern "C" void kernel_launch(void* const* d_in, const int* in_sizes, int n_in,
                              void* d_out, int out_size) {
    const int*   x   = (const int*)  d_in[0];   // [32, 1024]
    const int*   yc  = (const int*)  d_in[1];   // [32, 640]
    const float* F   = (const float*)d_in[2];   // [32000, 512]
    const float* G   = (const float*)d_in[3];   // [32000, 512]
    const float* Pw  = (const float*)d_in[4];   // [2560, 512]
    const float* Pb  = (const float*)d_in[5];   // [512]

    float* out   = (float*)d_out;                       // [32,128,512]
    float* a_out = out + (size_t)BB * SEQ * DM;         // [32,128,1024]

    __nv_bfloat16 *xe_hi, *xe_lo, *yce_hi, *yce_lo,
                  *pwt_hi, *pwt_lo, *py_hi, *py_lo, *a_hi, *a_lo;
    cudaGetSymbolAddress((void**)&xe_hi,  g_xe_hi);
    cudaGetSymbolAddress((void**)&xe_lo,  g_xe_lo);
    cudaGetSymbolAddress((void**)&yce_hi, g_yce_hi);
    cudaGetSymbolAddress((void**)&yce_lo, g_yce_lo);
    cudaGetSymbolAddress((void**)&pwt_hi, g_pwt_hi);
    cudaGetSymbolAddress((void**)&pwt_lo, g_pwt_lo);
    cudaGetSymbolAddress((void**)&py_hi,  g_py_hi);
    cudaGetSymbolAddress((void**)&py_lo,  g_py_lo);
    cudaGetSymbolAddress((void**)&a_hi,   g_a_hi);
    cudaGetSymbolAddress((void**)&a_lo,   g_a_lo);

    // 1) gather + split source embeddings
    gather_split_xe<<<BB * SRC, 64>>>(x, F);
    // 2) gather + split target-context embeddings
    gather_split_yce<<<dim3(BB * SEQ, CTX), 64>>>(yc, G);
    // 3) transpose + split P_w
    split_pwt_kernel<<<dim3(KPY / 64, DM / 64), 256>>>(Pw);
    // 4) py = yce @ P_w + P_b  -> bf16 hi/lo directly  (M=4096, N=512, K=2560)
    mma_gemm_kernel<false, true><<<dim3(DM / 128, (BB * SEQ) / 128, 1), 256>>>(
        yce_hi, yce_lo, 0, KPY,
        pwt_hi, pwt_lo, 0, KPY,
        nullptr, py_hi, py_lo, 0, DM, Pb, KPY);
    // 5) logits a[b,s,x] = py[b,s,:] . xe[b,x,:]   (M=128, N=1024, K=512, batched)
    mma_gemm_kernel<false, false><<<dim3(SRC / 128, 1, BB), 256>>>(
        py_hi, py_lo, (size_t)SEQ * DM, DM,
        xe_hi, xe_lo, (size_t)SRC * DM, DM,
        a_out, nullptr, nullptr, (size_t)SEQ * SRC, SRC, nullptr, DM);
    // 6) masked softmax + split
    softmax_mask_split<<<BB * SEQ, 256>>>(a_out, x);
    // 7) out[b,s,d] = a[b,s,:] . xe[b,:,d]   (M=128, N=512, K=1024, batched, trans-B)
    mma_gemm_kernel<true, false><<<dim3(DM / 128, 1, BB), 256>>>(
        a_hi, a_lo, (size_t)SEQ * SRC, SRC,
        xe_hi, xe_lo, (size_t)SRC * DM, DM,
        out, nullptr, nullptr, (size_t)SEQ * DM, DM, nullptr, SRC);
}

// round 6
// speedup vs baseline: 2.6209x; 1.0997x over previous
#include <cuda_runtime.h>
#include <cuda_bf16.h>
#include <cstdint>

// Problem constants
#define BB   32
#define SRC  1024
#define SEQ  128
#define CTX  5
#define DM   512
#define KPY  (CTX*DM)   // 2560

// ---------------------------------------------------------------------------
// Scratch (device globals; no allocations allowed)
// ---------------------------------------------------------------------------
__device__ __nv_bfloat16 g_xe_hi [(size_t)BB*SRC*DM];
__device__ __nv_bfloat16 g_xe_lo [(size_t)BB*SRC*DM];
__device__ __nv_bfloat16 g_yce_hi[(size_t)BB*SEQ*KPY];
__device__ __nv_bfloat16 g_yce_lo[(size_t)BB*SEQ*KPY];
__device__ __nv_bfloat16 g_pwt_hi[(size_t)DM*KPY];
__device__ __nv_bfloat16 g_pwt_lo[(size_t)DM*KPY];
__device__ __nv_bfloat16 g_py_hi [(size_t)BB*SEQ*DM];
__device__ __nv_bfloat16 g_py_lo [(size_t)BB*SEQ*DM];
__device__ __nv_bfloat16 g_a_hi  [(size_t)BB*SEQ*SRC];
__device__ __nv_bfloat16 g_a_lo  [(size_t)BB*SEQ*SRC];

// ---------------------------------------------------------------------------
// Helpers
// ---------------------------------------------------------------------------
__device__ __forceinline__ uint32_t smem_to_u32(const void* p) {
    uint32_t a;
    asm("{ .reg .u64 t; cvta.to.shared.u64 t, %1; cvt.u32.u64 %0, t; }"
        : "=r"(a) : "l"(p));
    return a;
}

#define CP_ASYNC16(dst, src) \
    asm volatile("cp.async.cg.shared.global [%0], [%1], 16;" \
                 :: "r"(dst), "l"(src) : "memory")
#define CP_COMMIT() asm volatile("cp.async.commit_group;" ::: "memory")
#define CP_WAIT(N)  asm volatile("cp.async.wait_group %0;" :: "n"(N) : "memory")

__device__ __forceinline__ void ldsm_x4(uint32_t r[4], uint32_t addr) {
    asm volatile("ldmatrix.sync.aligned.m8n8.x4.shared.b16 {%0,%1,%2,%3}, [%4];"
                 : "=r"(r[0]), "=r"(r[1]), "=r"(r[2]), "=r"(r[3]) : "r"(addr));
}
__device__ __forceinline__ void ldsm_x4_trans(uint32_t r[4], uint32_t addr) {
    asm volatile("ldmatrix.sync.aligned.m8n8.x4.trans.shared.b16 {%0,%1,%2,%3}, [%4];"
                 : "=r"(r[0]), "=r"(r[1]), "=r"(r[2]), "=r"(r[3]) : "r"(addr));
}

__device__ __forceinline__ void mma16816(float c[4],
                                         uint32_t a0, uint32_t a1, uint32_t a2, uint32_t a3,
                                         uint32_t b0, uint32_t b1) {
    asm volatile("mma.sync.aligned.m16n8k16.row.col.f32.bf16.bf16.f32 "
                 "{%0,%1,%2,%3}, {%4,%5,%6,%7}, {%8,%9}, {%0,%1,%2,%3};"
                 : "+f"(c[0]), "+f"(c[1]), "+f"(c[2]), "+f"(c[3])
                 : "r"(a0), "r"(a1), "r"(a2), "r"(a3), "r"(b0), "r"(b1));
}

// fp32 -> (bf16 hi, bf16 lo) split
__device__ __forceinline__ void split2(float v, unsigned short& h, unsigned short& l) {
    __nv_bfloat16 hb = __float2bfloat16(v);
    __nv_bfloat16 lb = __float2bfloat16(v - __bfloat162float(hb));
    h = __bfloat16_as_ushort(hb);
    l = __bfloat16_as_ushort(lb);
}

// ---------------------------------------------------------------------------
// Prep: gather + split xe (row = b*SRC + i)
// ---------------------------------------------------------------------------
__global__ void gather_split_xe(const int* __restrict__ x, const float* __restrict__ F) {
    const int row = blockIdx.x;
    const int tok = __ldg(&x[row]);
    const int t = threadIdx.x;
    const float4* src = (const float4*)(F + (size_t)tok * DM);
    float4 a = __ldg(&src[t * 2]);
    float4 b = __ldg(&src[t * 2 + 1]);
    float v[8] = {a.x, a.y, a.z, a.w, b.x, b.y, b.z, b.w};
    union { unsigned short us[8]; uint4 u; } H, L;
#pragma unroll
    for (int i = 0; i < 8; i++) split2(v[i], H.us[i], L.us[i]);
    *(uint4*)(g_xe_hi + (size_t)row * DM + t * 8) = H.u;
    *(uint4*)(g_xe_lo + (size_t)row * DM + t * 8) = L.u;
}

// ---------------------------------------------------------------------------
// Prep: gather + split yce  (grid = (4096, 5), 64 threads)
// ---------------------------------------------------------------------------
__global__ void gather_split_yce(const int* __restrict__ yc, const float* __restrict__ G) {
    const int m = blockIdx.x;
    const int c = blockIdx.y;
    const int tok = __ldg(&yc[m * CTX + c]);
    const int t = threadIdx.x;
    const float4* src = (const float4*)(G + (size_t)tok * DM);
    float4 a = __ldg(&src[t * 2]);
    float4 b = __ldg(&src[t * 2 + 1]);
    float v[8] = {a.x, a.y, a.z, a.w, b.x, b.y, b.z, b.w};
    union { unsigned short us[8]; uint4 u; } H, L;
#pragma unroll
    for (int i = 0; i < 8; i++) split2(v[i], H.us[i], L.us[i]);
    const size_t off = (size_t)m * KPY + c * DM + t * 8;
    *(uint4*)(g_yce_hi + off) = H.u;
    *(uint4*)(g_yce_lo + off) = L.u;
}

// ---------------------------------------------------------------------------
// Prep: transpose + split P_w [2560,512] -> PwT hi/lo [512][2560]
// ---------------------------------------------------------------------------
__global__ void split_pwt_kernel(const float* __restrict__ Pw) {
    __shared__ float s[64][65];
    const int k0 = blockIdx.x * 64;
    const int n0 = blockIdx.y * 64;
    const int tx = threadIdx.x & 31, ty = threadIdx.x >> 5;
#pragma unroll
    for (int i = 0; i < 8; i++) {
        const int r = ty + i * 8;                           // local k
        float2 v = *(const float2*)(Pw + (size_t)(k0 + r) * DM + n0 + tx * 2);
        s[r][tx * 2] = v.x; s[r][tx * 2 + 1] = v.y;
    }
    __syncthreads();
#pragma unroll
    for (int i = 0; i < 8; i++) {
        const int nr = ty + i * 8;                          // local n
        float v0 = s[tx * 2][nr], v1 = s[tx * 2 + 1][nr];
        unsigned short h0, l0, h1, l1;
        split2(v0, h0, l0); split2(v1, h1, l1);
        const size_t off = (size_t)(n0 + nr) * KPY + k0 + tx * 2;
        *(unsigned*)((unsigned short*)g_pwt_hi + off) = (unsigned)h0 | ((unsigned)h1 << 16);
        *(unsigned*)((unsigned short*)g_pwt_lo + off) = (unsigned)l0 | ((unsigned)l1 << 16);
    }
}

// ---------------------------------------------------------------------------
// mma.sync GEMM, virtual K' = 3K: A' = [Ahi|Ahi|Alo], B' = [Bhi|Blo|Bhi].
// CTA tile 128x128, BK=32, 8 warps (2m x 4n), warp tile 64x32, m16n8k16.
// 4-stage cp.async pipeline, ONE __syncthreads per chunk.
// ---------------------------------------------------------------------------
#define SROW 40                    // A smem row stride (halves)
#define BROW 136                   // trans-B smem row stride (halves)
#define ATILE_B (128 * SROW * 2)   // 10240
#define BTILE_NT (128 * SROW * 2)  // 10240
#define BTILE_TR (32 * BROW * 2)   // 8704
#define STAGES 4

template<bool TRANSB, bool SPLITOUT>
__global__ __launch_bounds__(256)
void mma_gemm_kernel(const __nv_bfloat16* __restrict__ Ahi, const __nv_bfloat16* __restrict__ Alo,
                     size_t strideA, int lda,
                     const __nv_bfloat16* __restrict__ Bhi, const __nv_bfloat16* __restrict__ Blo,
                     size_t strideB, int ldb,
                     float* __restrict__ C,
                     __nv_bfloat16* __restrict__ Chi, __nv_bfloat16* __restrict__ Clo,
                     size_t strideC, int ldc,
                     const float* __restrict__ bias, int K) {
    constexpr int BTILE = TRANSB ? BTILE_TR : BTILE_NT;
    constexpr int BUF   = ATILE_B + BTILE;
    extern __shared__ __align__(16) unsigned char smbuf[];
    const uint32_t s_base = smem_to_u32(smbuf);
    const uint32_t sA = s_base;
    const uint32_t sB = s_base + ATILE_B;

    const int tid  = threadIdx.x;
    const int lane = tid & 31;
    const int wid  = tid >> 5;
    const int wm   = wid & 1;       // m offset 0/64
    const int wn   = wid >> 1;      // n offset 0/32/64/96
    const int quad = lane >> 3;
    const int l8   = lane & 7;

    const int m0 = blockIdx.y * 128;
    const int n0 = blockIdx.x * 128;
    const size_t bz = blockIdx.z;
    const __nv_bfloat16* Ah = Ahi + bz * strideA + (size_t)m0 * lda;
    const __nv_bfloat16* Al = Alo + bz * strideA + (size_t)m0 * lda;
    const __nv_bfloat16* Bh;
    const __nv_bfloat16* Bl;
    if (TRANSB) { Bh = Bhi + bz * strideB + n0; Bl = Blo + bz * strideB + n0; }
    else        { Bh = Bhi + bz * strideB + (size_t)n0 * ldb;
                  Bl = Blo + bz * strideB + (size_t)n0 * ldb; }

    // A loader: 256 threads -> 128 rows x 4 chunks(16B), x2
    const int lrow   = tid >> 2;
    const int lchunk = tid & 3;
    // trans-B loader: 32 rows x 16 chunks(16B), x2
    const int tb_row = tid >> 4;
    const int tb_ch  = tid & 15;

    // ldmatrix base addresses (stage 0)
    const uint32_t a_addr0 = sA + ((uint32_t)(wm * 64 + (quad & 1) * 8 + l8) * SROW
                                   + (quad >> 1) * 8) * 2;
    const uint32_t b_addr_nt = sB + ((uint32_t)(wn * 32 + (quad >> 1) * 8 + l8) * SROW
                                     + (quad & 1) * 8) * 2;
    const uint32_t b_addr_tr = sB + ((uint32_t)((quad & 1) * 8 + l8) * BROW
                                     + wn * 32 + (quad >> 1) * 8) * 2;

    float acc[4][4][4];
#pragma unroll
    for (int i = 0; i < 4; i++)
#pragma unroll
        for (int j = 0; j < 4; j++)
#pragma unroll
            for (int r = 0; r < 4; r++) acc[i][j][r] = 0.f;

    const int NC = 3 * K / 32;

    auto load_tiles = [&](int stage, int cidx) {
        const int kp   = cidx * 32;
        const int seg  = kp / K;
        const int koff = kp - seg * K;
        const __nv_bfloat16* Ap = (seg < 2 ? Ah : Al) + koff;
        const uint32_t bo = (uint32_t)stage * BUF;
#pragma unroll
        for (int h = 0; h < 2; h++) {
            const int r = lrow + h * 64;
            CP_ASYNC16(sA + bo + ((uint32_t)r * SROW + lchunk * 8) * 2,
                       Ap + (size_t)r * lda + lchunk * 8);
        }
        if (TRANSB) {
            const __nv_bfloat16* Bp = (seg == 1 ? Bl : Bh) + (size_t)koff * ldb;
#pragma unroll
            for (int h = 0; h < 2; h++) {
                const int r = tb_row + h * 16;
                CP_ASYNC16(sB + bo + ((uint32_t)r * BROW + tb_ch * 8) * 2,
                           Bp + (size_t)r * ldb + tb_ch * 8);
            }
        } else {
            const __nv_bfloat16* Bp = (seg == 1 ? Bl : Bh) + koff;
#pragma unroll
            for (int h = 0; h < 2; h++) {
                const int r = lrow + h * 64;
                CP_ASYNC16(sB + bo + ((uint32_t)r * SROW + lchunk * 8) * 2,
                           Bp + (size_t)r * ldb + lchunk * 8);
            }
        }
    };

    // prologue: fill stages 0..2
#pragma unroll
    for (int s = 0; s < STAGES - 1; s++) {
        if (s < NC) load_tiles(s, s);
        CP_COMMIT();
    }

    for (int cidx = 0; cidx < NC; cidx++) {
        CP_WAIT(STAGES - 2);          // stage cidx%4 resident
        __syncthreads();              // all warps done with buffer being refilled next

        const uint32_t bo = (uint32_t)(cidx & (STAGES - 1)) * BUF;
#pragma unroll
        for (int ks = 0; ks < 2; ks++) {
            uint32_t afr[4][4];
#pragma unroll
            for (int mt = 0; mt < 4; mt++)
                ldsm_x4(afr[mt], a_addr0 + bo + mt * (16 * SROW * 2) + ks * 32);
            uint32_t bfr[2][4];
            if (TRANSB) {
#pragma unroll
                for (int p = 0; p < 2; p++)
                    ldsm_x4_trans(bfr[p], b_addr_tr + bo + ks * (16 * BROW * 2) + p * 32);
            } else {
#pragma unroll
                for (int p = 0; p < 2; p++)
                    ldsm_x4(bfr[p], b_addr_nt + bo + p * (16 * SROW * 2) + ks * 32);
            }
#pragma unroll
            for (int mt = 0; mt < 4; mt++)
#pragma unroll
                for (int nt = 0; nt < 4; nt++)
                    mma16816(acc[mt][nt],
                             afr[mt][0], afr[mt][1], afr[mt][2], afr[mt][3],
                             bfr[nt >> 1][(nt & 1) * 2], bfr[nt >> 1][(nt & 1) * 2 + 1]);
        }

        // refill the stage consumed (STAGES-1) iterations ago
        const int nxt = cidx + STAGES - 1;
        if (nxt < NC) load_tiles(nxt & (STAGES - 1), nxt);
        CP_COMMIT();                  // keep group count aligned (may be empty)
    }

    // epilogue
    const int mb = m0 + wm * 64;
    const int nb = n0 + wn * 32;
#pragma unroll
    for (int mt = 0; mt < 4; mt++) {
#pragma unroll
        for (int nt = 0; nt < 4; nt++) {
            const int r  = mb + mt * 16 + (lane >> 2);
            const int cc = nb + nt * 8 + (lane & 3) * 2;
            float bx = 0.f, by = 0.f;
            if (bias) { bx = __ldg(&bias[cc]); by = __ldg(&bias[cc + 1]); }
            float v00 = acc[mt][nt][0] + bx, v01 = acc[mt][nt][1] + by;
            float v10 = acc[mt][nt][2] + bx, v11 = acc[mt][nt][3] + by;
            if (SPLITOUT) {
                unsigned short h0, l0, h1, l1;
                split2(v00, h0, l0); split2(v01, h1, l1);
                *(ushort2*)&Chi[bz * strideC + (size_t)r * ldc + cc] = make_ushort2(h0, h1);
                *(ushort2*)&Clo[bz * strideC + (size_t)r * ldc + cc] = make_ushort2(l0, l1);
                split2(v10, h0, l0); split2(v11, h1, l1);
                *(ushort2*)&Chi[bz * strideC + (size_t)(r + 8) * ldc + cc] = make_ushort2(h0, h1);
                *(ushort2*)&Clo[bz * strideC + (size_t)(r + 8) * ldc + cc] = make_ushort2(l0, l1);
            } else {
                float* Cb = C + bz * strideC;
                *(float2*)&Cb[(size_t)r * ldc + cc]       = make_float2(v00, v01);
                *(float2*)&Cb[(size_t)(r + 8) * ldc + cc] = make_float2(v10, v11);
            }
        }
    }
}

// ---------------------------------------------------------------------------
// Masked softmax in-place + fused bf16 hi/lo split
// ---------------------------------------------------------------------------
__global__ void softmax_mask_split(float* __restrict__ a,
                                   const int* __restrict__ x) {
    const int row = blockIdx.x;          // b*SEQ + s
    const int b = row / SEQ;
    float* p = a + (size_t)row * SRC;
    const int* xb = x + b * SRC;
    const int t = threadIdx.x;

    float v[4];
    float mx = -1e30f;
#pragma unroll
    for (int i = 0; i < 4; i++) {
        const int col = t + i * 256;
        float val = p[col];
        if (__ldg(&xb[col]) == 0) val -= 1e9f;
        v[i] = val;
        mx = fmaxf(mx, val);
    }
    __shared__ float red[256];
    red[t] = mx; __syncthreads();
#pragma unroll
    for (int s = 128; s > 0; s >>= 1) {
        if (t < s) red[t] = fmaxf(red[t], red[t + s]);
        __syncthreads();
    }
    mx = red[0]; __syncthreads();

    float sum = 0.f;
#pragma unroll
    for (int i = 0; i < 4; i++) { v[i] = __expf(v[i] - mx); sum += v[i]; }
    red[t] = sum; __syncthreads();
#pragma unroll
    for (int s = 128; s > 0; s >>= 1) {
        if (t < s) red[t] += red[t + s];
        __syncthreads();
    }
    const float inv = 1.0f / red[0];
    unsigned short* ah = (unsigned short*)g_a_hi + (size_t)row * SRC;
    unsigned short* al = (unsigned short*)g_a_lo + (size_t)row * SRC;
#pragma unroll
    for (int i = 0; i < 4; i++) {
        const int col = t + i * 256;
        const float val = v[i] * inv;
        p[col] = val;
        unsigned short h, l;
        split2(val, h, l);
        ah[col] = h; al[col] = l;
    }
}

// ---------------------------------------------------------------------------
extern "C" void kernel_launch(void* const* d_in, const int* in_sizes, int n_in,
                              void* d_out, int out_size) {
    const int*   x   = (const int*)  d_in[0];   // [32, 1024]
    const int*   yc  = (const int*)  d_in[1];   // [32, 640]
    const float* F   = (const float*)d_in[2];   // [32000, 512]
    const float* G   = (const float*)d_in[3];   // [32000, 512]
    const float* Pw  = (const float*)d_in[4];   // [2560, 512]
    const float* Pb  = (const float*)d_in[5];   // [512]

    float* out   = (float*)d_out;                       // [32,128,512]
    float* a_out = out + (size_t)BB * SEQ * DM;         // [32,128,1024]

    constexpr int SMEM_NT = STAGES * (ATILE_B + BTILE_NT);   // 81920
    constexpr int SMEM_TR = STAGES * (ATILE_B + BTILE_TR);   // 75776
    cudaFuncSetAttribute(mma_gemm_kernel<false, true>,
                         cudaFuncAttributeMaxDynamicSharedMemorySize, SMEM_NT);
    cudaFuncSetAttribute(mma_gemm_kernel<false, false>,
                         cudaFuncAttributeMaxDynamicSharedMemorySize, SMEM_NT);
    cudaFuncSetAttribute(mma_gemm_kernel<true, false>,
                         cudaFuncAttributeMaxDynamicSharedMemorySize, SMEM_TR);

    __nv_bfloat16 *xe_hi, *xe_lo, *yce_hi, *yce_lo,
                  *pwt_hi, *pwt_lo, *py_hi, *py_lo, *a_hi, *a_lo;
    cudaGetSymbolAddress((void**)&xe_hi,  g_xe_hi);
    cudaGetSymbolAddress((void**)&xe_lo,  g_xe_lo);
    cudaGetSymbolAddress((void**)&yce_hi, g_yce_hi);
    cudaGetSymbolAddress((void**)&yce_lo, g_yce_lo);
    cudaGetSymbolAddress((void**)&pwt_hi, g_pwt_hi);
    cudaGetSymbolAddress((void**)&pwt_lo, g_pwt_lo);
    cudaGetSymbolAddress((void**)&py_hi,  g_py_hi);
    cudaGetSymbolAddress((void**)&py_lo,  g_py_lo);
    cudaGetSymbolAddress((void**)&a_hi,   g_a_hi);
    cudaGetSymbolAddress((void**)&a_lo,   g_a_lo);

    // 1) gather + split source embeddings
    gather_split_xe<<<BB * SRC, 64>>>(x, F);
    // 2) gather + split target-context embeddings
    gather_split_yce<<<dim3(BB * SEQ, CTX), 64>>>(yc, G);
    // 3) transpose + split P_w
    split_pwt_kernel<<<dim3(KPY / 64, DM / 64), 256>>>(Pw);
    // 4) py = yce @ P_w + P_b  -> bf16 hi/lo directly  (M=4096, N=512, K=2560)
    mma_gemm_kernel<false, true><<<dim3(DM / 128, (BB * SEQ) / 128, 1), 256, SMEM_NT>>>(
        yce_hi, yce_lo, 0, KPY,
        pwt_hi, pwt_lo, 0, KPY,
        nullptr, py_hi, py_lo, 0, DM, Pb, KPY);
    // 5) logits a[b,s,x] = py[b,s,:] . xe[b,x,:]   (M=128, N=1024, K=512, batched)
    mma_gemm_kernel<false, false><<<dim3(SRC / 128, 1, BB), 256, SMEM_NT>>>(
        py_hi, py_lo, (size_t)SEQ * DM, DM,
        xe_hi, xe_lo, (size_t)SRC * DM, DM,
        a_out, nullptr, nullptr, (size_t)SEQ * SRC, SRC, nullptr, DM);
    // 6) masked softmax + split
    softmax_mask_split<<<BB * SEQ, 256>>>(a_out, x);
    // 7) out[b,s,d] = a[b,s,:] . xe[b,:,d]   (M=128, N=512, K=1024, batched, trans-B)
    mma_gemm_kernel<true, false><<<dim3(DM / 128, 1, BB), 256, SMEM_TR>>>(
        a_hi, a_lo, (size_t)SEQ * SRC, SRC,
        xe_hi, xe_lo, (size_t)SRC * DM, DM,
        out, nullptr, nullptr, (size_t)SEQ * DM, DM, nullptr, SRC);
}

// round 7
// speedup vs baseline: 3.2322x; 1.2332x over previous
#include <cuda_runtime.h>
#include <cuda_bf16.h>
#include <cstdint>

// Problem constants
#define BB   32
#define SRC  1024
#define SEQ  128
#define CTX  5
#define DM   512
#define KPY  (CTX*DM)   // 2560

// ---------------------------------------------------------------------------
// Scratch (device globals; no allocations allowed)
// ---------------------------------------------------------------------------
__device__ __nv_bfloat16 g_xe_hi [(size_t)BB*SRC*DM];
__device__ __nv_bfloat16 g_xe_lo [(size_t)BB*SRC*DM];
__device__ __nv_bfloat16 g_yce_hi[(size_t)BB*SEQ*KPY];
__device__ __nv_bfloat16 g_yce_lo[(size_t)BB*SEQ*KPY];
__device__ __nv_bfloat16 g_pwt_hi[(size_t)DM*KPY];
__device__ __nv_bfloat16 g_pwt_lo[(size_t)DM*KPY];
__device__ __nv_bfloat16 g_py_hi [(size_t)BB*SEQ*DM];
__device__ __nv_bfloat16 g_py_lo [(size_t)BB*SEQ*DM];
__device__ __nv_bfloat16 g_a_hi  [(size_t)BB*SEQ*SRC];
__device__ __nv_bfloat16 g_a_lo  [(size_t)BB*SEQ*SRC];
__device__ float         g_part  [(size_t)2*BB*SEQ*DM];   // 16MB split-K partials

// ---------------------------------------------------------------------------
// Helpers
// ---------------------------------------------------------------------------
__device__ __forceinline__ uint32_t smem_to_u32(const void* p) {
    uint32_t a;
    asm("{ .reg .u64 t; cvta.to.shared.u64 t, %1; cvt.u32.u64 %0, t; }"
        : "=r"(a) : "l"(p));
    return a;
}

#define CP_ASYNC16(dst, src) \
    asm volatile("cp.async.cg.shared.global [%0], [%1], 16;" \
                 :: "r"(dst), "l"(src) : "memory")
#define CP_COMMIT() asm volatile("cp.async.commit_group;" ::: "memory")
#define CP_WAIT(N)  asm volatile("cp.async.wait_group %0;" :: "n"(N) : "memory")

__device__ __forceinline__ void ldsm_x4(uint32_t r[4], uint32_t addr) {
    asm volatile("ldmatrix.sync.aligned.m8n8.x4.shared.b16 {%0,%1,%2,%3}, [%4];"
                 : "=r"(r[0]), "=r"(r[1]), "=r"(r[2]), "=r"(r[3]) : "r"(addr));
}
__device__ __forceinline__ void ldsm_x4_trans(uint32_t r[4], uint32_t addr) {
    asm volatile("ldmatrix.sync.aligned.m8n8.x4.trans.shared.b16 {%0,%1,%2,%3}, [%4];"
                 : "=r"(r[0]), "=r"(r[1]), "=r"(r[2]), "=r"(r[3]) : "r"(addr));
}

__device__ __forceinline__ void mma16816(float c[4],
                                         uint32_t a0, uint32_t a1, uint32_t a2, uint32_t a3,
                                         uint32_t b0, uint32_t b1) {
    asm volatile("mma.sync.aligned.m16n8k16.row.col.f32.bf16.bf16.f32 "
                 "{%0,%1,%2,%3}, {%4,%5,%6,%7}, {%8,%9}, {%0,%1,%2,%3};"
                 : "+f"(c[0]), "+f"(c[1]), "+f"(c[2]), "+f"(c[3])
                 : "r"(a0), "r"(a1), "r"(a2), "r"(a3), "r"(b0), "r"(b1));
}

// fp32 -> (bf16 hi, bf16 lo) split
__device__ __forceinline__ void split2(float v, unsigned short& h, unsigned short& l) {
    __nv_bfloat16 hb = __float2bfloat16(v);
    __nv_bfloat16 lb = __float2bfloat16(v - __bfloat162float(hb));
    h = __bfloat16_as_ushort(hb);
    l = __bfloat16_as_ushort(lb);
}

// ---------------------------------------------------------------------------
// Prep: gather + split xe (row = b*SRC + i)
// ---------------------------------------------------------------------------
__global__ void gather_split_xe(const int* __restrict__ x, const float* __restrict__ F) {
    const int row = blockIdx.x;
    const int tok = __ldg(&x[row]);
    const int t = threadIdx.x;
    const float4* src = (const float4*)(F + (size_t)tok * DM);
    float4 a = __ldg(&src[t * 2]);
    float4 b = __ldg(&src[t * 2 + 1]);
    float v[8] = {a.x, a.y, a.z, a.w, b.x, b.y, b.z, b.w};
    union { unsigned short us[8]; uint4 u; } H, L;
#pragma unroll
    for (int i = 0; i < 8; i++) split2(v[i], H.us[i], L.us[i]);
    *(uint4*)(g_xe_hi + (size_t)row * DM + t * 8) = H.u;
    *(uint4*)(g_xe_lo + (size_t)row * DM + t * 8) = L.u;
}

// ---------------------------------------------------------------------------
// Prep: gather + split yce  (grid = (4096, 5), 64 threads)
// ---------------------------------------------------------------------------
__global__ void gather_split_yce(const int* __restrict__ yc, const float* __restrict__ G) {
    const int m = blockIdx.x;
    const int c = blockIdx.y;
    const int tok = __ldg(&yc[m * CTX + c]);
    const int t = threadIdx.x;
    const float4* src = (const float4*)(G + (size_t)tok * DM);
    float4 a = __ldg(&src[t * 2]);
    float4 b = __ldg(&src[t * 2 + 1]);
    float v[8] = {a.x, a.y, a.z, a.w, b.x, b.y, b.z, b.w};
    union { unsigned short us[8]; uint4 u; } H, L;
#pragma unroll
    for (int i = 0; i < 8; i++) split2(v[i], H.us[i], L.us[i]);
    const size_t off = (size_t)m * KPY + c * DM + t * 8;
    *(uint4*)(g_yce_hi + off) = H.u;
    *(uint4*)(g_yce_lo + off) = L.u;
}

// ---------------------------------------------------------------------------
// Prep: transpose + split P_w [2560,512] -> PwT hi/lo [512][2560]
// ---------------------------------------------------------------------------
__global__ void split_pwt_kernel(const float* __restrict__ Pw) {
    __shared__ float s[64][65];
    const int k0 = blockIdx.x * 64;
    const int n0 = blockIdx.y * 64;
    const int tx = threadIdx.x & 31, ty = threadIdx.x >> 5;
#pragma unroll
    for (int i = 0; i < 8; i++) {
        const int r = ty + i * 8;                           // local k
        float2 v = *(const float2*)(Pw + (size_t)(k0 + r) * DM + n0 + tx * 2);
        s[r][tx * 2] = v.x; s[r][tx * 2 + 1] = v.y;
    }
    __syncthreads();
#pragma unroll
    for (int i = 0; i < 8; i++) {
        const int nr = ty + i * 8;                          // local n
        float v0 = s[tx * 2][nr], v1 = s[tx * 2 + 1][nr];
        unsigned short h0, l0, h1, l1;
        split2(v0, h0, l0); split2(v1, h1, l1);
        const size_t off = (size_t)(n0 + nr) * KPY + k0 + tx * 2;
        *(unsigned*)((unsigned short*)g_pwt_hi + off) = (unsigned)h0 | ((unsigned)h1 << 16);
        *(unsigned*)((unsigned short*)g_pwt_lo + off) = (unsigned)l0 | ((unsigned)l1 << 16);
    }
}

// ---------------------------------------------------------------------------
// mma.sync GEMM, virtual K' = 3K: A' = [Ahi|Ahi|Alo], B' = [Bhi|Blo|Bhi].
// CTA tile 128x128, BK=32, 8 warps (2m x 4n), warp tile 64x32, m16n8k16.
// 4-stage cp.async pipeline, one __syncthreads per chunk, fp32 output.
// Optional split-K: blockIdx.z = batch*ksplit + s; s handles chunk range
// [s*NC/ksplit, (s+1)*NC/ksplit); C offset += s*strideS.
// ---------------------------------------------------------------------------
#define SROW 40                    // A smem row stride (halves)
#define BROW 136                   // trans-B smem row stride (halves)
#define ATILE_B (128 * SROW * 2)   // 10240
#define BTILE_NT (128 * SROW * 2)  // 10240
#define BTILE_TR (32 * BROW * 2)   // 8704
#define STAGES 4

template<bool TRANSB>
__global__ __launch_bounds__(256, 2)
void mma_gemm_kernel(const __nv_bfloat16* __restrict__ Ahi, const __nv_bfloat16* __restrict__ Alo,
                     size_t strideA, int lda,
                     const __nv_bfloat16* __restrict__ Bhi, const __nv_bfloat16* __restrict__ Blo,
                     size_t strideB, int ldb,
                     float* __restrict__ C, size_t strideC, int ldc,
                     int ksplit, size_t strideS, int K) {
    constexpr int BTILE = TRANSB ? BTILE_TR : BTILE_NT;
    constexpr int BUF   = ATILE_B + BTILE;
    extern __shared__ __align__(16) unsigned char smbuf[];
    const uint32_t s_base = smem_to_u32(smbuf);
    const uint32_t sA = s_base;
    const uint32_t sB = s_base + ATILE_B;

    const int tid  = threadIdx.x;
    const int lane = tid & 31;
    const int wid  = tid >> 5;
    const int wm   = wid & 1;       // m offset 0/64
    const int wn   = wid >> 1;      // n offset 0/32/64/96
    const int quad = lane >> 3;
    const int l8   = lane & 7;

    const int m0 = blockIdx.y * 128;
    const int n0 = blockIdx.x * 128;
    const int z  = blockIdx.z;
    const int s_k = z % ksplit;
    const size_t bz = z / ksplit;

    const __nv_bfloat16* Ah = Ahi + bz * strideA + (size_t)m0 * lda;
    const __nv_bfloat16* Al = Alo + bz * strideA + (size_t)m0 * lda;
    const __nv_bfloat16* Bh;
    const __nv_bfloat16* Bl;
    if (TRANSB) { Bh = Bhi + bz * strideB + n0; Bl = Blo + bz * strideB + n0; }
    else        { Bh = Bhi + bz * strideB + (size_t)n0 * ldb;
                  Bl = Blo + bz * strideB + (size_t)n0 * ldb; }

    // A loader: 256 threads -> 128 rows x 4 chunks(16B), x2
    const int lrow   = tid >> 2;
    const int lchunk = tid & 3;
    // trans-B loader: 32 rows x 16 chunks(16B), x2
    const int tb_row = tid >> 4;
    const int tb_ch  = tid & 15;

    // ldmatrix base addresses (stage 0)
    const uint32_t a_addr0 = sA + ((uint32_t)(wm * 64 + (quad & 1) * 8 + l8) * SROW
                                   + (quad >> 1) * 8) * 2;
    const uint32_t b_addr_nt = sB + ((uint32_t)(wn * 32 + (quad >> 1) * 8 + l8) * SROW
                                     + (quad & 1) * 8) * 2;
    const uint32_t b_addr_tr = sB + ((uint32_t)((quad & 1) * 8 + l8) * BROW
                                     + wn * 32 + (quad >> 1) * 8) * 2;

    float acc[4][4][4];
#pragma unroll
    for (int i = 0; i < 4; i++)
#pragma unroll
        for (int j = 0; j < 4; j++)
#pragma unroll
            for (int r = 0; r < 4; r++) acc[i][j][r] = 0.f;

    const int NC = 3 * K / 32;
    const int cspan = NC / ksplit;
    const int c0 = s_k * cspan;
    const int c1 = c0 + cspan;

    auto load_tiles = [&](int stage, int cidx) {
        const int kp   = cidx * 32;
        const int seg  = kp / K;
        const int koff = kp - seg * K;
        const __nv_bfloat16* Ap = (seg < 2 ? Ah : Al) + koff;
        const uint32_t bo = (uint32_t)stage * BUF;
#pragma unroll
        for (int h = 0; h < 2; h++) {
            const int r = lrow + h * 64;
            CP_ASYNC16(sA + bo + ((uint32_t)r * SROW + lchunk * 8) * 2,
                       Ap + (size_t)r * lda + lchunk * 8);
        }
        if (TRANSB) {
            const __nv_bfloat16* Bp = (seg == 1 ? Bl : Bh) + (size_t)koff * ldb;
#pragma unroll
            for (int h = 0; h < 2; h++) {
                const int r = tb_row + h * 16;
                CP_ASYNC16(sB + bo + ((uint32_t)r * BROW + tb_ch * 8) * 2,
                           Bp + (size_t)r * ldb + tb_ch * 8);
            }
        } else {
            const __nv_bfloat16* Bp = (seg == 1 ? Bl : Bh) + koff;
#pragma unroll
            for (int h = 0; h < 2; h++) {
                const int r = lrow + h * 64;
                CP_ASYNC16(sB + bo + ((uint32_t)r * SROW + lchunk * 8) * 2,
                           Bp + (size_t)r * ldb + lchunk * 8);
            }
        }
    };

    // prologue: fill stages for first 3 chunks
#pragma unroll
    for (int s = 0; s < STAGES - 1; s++) {
        if (c0 + s < c1) load_tiles(s, c0 + s);
        CP_COMMIT();
    }

    for (int cidx = c0; cidx < c1; cidx++) {
        CP_WAIT(STAGES - 2);
        __syncthreads();

        const uint32_t bo = (uint32_t)((cidx - c0) & (STAGES - 1)) * BUF;
#pragma unroll
        for (int ks = 0; ks < 2; ks++) {
            uint32_t afr[4][4];
#pragma unroll
            for (int mt = 0; mt < 4; mt++)
                ldsm_x4(afr[mt], a_addr0 + bo + mt * (16 * SROW * 2) + ks * 32);
            uint32_t bfr[2][4];
            if (TRANSB) {
#pragma unroll
                for (int p = 0; p < 2; p++)
                    ldsm_x4_trans(bfr[p], b_addr_tr + bo + ks * (16 * BROW * 2) + p * 32);
            } else {
#pragma unroll
                for (int p = 0; p < 2; p++)
                    ldsm_x4(bfr[p], b_addr_nt + bo + p * (16 * SROW * 2) + ks * 32);
            }
#pragma unroll
            for (int mt = 0; mt < 4; mt++)
#pragma unroll
                for (int nt = 0; nt < 4; nt++)
                    mma16816(acc[mt][nt],
                             afr[mt][0], afr[mt][1], afr[mt][2], afr[mt][3],
                             bfr[nt >> 1][(nt & 1) * 2], bfr[nt >> 1][(nt & 1) * 2 + 1]);
        }

        const int nxt = cidx + STAGES - 1;
        if (nxt < c1) load_tiles((nxt - c0) & (STAGES - 1), nxt);
        CP_COMMIT();
    }

    // epilogue (fp32)
    float* Cb = C + (size_t)s_k * strideS + bz * strideC;
    const int mb = m0 + wm * 64;
    const int nb = n0 + wn * 32;
#pragma unroll
    for (int mt = 0; mt < 4; mt++) {
#pragma unroll
        for (int nt = 0; nt < 4; nt++) {
            const int r  = mb + mt * 16 + (lane >> 2);
            const int cc = nb + nt * 8 + (lane & 3) * 2;
            *(float2*)&Cb[(size_t)r * ldc + cc] =
                make_float2(acc[mt][nt][0], acc[mt][nt][1]);
            *(float2*)&Cb[(size_t)(r + 8) * ldc + cc] =
                make_float2(acc[mt][nt][2], acc[mt][nt][3]);
        }
    }
}

// ---------------------------------------------------------------------------
// Split-K reduce for py: py = part0 + part1 + bias -> bf16 hi/lo
// grid = 4096, 64 threads x 8 elems
// ---------------------------------------------------------------------------
__global__ void reduce_bias_split_py(const float* __restrict__ Pb) {
    const int row = blockIdx.x;
    const int t = threadIdx.x;
    const float* p0 = g_part + (size_t)row * DM;
    const float* p1 = p0 + (size_t)BB * SEQ * DM;
    float4 a0 = *(const float4*)(p0 + t * 8);
    float4 a1 = *(const float4*)(p0 + t * 8 + 4);
    float4 b0 = *(const float4*)(p1 + t * 8);
    float4 b1 = *(const float4*)(p1 + t * 8 + 4);
    float4 c0 = __ldg((const float4*)(Pb + t * 8));
    float4 c1 = __ldg((const float4*)(Pb + t * 8 + 4));
    float v[8] = {a0.x + b0.x + c0.x, a0.y + b0.y + c0.y,
                  a0.z + b0.z + c0.z, a0.w + b0.w + c0.w,
                  a1.x + b1.x + c1.x, a1.y + b1.y + c1.y,
                  a1.z + b1.z + c1.z, a1.w + b1.w + c1.w};
    union { unsigned short us[8]; uint4 u; } H, L;
#pragma unroll
    for (int i = 0; i < 8; i++) split2(v[i], H.us[i], L.us[i]);
    *(uint4*)(g_py_hi + (size_t)row * DM + t * 8) = H.u;
    *(uint4*)(g_py_lo + (size_t)row * DM + t * 8) = L.u;
}

// ---------------------------------------------------------------------------
// Split-K reduce for out: out = part0 + part1   (2M floats)
// ---------------------------------------------------------------------------
__global__ void reduce_out_kernel(float* __restrict__ out) {
    const size_t i = ((size_t)blockIdx.x * 256 + threadIdx.x) * 4;
    float4 a = *(const float4*)(g_part + i);
    float4 b = *(const float4*)(g_part + i + (size_t)BB * SEQ * DM);
    *(float4*)(out + i) = make_float4(a.x + b.x, a.y + b.y, a.z + b.z, a.w + b.w);
}

// ---------------------------------------------------------------------------
// Masked softmax in-place + fused bf16 hi/lo split
// ---------------------------------------------------------------------------
__global__ void softmax_mask_split(float* __restrict__ a,
                                   const int* __restrict__ x) {
    const int row = blockIdx.x;          // b*SEQ + s
    const int b = row / SEQ;
    float* p = a + (size_t)row * SRC;
    const int* xb = x + b * SRC;
    const int t = threadIdx.x;

    float v[4];
    float mx = -1e30f;
#pragma unroll
    for (int i = 0; i < 4; i++) {
        const int col = t + i * 256;
        float val = p[col];
        if (__ldg(&xb[col]) == 0) val -= 1e9f;
        v[i] = val;
        mx = fmaxf(mx, val);
    }
    __shared__ float red[256];
    red[t] = mx; __syncthreads();
#pragma unroll
    for (int s = 128; s > 0; s >>= 1) {
        if (t < s) red[t] = fmaxf(red[t], red[t + s]);
        __syncthreads();
    }
    mx = red[0]; __syncthreads();

    float sum = 0.f;
#pragma unroll
    for (int i = 0; i < 4; i++) { v[i] = __expf(v[i] - mx); sum += v[i]; }
    red[t] = sum; __syncthreads();
#pragma unroll
    for (int s = 128; s > 0; s >>= 1) {
        if (t < s) red[t] += red[t + s];
        __syncthreads();
    }
    const float inv = 1.0f / red[0];
    unsigned short* ah = (unsigned short*)g_a_hi + (size_t)row * SRC;
    unsigned short* al = (unsigned short*)g_a_lo + (size_t)row * SRC;
#pragma unroll
    for (int i = 0; i < 4; i++) {
        const int col = t + i * 256;
        const float val = v[i] * inv;
        p[col] = val;
        unsigned short h, l;
        split2(val, h, l);
        ah[col] = h; al[col] = l;
    }
}

// ---------------------------------------------------------------------------
extern "C" void kernel_launch(void* const* d_in, const int* in_sizes, int n_in,
                              void* d_out, int out_size) {
    const int*   x   = (const int*)  d_in[0];   // [32, 1024]
    const int*   yc  = (const int*)  d_in[1];   // [32, 640]
    const float* F   = (const float*)d_in[2];   // [32000, 512]
    const float* G   = (const float*)d_in[3];   // [32000, 512]
    const float* Pw  = (const float*)d_in[4];   // [2560, 512]
    const float* Pb  = (const float*)d_in[5];   // [512]

    float* out   = (float*)d_out;                       // [32,128,512]
    float* a_out = out + (size_t)BB * SEQ * DM;         // [32,128,1024]

    constexpr int SMEM_NT = STAGES * (ATILE_B + BTILE_NT);   // 81920
    constexpr int SMEM_TR = STAGES * (ATILE_B + BTILE_TR);   // 75776
    cudaFuncSetAttribute(mma_gemm_kernel<false>,
                         cudaFuncAttributeMaxDynamicSharedMemorySize, SMEM_NT);
    cudaFuncSetAttribute(mma_gemm_kernel<true>,
                         cudaFuncAttributeMaxDynamicSharedMemorySize, SMEM_TR);

    __nv_bfloat16 *xe_hi, *xe_lo, *yce_hi, *yce_lo,
                  *pwt_hi, *pwt_lo, *py_hi, *py_lo, *a_hi, *a_lo;
    float* part;
    cudaGetSymbolAddress((void**)&xe_hi,  g_xe_hi);
    cudaGetSymbolAddress((void**)&xe_lo,  g_xe_lo);
    cudaGetSymbolAddress((void**)&yce_hi, g_yce_hi);
    cudaGetSymbolAddress((void**)&yce_lo, g_yce_lo);
    cudaGetSymbolAddress((void**)&pwt_hi, g_pwt_hi);
    cudaGetSymbolAddress((void**)&pwt_lo, g_pwt_lo);
    cudaGetSymbolAddress((void**)&py_hi,  g_py_hi);
    cudaGetSymbolAddress((void**)&py_lo,  g_py_lo);
    cudaGetSymbolAddress((void**)&a_hi,   g_a_hi);
    cudaGetSymbolAddress((void**)&a_lo,   g_a_lo);
    cudaGetSymbolAddress((void**)&part,   g_part);

    const size_t PART_S = (size_t)BB * SEQ * DM;   // partial-buffer stride

    // 1) gather + split source embeddings
    gather_split_xe<<<BB * SRC, 64>>>(x, F);
    // 2) gather + split target-context embeddings
    gather_split_yce<<<dim3(BB * SEQ, CTX), 64>>>(yc, G);
    // 3) transpose + split P_w
    split_pwt_kernel<<<dim3(KPY / 64, DM / 64), 256>>>(Pw);
    // 4) py partials (split-K=2): M=4096, N=512, K=2560
    mma_gemm_kernel<false><<<dim3(DM / 128, (BB * SEQ) / 128, 2), 256, SMEM_NT>>>(
        yce_hi, yce_lo, 0, KPY,
        pwt_hi, pwt_lo, 0, KPY,
        part, 0, DM, 2, PART_S, KPY);
    // 5) reduce + bias + split -> py hi/lo
    reduce_bias_split_py<<<BB * SEQ, 64>>>(Pb);
    // 6) logits a[b,s,x] = py[b,s,:] . xe[b,x,:]   (M=128, N=1024, K=512, batched)
    mma_gemm_kernel<false><<<dim3(SRC / 128, 1, BB), 256, SMEM_NT>>>(
        py_hi, py_lo, (size_t)SEQ * DM, DM,
        xe_hi, xe_lo, (size_t)SRC * DM, DM,
        a_out, (size_t)SEQ * SRC, SRC, 1, 0, DM);
    // 7) masked softmax + split
    softmax_mask_split<<<BB * SEQ, 256>>>(a_out, x);
    // 8) out partials (split-K=2, trans-B): M=128, N=512, K=1024, batched
    mma_gemm_kernel<true><<<dim3(DM / 128, 1, BB * 2), 256, SMEM_TR>>>(
        a_hi, a_lo, (size_t)SEQ * SRC, SRC,
        xe_hi, xe_lo, (size_t)SRC * DM, DM,
        part, (size_t)SEQ * DM, DM, 2, PART_S, SRC);
    // 9) reduce partials -> out
    reduce_out_kernel<<<(BB * SEQ * DM) / 1024, 256>>>(out);
}

// round 8
// speedup vs baseline: 3.3280x; 1.0296x over previous
#include <cuda_runtime.h>
#include <cuda_bf16.h>
#include <cstdint>

// Problem constants
#define BB   32
#define SRC  1024
#define SEQ  128
#define CTX  5
#define DM   512
#define KPY  (CTX*DM)   // 2560

// ---------------------------------------------------------------------------
// Scratch (device globals; no allocations allowed)
// ---------------------------------------------------------------------------
__device__ __nv_bfloat16 g_xe_hi [(size_t)BB*SRC*DM];
__device__ __nv_bfloat16 g_xe_lo [(size_t)BB*SRC*DM];
__device__ __nv_bfloat16 g_yce_hi[(size_t)BB*SEQ*KPY];
__device__ __nv_bfloat16 g_yce_lo[(size_t)BB*SEQ*KPY];
__device__ __nv_bfloat16 g_pwt_hi[(size_t)DM*KPY];
__device__ __nv_bfloat16 g_pwt_lo[(size_t)DM*KPY];
__device__ __nv_bfloat16 g_py_hi [(size_t)BB*SEQ*DM];
__device__ __nv_bfloat16 g_py_lo [(size_t)BB*SEQ*DM];
__device__ __nv_bfloat16 g_a_hi  [(size_t)BB*SEQ*SRC];
__device__ __nv_bfloat16 g_a_lo  [(size_t)BB*SEQ*SRC];
__device__ float         g_part  [(size_t)2*BB*SEQ*DM];   // 16MB split-K partials

// ---------------------------------------------------------------------------
// Helpers
// ---------------------------------------------------------------------------
__device__ __forceinline__ uint32_t smem_to_u32(const void* p) {
    uint32_t a;
    asm("{ .reg .u64 t; cvta.to.shared.u64 t, %1; cvt.u32.u64 %0, t; }"
        : "=r"(a) : "l"(p));
    return a;
}

#define CP_ASYNC16(dst, src) \
    asm volatile("cp.async.cg.shared.global [%0], [%1], 16;" \
                 :: "r"(dst), "l"(src) : "memory")
#define CP_COMMIT() asm volatile("cp.async.commit_group;" ::: "memory")
#define CP_WAIT(N)  asm volatile("cp.async.wait_group %0;" :: "n"(N) : "memory")

__device__ __forceinline__ void ldsm_x4(uint32_t r[4], uint32_t addr) {
    asm volatile("ldmatrix.sync.aligned.m8n8.x4.shared.b16 {%0,%1,%2,%3}, [%4];"
                 : "=r"(r[0]), "=r"(r[1]), "=r"(r[2]), "=r"(r[3]) : "r"(addr));
}
__device__ __forceinline__ void ldsm_x4_trans(uint32_t r[4], uint32_t addr) {
    asm volatile("ldmatrix.sync.aligned.m8n8.x4.trans.shared.b16 {%0,%1,%2,%3}, [%4];"
                 : "=r"(r[0]), "=r"(r[1]), "=r"(r[2]), "=r"(r[3]) : "r"(addr));
}

__device__ __forceinline__ void mma16816(float c[4],
                                         uint32_t a0, uint32_t a1, uint32_t a2, uint32_t a3,
                                         uint32_t b0, uint32_t b1) {
    asm volatile("mma.sync.aligned.m16n8k16.row.col.f32.bf16.bf16.f32 "
                 "{%0,%1,%2,%3}, {%4,%5,%6,%7}, {%8,%9}, {%0,%1,%2,%3};"
                 : "+f"(c[0]), "+f"(c[1]), "+f"(c[2]), "+f"(c[3])
                 : "r"(a0), "r"(a1), "r"(a2), "r"(a3), "r"(b0), "r"(b1));
}

// fp32 -> (bf16 hi, bf16 lo) split
__device__ __forceinline__ void split2(float v, unsigned short& h, unsigned short& l) {
    __nv_bfloat16 hb = __float2bfloat16(v);
    __nv_bfloat16 lb = __float2bfloat16(v - __bfloat162float(hb));
    h = __bfloat16_as_ushort(hb);
    l = __bfloat16_as_ushort(lb);
}

// ---------------------------------------------------------------------------
// Prep: gather + split xe (row = b*SRC + i)
// ---------------------------------------------------------------------------
__global__ void gather_split_xe(const int* __restrict__ x, const float* __restrict__ F) {
    const int row = blockIdx.x;
    const int tok = __ldg(&x[row]);
    const int t = threadIdx.x;
    const float4* src = (const float4*)(F + (size_t)tok * DM);
    float4 a = __ldg(&src[t * 2]);
    float4 b = __ldg(&src[t * 2 + 1]);
    float v[8] = {a.x, a.y, a.z, a.w, b.x, b.y, b.z, b.w};
    union { unsigned short us[8]; uint4 u; } H, L;
#pragma unroll
    for (int i = 0; i < 8; i++) split2(v[i], H.us[i], L.us[i]);
    *(uint4*)(g_xe_hi + (size_t)row * DM + t * 8) = H.u;
    *(uint4*)(g_xe_lo + (size_t)row * DM + t * 8) = L.u;
}

// ---------------------------------------------------------------------------
// Prep: gather + split yce  (grid = (4096, 5), 64 threads)
// ---------------------------------------------------------------------------
__global__ void gather_split_yce(const int* __restrict__ yc, const float* __restrict__ G) {
    const int m = blockIdx.x;
    const int c = blockIdx.y;
    const int tok = __ldg(&yc[m * CTX + c]);
    const int t = threadIdx.x;
    const float4* src = (const float4*)(G + (size_t)tok * DM);
    float4 a = __ldg(&src[t * 2]);
    float4 b = __ldg(&src[t * 2 + 1]);
    float v[8] = {a.x, a.y, a.z, a.w, b.x, b.y, b.z, b.w};
    union { unsigned short us[8]; uint4 u; } H, L;
#pragma unroll
    for (int i = 0; i < 8; i++) split2(v[i], H.us[i], L.us[i]);
    const size_t off = (size_t)m * KPY + c * DM + t * 8;
    *(uint4*)(g_yce_hi + off) = H.u;
    *(uint4*)(g_yce_lo + off) = L.u;
}

// ---------------------------------------------------------------------------
// Prep: transpose + split P_w [2560,512] -> PwT hi/lo [512][2560]
// ---------------------------------------------------------------------------
__global__ void split_pwt_kernel(const float* __restrict__ Pw) {
    __shared__ float s[64][65];
    const int k0 = blockIdx.x * 64;
    const int n0 = blockIdx.y * 64;
    const int tx = threadIdx.x & 31, ty = threadIdx.x >> 5;
#pragma unroll
    for (int i = 0; i < 8; i++) {
        const int r = ty + i * 8;                           // local k
        float2 v = *(const float2*)(Pw + (size_t)(k0 + r) * DM + n0 + tx * 2);
        s[r][tx * 2] = v.x; s[r][tx * 2 + 1] = v.y;
    }
    __syncthreads();
#pragma unroll
    for (int i = 0; i < 8; i++) {
        const int nr = ty + i * 8;                          // local n
        float v0 = s[tx * 2][nr], v1 = s[tx * 2 + 1][nr];
        unsigned short h0, l0, h1, l1;
        split2(v0, h0, l0); split2(v1, h1, l1);
        const size_t off = (size_t)(n0 + nr) * KPY + k0 + tx * 2;
        *(unsigned*)((unsigned short*)g_pwt_hi + off) = (unsigned)h0 | ((unsigned)h1 << 16);
        *(unsigned*)((unsigned short*)g_pwt_lo + off) = (unsigned)l0 | ((unsigned)l1 << 16);
    }
}

// ---------------------------------------------------------------------------
// mma.sync GEMM, 3-term split with A-reuse pairing:
//   phase 1 chunks (c < NC1):  Ahi x (Bhi, Blo)   -- A loaded once, 2x HMMA
//   phase 2 chunks (c >= NC1): Alo x Bhi
// CTA tile 128x128, BK=32, 8 warps (2m x 4n), m16n8k16, 3-stage cp.async,
// one __syncthreads per chunk, fp32 output. Split-K=2 balanced at SP=3*NC1/4.
// ---------------------------------------------------------------------------
#define SROW 40                    // A / NT-B smem row stride (halves)
#define BROW 136                   // trans-B smem row stride (halves)
#define ATILE_B (128 * SROW * 2)   // 10240
#define BTILE_NT (128 * SROW * 2)  // 10240
#define BTILE_TR (32 * BROW * 2)   // 8704
#define STAGES 3

template<int K, bool TRANSB>
__global__ __launch_bounds__(256, 2)
void mma_gemm_kernel(const __nv_bfloat16* __restrict__ Ahi, const __nv_bfloat16* __restrict__ Alo,
                     size_t strideA, int lda,
                     const __nv_bfloat16* __restrict__ Bhi, const __nv_bfloat16* __restrict__ Blo,
                     size_t strideB, int ldb,
                     float* __restrict__ C, size_t strideC, int ldc,
                     int ksplit, size_t strideS) {
    constexpr int BTILE   = TRANSB ? BTILE_TR : BTILE_NT;
    constexpr int STAGE_B = ATILE_B + 2 * BTILE;
    constexpr int NC1 = K / 32;          // paired chunks
    constexpr int NCT = 2 * NC1;         // + phase-2 chunks
    constexpr int SP  = (3 * NC1) / 4;   // split-K balance point

    extern __shared__ __align__(16) unsigned char smbuf[];
    const uint32_t s_base = smem_to_u32(smbuf);
    const uint32_t sA  = s_base;
    const uint32_t sB0 = s_base + ATILE_B;

    const int tid  = threadIdx.x;
    const int lane = tid & 31;
    const int wid  = tid >> 5;
    const int wm   = wid & 1;
    const int wn   = wid >> 1;
    const int quad = lane >> 3;
    const int l8   = lane & 7;

    const int m0 = blockIdx.y * 128;
    const int n0 = blockIdx.x * 128;
    const int z  = blockIdx.z;
    const int s_k = (ksplit == 2) ? (z & 1) : 0;
    const size_t bz = (ksplit == 2) ? (z >> 1) : z;

    const __nv_bfloat16* Ah = Ahi + bz * strideA + (size_t)m0 * lda;
    const __nv_bfloat16* Al = Alo + bz * strideA + (size_t)m0 * lda;
    const __nv_bfloat16* Bh;
    const __nv_bfloat16* Bl;
    if (TRANSB) { Bh = Bhi + bz * strideB + n0; Bl = Blo + bz * strideB + n0; }
    else        { Bh = Bhi + bz * strideB + (size_t)n0 * ldb;
                  Bl = Blo + bz * strideB + (size_t)n0 * ldb; }

    // A / NT-B loader: 256 threads -> 128 rows x 4 chunks(16B), x2
    const int lrow   = tid >> 2;
    const int lchunk = tid & 3;
    // trans-B loader: 32 rows x 16 chunks(16B), x2
    const int tb_row = tid >> 4;
    const int tb_ch  = tid & 15;

    // ldmatrix base addresses (stage 0, B slot 0)
    const uint32_t a_addr0 = sA + ((uint32_t)(wm * 64 + (quad & 1) * 8 + l8) * SROW
                                   + (quad >> 1) * 8) * 2;
    const uint32_t b_addr_nt = sB0 + ((uint32_t)(wn * 32 + (quad >> 1) * 8 + l8) * SROW
                                      + (quad & 1) * 8) * 2;
    const uint32_t b_addr_tr = sB0 + ((uint32_t)((quad & 1) * 8 + l8) * BROW
                                      + wn * 32 + (quad >> 1) * 8) * 2;

    float acc[4][4][4];
#pragma unroll
    for (int i = 0; i < 4; i++)
#pragma unroll
        for (int j = 0; j < 4; j++)
#pragma unroll
            for (int r = 0; r < 4; r++) acc[i][j][r] = 0.f;

    const int c0 = (s_k == 0) ? 0 : SP;
    const int c1 = (ksplit == 2) ? ((s_k == 0) ? SP : NCT) : NCT;

    auto load_tiles = [&](int stage, int c) {
        const uint32_t bo = (uint32_t)stage * STAGE_B;
        const bool pair = (c < NC1);
        const int koff = (pair ? c : c - NC1) * 32;
        const __nv_bfloat16* Ap = (pair ? Ah : Al) + koff;
#pragma unroll
        for (int h = 0; h < 2; h++) {
            const int r = lrow + h * 64;
            CP_ASYNC16(sA + bo + ((uint32_t)r * SROW + lchunk * 8) * 2,
                       Ap + (size_t)r * lda + lchunk * 8);
        }
        if (TRANSB) {
            const __nv_bfloat16* B0p = Bh + (size_t)koff * ldb;
#pragma unroll
            for (int h = 0; h < 2; h++) {
                const int r = tb_row + h * 16;
                CP_ASYNC16(sB0 + bo + ((uint32_t)r * BROW + tb_ch * 8) * 2,
                           B0p + (size_t)r * ldb + tb_ch * 8);
            }
            if (pair) {
                const __nv_bfloat16* B1p = Bl + (size_t)koff * ldb;
#pragma unroll
                for (int h = 0; h < 2; h++) {
                    const int r = tb_row + h * 16;
                    CP_ASYNC16(sB0 + BTILE + bo + ((uint32_t)r * BROW + tb_ch * 8) * 2,
                               B1p + (size_t)r * ldb + tb_ch * 8);
                }
            }
        } else {
            const __nv_bfloat16* B0p = Bh + koff;
#pragma unroll
            for (int h = 0; h < 2; h++) {
                const int r = lrow + h * 64;
                CP_ASYNC16(sB0 + bo + ((uint32_t)r * SROW + lchunk * 8) * 2,
                           B0p + (size_t)r * ldb + lchunk * 8);
            }
            if (pair) {
                const __nv_bfloat16* B1p = Bl + koff;
#pragma unroll
                for (int h = 0; h < 2; h++) {
                    const int r = lrow + h * 64;
                    CP_ASYNC16(sB0 + BTILE + bo + ((uint32_t)r * SROW + lchunk * 8) * 2,
                               B1p + (size_t)r * ldb + lchunk * 8);
                }
            }
        }
    };

    // prologue: stages 0,1 <- chunks c0, c0+1
    load_tiles(0, c0); CP_COMMIT();
    if (c0 + 1 < c1) load_tiles(1, c0 + 1);
    CP_COMMIT();

    int st = 0;        // compute stage
    int ld = 2;        // next load stage
    for (int c = c0; c < c1; c++) {
        CP_WAIT(STAGES - 2);
        __syncthreads();

        const uint32_t bo = (uint32_t)st * STAGE_B;
        const bool pair = (c < NC1);
#pragma unroll
        for (int ks = 0; ks < 2; ks++) {
            uint32_t afr[4][4];
#pragma unroll
            for (int mt = 0; mt < 4; mt++)
                ldsm_x4(afr[mt], a_addr0 + bo + mt * (16 * SROW * 2) + ks * 32);
            uint32_t bfr[2][4];
            if (TRANSB) {
#pragma unroll
                for (int p = 0; p < 2; p++)
                    ldsm_x4_trans(bfr[p], b_addr_tr + bo + ks * (16 * BROW * 2) + p * 32);
            } else {
#pragma unroll
                for (int p = 0; p < 2; p++)
                    ldsm_x4(bfr[p], b_addr_nt + bo + p * (16 * SROW * 2) + ks * 32);
            }
#pragma unroll
            for (int mt = 0; mt < 4; mt++)
#pragma unroll
                for (int nt = 0; nt < 4; nt++)
                    mma16816(acc[mt][nt],
                             afr[mt][0], afr[mt][1], afr[mt][2], afr[mt][3],
                             bfr[nt >> 1][(nt & 1) * 2], bfr[nt >> 1][(nt & 1) * 2 + 1]);
            if (pair) {
                if (TRANSB) {
#pragma unroll
                    for (int p = 0; p < 2; p++)
                        ldsm_x4_trans(bfr[p], b_addr_tr + BTILE + bo + ks * (16 * BROW * 2) + p * 32);
                } else {
#pragma unroll
                    for (int p = 0; p < 2; p++)
                        ldsm_x4(bfr[p], b_addr_nt + BTILE + bo + p * (16 * SROW * 2) + ks * 32);
                }
#pragma unroll
                for (int mt = 0; mt < 4; mt++)
#pragma unroll
                    for (int nt = 0; nt < 4; nt++)
                        mma16816(acc[mt][nt],
                                 afr[mt][0], afr[mt][1], afr[mt][2], afr[mt][3],
                                 bfr[nt >> 1][(nt & 1) * 2], bfr[nt >> 1][(nt & 1) * 2 + 1]);
            }
        }

        const int nxt = c + 2;
        if (nxt < c1) load_tiles(ld, nxt);
        CP_COMMIT();
        st = (st == STAGES - 1) ? 0 : st + 1;
        ld = (ld == STAGES - 1) ? 0 : ld + 1;
    }

    // epilogue (fp32)
    float* Cb = C + (size_t)s_k * strideS + bz * strideC;
    const int mb = m0 + wm * 64;
    const int nb = n0 + wn * 32;
#pragma unroll
    for (int mt = 0; mt < 4; mt++) {
#pragma unroll
        for (int nt = 0; nt < 4; nt++) {
            const int r  = mb + mt * 16 + (lane >> 2);
            const int cc = nb + nt * 8 + (lane & 3) * 2;
            *(float2*)&Cb[(size_t)r * ldc + cc] =
                make_float2(acc[mt][nt][0], acc[mt][nt][1]);
            *(float2*)&Cb[(size_t)(r + 8) * ldc + cc] =
                make_float2(acc[mt][nt][2], acc[mt][nt][3]);
        }
    }
}

// ---------------------------------------------------------------------------
// Split-K reduce for py: py = part0 + part1 + bias -> bf16 hi/lo
// ---------------------------------------------------------------------------
__global__ void reduce_bias_split_py(const float* __restrict__ Pb) {
    const int row = blockIdx.x;
    const int t = threadIdx.x;
    const float* p0 = g_part + (size_t)row * DM;
    const float* p1 = p0 + (size_t)BB * SEQ * DM;
    float4 a0 = *(const float4*)(p0 + t * 8);
    float4 a1 = *(const float4*)(p0 + t * 8 + 4);
    float4 b0 = *(const float4*)(p1 + t * 8);
    float4 b1 = *(const float4*)(p1 + t * 8 + 4);
    float4 c0 = __ldg((const float4*)(Pb + t * 8));
    float4 c1 = __ldg((const float4*)(Pb + t * 8 + 4));
    float v[8] = {a0.x + b0.x + c0.x, a0.y + b0.y + c0.y,
                  a0.z + b0.z + c0.z, a0.w + b0.w + c0.w,
                  a1.x + b1.x + c1.x, a1.y + b1.y + c1.y,
                  a1.z + b1.z + c1.z, a1.w + b1.w + c1.w};
    union { unsigned short us[8]; uint4 u; } H, L;
#pragma unroll
    for (int i = 0; i < 8; i++) split2(v[i], H.us[i], L.us[i]);
    *(uint4*)(g_py_hi + (size_t)row * DM + t * 8) = H.u;
    *(uint4*)(g_py_lo + (size_t)row * DM + t * 8) = L.u;
}

// ---------------------------------------------------------------------------
// Split-K reduce for out: out = part0 + part1   (2M floats)
// ---------------------------------------------------------------------------
__global__ void reduce_out_kernel(float* __restrict__ out) {
    const size_t i = ((size_t)blockIdx.x * 256 + threadIdx.x) * 4;
    float4 a = *(const float4*)(g_part + i);
    float4 b = *(const float4*)(g_part + i + (size_t)BB * SEQ * DM);
    *(float4*)(out + i) = make_float4(a.x + b.x, a.y + b.y, a.z + b.z, a.w + b.w);
}

// ---------------------------------------------------------------------------
// Masked softmax in-place + fused bf16 hi/lo split
// ---------------------------------------------------------------------------
__global__ void softmax_mask_split(float* __restrict__ a,
                                   const int* __restrict__ x) {
    const int row = blockIdx.x;          // b*SEQ + s
    const int b = row / SEQ;
    float* p = a + (size_t)row * SRC;
    const int* xb = x + b * SRC;
    const int t = threadIdx.x;

    float v[4];
    float mx = -1e30f;
#pragma unroll
    for (int i = 0; i < 4; i++) {
        const int col = t + i * 256;
        float val = p[col];
        if (__ldg(&xb[col]) == 0) val -= 1e9f;
        v[i] = val;
        mx = fmaxf(mx, val);
    }
    __shared__ float red[256];
    red[t] = mx; __syncthreads();
#pragma unroll
    for (int s = 128; s > 0; s >>= 1) {
        if (t < s) red[t] = fmaxf(red[t], red[t + s]);
        __syncthreads();
    }
    mx = red[0]; __syncthreads();

    float sum = 0.f;
#pragma unroll
    for (int i = 0; i < 4; i++) { v[i] = __expf(v[i] - mx); sum += v[i]; }
    red[t] = sum; __syncthreads();
#pragma unroll
    for (int s = 128; s > 0; s >>= 1) {
        if (t < s) red[t] += red[t + s];
        __syncthreads();
    }
    const float inv = 1.0f / red[0];
    unsigned short* ah = (unsigned short*)g_a_hi + (size_t)row * SRC;
    unsigned short* al = (unsigned short*)g_a_lo + (size_t)row * SRC;
#pragma unroll
    for (int i = 0; i < 4; i++) {
        const int col = t + i * 256;
        const float val = v[i] * inv;
        p[col] = val;
        unsigned short h, l;
        split2(val, h, l);
        ah[col] = h; al[col] = l;
    }
}

// ---------------------------------------------------------------------------
extern "C" void kernel_launch(void* const* d_in, const int* in_sizes, int n_in,
                              void* d_out, int out_size) {
    const int*   x   = (const int*)  d_in[0];   // [32, 1024]
    const int*   yc  = (const int*)  d_in[1];   // [32, 640]
    const float* F   = (const float*)d_in[2];   // [32000, 512]
    const float* G   = (const float*)d_in[3];   // [32000, 512]
    const float* Pw  = (const float*)d_in[4];   // [2560, 512]
    const float* Pb  = (const float*)d_in[5];   // [512]

    float* out   = (float*)d_out;                       // [32,128,512]
    float* a_out = out + (size_t)BB * SEQ * DM;         // [32,128,1024]

    constexpr int SMEM_NT = STAGES * (ATILE_B + 2 * BTILE_NT);   // 92160
    constexpr int SMEM_TR = STAGES * (ATILE_B + 2 * BTILE_TR);   // 82944
    cudaFuncSetAttribute(mma_gemm_kernel<KPY, false>,
                         cudaFuncAttributeMaxDynamicSharedMemorySize, SMEM_NT);
    cudaFuncSetAttribute(mma_gemm_kernel<DM, false>,
                         cudaFuncAttributeMaxDynamicSharedMemorySize, SMEM_NT);
    cudaFuncSetAttribute(mma_gemm_kernel<SRC, true>,
                         cudaFuncAttributeMaxDynamicSharedMemorySize, SMEM_TR);

    __nv_bfloat16 *xe_hi, *xe_lo, *yce_hi, *yce_lo,
                  *pwt_hi, *pwt_lo, *py_hi, *py_lo, *a_hi, *a_lo;
    float* part;
    cudaGetSymbolAddress((void**)&xe_hi,  g_xe_hi);
    cudaGetSymbolAddress((void**)&xe_lo,  g_xe_lo);
    cudaGetSymbolAddress((void**)&yce_hi, g_yce_hi);
    cudaGetSymbolAddress((void**)&yce_lo, g_yce_lo);
    cudaGetSymbolAddress((void**)&pwt_hi, g_pwt_hi);
    cudaGetSymbolAddress((void**)&pwt_lo, g_pwt_lo);
    cudaGetSymbolAddress((void**)&py_hi,  g_py_hi);
    cudaGetSymbolAddress((void**)&py_lo,  g_py_lo);
    cudaGetSymbolAddress((void**)&a_hi,   g_a_hi);
    cudaGetSymbolAddress((void**)&a_lo,   g_a_lo);
    cudaGetSymbolAddress((void**)&part,   g_part);

    const size_t PART_S = (size_t)BB * SEQ * DM;   // partial-buffer stride

    // 1) gather + split source embeddings
    gather_split_xe<<<BB * SRC, 64>>>(x, F);
    // 2) gather + split target-context embeddings
    gather_split_yce<<<dim3(BB * SEQ, CTX), 64>>>(yc, G);
    // 3) transpose + split P_w
    split_pwt_kernel<<<dim3(KPY / 64, DM / 64), 256>>>(Pw);
    // 4) py partials (split-K=2): M=4096, N=512, K=2560
    mma_gemm_kernel<KPY, false><<<dim3(DM / 128, (BB * SEQ) / 128, 2), 256, SMEM_NT>>>(
        yce_hi, yce_lo, 0, KPY,
        pwt_hi, pwt_lo, 0, KPY,
        part, 0, DM, 2, PART_S);
    // 5) reduce + bias + split -> py hi/lo
    reduce_bias_split_py<<<BB * SEQ, 64>>>(Pb);
    // 6) logits a[b,s,x] = py[b,s,:] . xe[b,x,:]   (M=128, N=1024, K=512, batched)
    mma_gemm_kernel<DM, false><<<dim3(SRC / 128, 1, BB), 256, SMEM_NT>>>(
        py_hi, py_lo, (size_t)SEQ * DM, DM,
        xe_hi, xe_lo, (size_t)SRC * DM, DM,
        a_out, (size_t)SEQ * SRC, SRC, 1, 0);
    // 7) masked softmax + split
    softmax_mask_split<<<BB * SEQ, 256>>>(a_out, x);
    // 8) out partials (split-K=2, trans-B): M=128, N=512, K=1024, batched
    mma_gemm_kernel<SRC, true><<<dim3(DM / 128, 1, BB * 2), 256, SMEM_TR>>>(
        a_hi, a_lo, (size_t)SEQ * SRC, SRC,
        xe_hi, xe_lo, (size_t)SRC * DM, DM,
        part, (size_t)SEQ * DM, DM, 2, PART_S);
    // 9) reduce partials -> out
    reduce_out_kernel<<<(BB * SEQ * DM) / 1024, 256>>>(out);
}

// round 9
// speedup vs baseline: 3.5994x; 1.0816x over previous
#include <cuda_runtime.h>
#include <cuda_bf16.h>
#include <cstdint>

// Problem constants
#define BB   32
#define SRC  1024
#define SEQ  128
#define CTX  5
#define DM   512
#define KPY  (CTX*DM)   // 2560

// ---------------------------------------------------------------------------
// Scratch (device globals; no allocations allowed)
// ---------------------------------------------------------------------------
__device__ __nv_bfloat16 g_xe_hi [(size_t)BB*SRC*DM];
__device__ __nv_bfloat16 g_xe_lo [(size_t)BB*SRC*DM];
__device__ __nv_bfloat16 g_yce_hi[(size_t)BB*SEQ*KPY];
__device__ __nv_bfloat16 g_yce_lo[(size_t)BB*SEQ*KPY];
__device__ __nv_bfloat16 g_pwt_hi[(size_t)DM*KPY];
__device__ __nv_bfloat16 g_pwt_lo[(size_t)DM*KPY];
__device__ __nv_bfloat16 g_py_hi [(size_t)BB*SEQ*DM];
__device__ __nv_bfloat16 g_py_lo [(size_t)BB*SEQ*DM];
__device__ __nv_bfloat16 g_a_hi  [(size_t)BB*SEQ*SRC];
__device__ __nv_bfloat16 g_a_lo  [(size_t)BB*SEQ*SRC];
__device__ float         g_part  [(size_t)2*BB*SEQ*DM];   // 16MB split-K partials

// ---------------------------------------------------------------------------
// Helpers
// ---------------------------------------------------------------------------
__device__ __forceinline__ uint32_t smem_to_u32(const void* p) {
    uint32_t a;
    asm("{ .reg .u64 t; cvta.to.shared.u64 t, %1; cvt.u32.u64 %0, t; }"
        : "=r"(a) : "l"(p));
    return a;
}

#define CP_ASYNC16(dst, src) \
    asm volatile("cp.async.cg.shared.global [%0], [%1], 16;" \
                 :: "r"(dst), "l"(src) : "memory")
#define CP_COMMIT() asm volatile("cp.async.commit_group;" ::: "memory")
#define CP_WAIT(N)  asm volatile("cp.async.wait_group %0;" :: "n"(N) : "memory")

__device__ __forceinline__ void ldsm_x4(uint32_t r[4], uint32_t addr) {
    asm volatile("ldmatrix.sync.aligned.m8n8.x4.shared.b16 {%0,%1,%2,%3}, [%4];"
                 : "=r"(r[0]), "=r"(r[1]), "=r"(r[2]), "=r"(r[3]) : "r"(addr));
}
__device__ __forceinline__ void ldsm_x4_trans(uint32_t r[4], uint32_t addr) {
    asm volatile("ldmatrix.sync.aligned.m8n8.x4.trans.shared.b16 {%0,%1,%2,%3}, [%4];"
                 : "=r"(r[0]), "=r"(r[1]), "=r"(r[2]), "=r"(r[3]) : "r"(addr));
}

__device__ __forceinline__ void mma16816(float c[4],
                                         uint32_t a0, uint32_t a1, uint32_t a2, uint32_t a3,
                                         uint32_t b0, uint32_t b1) {
    asm volatile("mma.sync.aligned.m16n8k16.row.col.f32.bf16.bf16.f32 "
                 "{%0,%1,%2,%3}, {%4,%5,%6,%7}, {%8,%9}, {%0,%1,%2,%3};"
                 : "+f"(c[0]), "+f"(c[1]), "+f"(c[2]), "+f"(c[3])
                 : "r"(a0), "r"(a1), "r"(a2), "r"(a3), "r"(b0), "r"(b1));
}

// fp32 -> (bf16 hi, bf16 lo) split
__device__ __forceinline__ void split2(float v, unsigned short& h, unsigned short& l) {
    __nv_bfloat16 hb = __float2bfloat16(v);
    __nv_bfloat16 lb = __float2bfloat16(v - __bfloat162float(hb));
    h = __bfloat16_as_ushort(hb);
    l = __bfloat16_as_ushort(lb);
}

// ---------------------------------------------------------------------------
// Prep: gather + split yce  (grid = (4096, 5), 64 threads)
// ---------------------------------------------------------------------------
__global__ void gather_split_yce(const int* __restrict__ yc, const float* __restrict__ G) {
    const int m = blockIdx.x;
    const int c = blockIdx.y;
    const int tok = __ldg(&yc[m * CTX + c]);
    const int t = threadIdx.x;
    const float4* src = (const float4*)(G + (size_t)tok * DM);
    float4 a = __ldg(&src[t * 2]);
    float4 b = __ldg(&src[t * 2 + 1]);
    float v[8] = {a.x, a.y, a.z, a.w, b.x, b.y, b.z, b.w};
    union { unsigned short us[8]; uint4 u; } H, L;
#pragma unroll
    for (int i = 0; i < 8; i++) split2(v[i], H.us[i], L.us[i]);
    const size_t off = (size_t)m * KPY + c * DM + t * 8;
    *(uint4*)(g_yce_hi + off) = H.u;
    *(uint4*)(g_yce_lo + off) = L.u;
}

// ---------------------------------------------------------------------------
// Prep: transpose + split P_w [2560,512] -> PwT hi/lo [512][2560]
// ---------------------------------------------------------------------------
__global__ void split_pwt_kernel(const float* __restrict__ Pw) {
    __shared__ float s[64][65];
    const int k0 = blockIdx.x * 64;
    const int n0 = blockIdx.y * 64;
    const int tx = threadIdx.x & 31, ty = threadIdx.x >> 5;
#pragma unroll
    for (int i = 0; i < 8; i++) {
        const int r = ty + i * 8;                           // local k
        float2 v = *(const float2*)(Pw + (size_t)(k0 + r) * DM + n0 + tx * 2);
        s[r][tx * 2] = v.x; s[r][tx * 2 + 1] = v.y;
    }
    __syncthreads();
#pragma unroll
    for (int i = 0; i < 8; i++) {
        const int nr = ty + i * 8;                          // local n
        float v0 = s[tx * 2][nr], v1 = s[tx * 2 + 1][nr];
        unsigned short h0, l0, h1, l1;
        split2(v0, h0, l0); split2(v1, h1, l1);
        const size_t off = (size_t)(n0 + nr) * KPY + k0 + tx * 2;
        *(unsigned*)((unsigned short*)g_pwt_hi + off) = (unsigned)h0 | ((unsigned)h1 << 16);
        *(unsigned*)((unsigned short*)g_pwt_lo + off) = (unsigned)l0 | ((unsigned)l1 << 16);
    }
}

// ---------------------------------------------------------------------------
// mma.sync GEMM, 3-term split with A-reuse pairing:
//   phase 1 chunks (c < NC1):  Ahi x (Bhi, Blo)   -- A loaded once, 2x HMMA
//   phase 2 chunks (c >= NC1): Alo x Bhi
// CTA tile 128x128, BK=32, 8 warps (2m x 4n), m16n8k16, 3-stage cp.async,
// one __syncthreads per chunk, fp32 output. Split-K=2 balanced at SP=3*NC1/4.
// Extra z-planes (z >= zmain) run an independent xe gather+split (overlap).
// ---------------------------------------------------------------------------
#define SROW 40                    // A / NT-B smem row stride (halves)
#define BROW 136                   // trans-B smem row stride (halves)
#define ATILE_B (128 * SROW * 2)   // 10240
#define BTILE_NT (128 * SROW * 2)  // 10240
#define BTILE_TR (32 * BROW * 2)   // 8704
#define STAGES 3

template<int K, bool TRANSB>
__global__ __launch_bounds__(256, 2)
void mma_gemm_kernel(const __nv_bfloat16* __restrict__ Ahi, const __nv_bfloat16* __restrict__ Alo,
                     size_t strideA, int lda,
                     const __nv_bfloat16* __restrict__ Bhi, const __nv_bfloat16* __restrict__ Blo,
                     size_t strideB, int ldb,
                     float* __restrict__ C, size_t strideC, int ldc,
                     int ksplit, size_t strideS,
                     int zmain, const int* __restrict__ gx, const float* __restrict__ gF) {
    const int tid = threadIdx.x;
    const int z   = blockIdx.z;

    // ---- piggyback plane: gather + split xe (independent of GEMM inputs) ----
    if (z >= zmain) {
        const int gid  = blockIdx.y * gridDim.x + blockIdx.x;   // 0..127
        const int rsub = tid >> 6;                              // 0..3
        const int col8 = (tid & 63) * 8;                        // 0..504
        const int rbase = gid * 256;
#pragma unroll 4
        for (int rr = 0; rr < 64; rr++) {
            const int row = rbase + rr * 4 + rsub;
            const int tok = __ldg(&gx[row]);
            const float* src = gF + (size_t)tok * DM + col8;
            float4 a = __ldg((const float4*)src);
            float4 b = __ldg((const float4*)(src + 4));
            float v[8] = {a.x, a.y, a.z, a.w, b.x, b.y, b.z, b.w};
            union { unsigned short us[8]; uint4 u; } H, L;
#pragma unroll
            for (int i = 0; i < 8; i++) split2(v[i], H.us[i], L.us[i]);
            *(uint4*)(g_xe_hi + (size_t)row * DM + col8) = H.u;
            *(uint4*)(g_xe_lo + (size_t)row * DM + col8) = L.u;
        }
        return;
    }

    constexpr int BTILE   = TRANSB ? BTILE_TR : BTILE_NT;
    constexpr int STAGE_B = ATILE_B + 2 * BTILE;
    constexpr int NC1 = K / 32;          // paired chunks
    constexpr int NCT = 2 * NC1;         // + phase-2 chunks
    constexpr int SP  = (3 * NC1) / 4;   // split-K balance point

    extern __shared__ __align__(16) unsigned char smbuf[];
    const uint32_t s_base = smem_to_u32(smbuf);
    const uint32_t sA  = s_base;
    const uint32_t sB0 = s_base + ATILE_B;

    const int lane = tid & 31;
    const int wid  = tid >> 5;
    const int wm   = wid & 1;
    const int wn   = wid >> 1;
    const int quad = lane >> 3;
    const int l8   = lane & 7;

    const int m0 = blockIdx.y * 128;
    const int n0 = blockIdx.x * 128;
    const int s_k = (ksplit == 2) ? (z & 1) : 0;
    const size_t bz = (ksplit == 2) ? (z >> 1) : z;

    const __nv_bfloat16* Ah = Ahi + bz * strideA + (size_t)m0 * lda;
    const __nv_bfloat16* Al = Alo + bz * strideA + (size_t)m0 * lda;
    const __nv_bfloat16* Bh;
    const __nv_bfloat16* Bl;
    if (TRANSB) { Bh = Bhi + bz * strideB + n0; Bl = Blo + bz * strideB + n0; }
    else        { Bh = Bhi + bz * strideB + (size_t)n0 * ldb;
                  Bl = Blo + bz * strideB + (size_t)n0 * ldb; }

    // A / NT-B loader: 256 threads -> 128 rows x 4 chunks(16B), x2
    const int lrow   = tid >> 2;
    const int lchunk = tid & 3;
    // trans-B loader: 32 rows x 16 chunks(16B), x2
    const int tb_row = tid >> 4;
    const int tb_ch  = tid & 15;

    // ldmatrix base addresses (stage 0, B slot 0)
    const uint32_t a_addr0 = sA + ((uint32_t)(wm * 64 + (quad & 1) * 8 + l8) * SROW
                                   + (quad >> 1) * 8) * 2;
    const uint32_t b_addr_nt = sB0 + ((uint32_t)(wn * 32 + (quad >> 1) * 8 + l8) * SROW
                                      + (quad & 1) * 8) * 2;
    const uint32_t b_addr_tr = sB0 + ((uint32_t)((quad & 1) * 8 + l8) * BROW
                                      + wn * 32 + (quad >> 1) * 8) * 2;

    float acc[4][4][4];
#pragma unroll
    for (int i = 0; i < 4; i++)
#pragma unroll
        for (int j = 0; j < 4; j++)
#pragma unroll
            for (int r = 0; r < 4; r++) acc[i][j][r] = 0.f;

    const int c0 = (s_k == 0) ? 0 : SP;
    const int c1 = (ksplit == 2) ? ((s_k == 0) ? SP : NCT) : NCT;

    auto load_tiles = [&](int stage, int c) {
        const uint32_t bo = (uint32_t)stage * STAGE_B;
        const bool pair = (c < NC1);
        const int koff = (pair ? c : c - NC1) * 32;
        const __nv_bfloat16* Ap = (pair ? Ah : Al) + koff;
#pragma unroll
        for (int h = 0; h < 2; h++) {
            const int r = lrow + h * 64;
            CP_ASYNC16(sA + bo + ((uint32_t)r * SROW + lchunk * 8) * 2,
                       Ap + (size_t)r * lda + lchunk * 8);
        }
        if (TRANSB) {
            const __nv_bfloat16* B0p = Bh + (size_t)koff * ldb;
#pragma unroll
            for (int h = 0; h < 2; h++) {
                const int r = tb_row + h * 16;
                CP_ASYNC16(sB0 + bo + ((uint32_t)r * BROW + tb_ch * 8) * 2,
                           B0p + (size_t)r * ldb + tb_ch * 8);
            }
            if (pair) {
                const __nv_bfloat16* B1p = Bl + (size_t)koff * ldb;
#pragma unroll
                for (int h = 0; h < 2; h++) {
                    const int r = tb_row + h * 16;
                    CP_ASYNC16(sB0 + BTILE + bo + ((uint32_t)r * BROW + tb_ch * 8) * 2,
                               B1p + (size_t)r * ldb + tb_ch * 8);
                }
            }
        } else {
            const __nv_bfloat16* B0p = Bh + koff;
#pragma unroll
            for (int h = 0; h < 2; h++) {
                const int r = lrow + h * 64;
                CP_ASYNC16(sB0 + bo + ((uint32_t)r * SROW + lchunk * 8) * 2,
                           B0p + (size_t)r * ldb + lchunk * 8);
            }
            if (pair) {
                const __nv_bfloat16* B1p = Bl + koff;
#pragma unroll
                for (int h = 0; h < 2; h++) {
                    const int r = lrow + h * 64;
                    CP_ASYNC16(sB0 + BTILE + bo + ((uint32_t)r * SROW + lchunk * 8) * 2,
                               B1p + (size_t)r * ldb + lchunk * 8);
                }
            }
        }
    };

    // prologue: stages 0,1 <- chunks c0, c0+1
    load_tiles(0, c0); CP_COMMIT();
    if (c0 + 1 < c1) load_tiles(1, c0 + 1);
    CP_COMMIT();

    int st = 0;        // compute stage
    int ld = 2;        // next load stage
    for (int c = c0; c < c1; c++) {
        CP_WAIT(STAGES - 2);
        __syncthreads();

        const uint32_t bo = (uint32_t)st * STAGE_B;
        const bool pair = (c < NC1);
#pragma unroll
        for (int ks = 0; ks < 2; ks++) {
            uint32_t afr[4][4];
#pragma unroll
            for (int mt = 0; mt < 4; mt++)
                ldsm_x4(afr[mt], a_addr0 + bo + mt * (16 * SROW * 2) + ks * 32);
            uint32_t bfr[2][4];
            if (TRANSB) {
#pragma unroll
                for (int p = 0; p < 2; p++)
                    ldsm_x4_trans(bfr[p], b_addr_tr + bo + ks * (16 * BROW * 2) + p * 32);
            } else {
#pragma unroll
                for (int p = 0; p < 2; p++)
                    ldsm_x4(bfr[p], b_addr_nt + bo + p * (16 * SROW * 2) + ks * 32);
            }
#pragma unroll
            for (int mt = 0; mt < 4; mt++)
#pragma unroll
                for (int nt = 0; nt < 4; nt++)
                    mma16816(acc[mt][nt],
                             afr[mt][0], afr[mt][1], afr[mt][2], afr[mt][3],
                             bfr[nt >> 1][(nt & 1) * 2], bfr[nt >> 1][(nt & 1) * 2 + 1]);
            if (pair) {
                if (TRANSB) {
#pragma unroll
                    for (int p = 0; p < 2; p++)
                        ldsm_x4_trans(bfr[p], b_addr_tr + BTILE + bo + ks * (16 * BROW * 2) + p * 32);
                } else {
#pragma unroll
                    for (int p = 0; p < 2; p++)
                        ldsm_x4(bfr[p], b_addr_nt + BTILE + bo + p * (16 * SROW * 2) + ks * 32);
                }
#pragma unroll
                for (int mt = 0; mt < 4; mt++)
#pragma unroll
                    for (int nt = 0; nt < 4; nt++)
                        mma16816(acc[mt][nt],
                                 afr[mt][0], afr[mt][1], afr[mt][2], afr[mt][3],
                                 bfr[nt >> 1][(nt & 1) * 2], bfr[nt >> 1][(nt & 1) * 2 + 1]);
            }
        }

        const int nxt = c + 2;
        if (nxt < c1) load_tiles(ld, nxt);
        CP_COMMIT();
        st = (st == STAGES - 1) ? 0 : st + 1;
        ld = (ld == STAGES - 1) ? 0 : ld + 1;
    }

    // epilogue (fp32)
    float* Cb = C + (size_t)s_k * strideS + bz * strideC;
    const int mb = m0 + wm * 64;
    const int nb = n0 + wn * 32;
#pragma unroll
    for (int mt = 0; mt < 4; mt++) {
#pragma unroll
        for (int nt = 0; nt < 4; nt++) {
            const int r  = mb + mt * 16 + (lane >> 2);
            const int cc = nb + nt * 8 + (lane & 3) * 2;
            *(float2*)&Cb[(size_t)r * ldc + cc] =
                make_float2(acc[mt][nt][0], acc[mt][nt][1]);
            *(float2*)&Cb[(size_t)(r + 8) * ldc + cc] =
                make_float2(acc[mt][nt][2], acc[mt][nt][3]);
        }
    }
}

// ---------------------------------------------------------------------------
// Split-K reduce for py: py = part0 + part1 + bias -> bf16 hi/lo
// ---------------------------------------------------------------------------
__global__ void reduce_bias_split_py(const float* __restrict__ Pb) {
    const int row = blockIdx.x;
    const int t = threadIdx.x;
    const float* p0 = g_part + (size_t)row * DM;
    const float* p1 = p0 + (size_t)BB * SEQ * DM;
    float4 a0 = *(const float4*)(p0 + t * 8);
    float4 a1 = *(const float4*)(p0 + t * 8 + 4);
    float4 b0 = *(const float4*)(p1 + t * 8);
    float4 b1 = *(const float4*)(p1 + t * 8 + 4);
    float4 c0 = __ldg((const float4*)(Pb + t * 8));
    float4 c1 = __ldg((const float4*)(Pb + t * 8 + 4));
    float v[8] = {a0.x + b0.x + c0.x, a0.y + b0.y + c0.y,
                  a0.z + b0.z + c0.z, a0.w + b0.w + c0.w,
                  a1.x + b1.x + c1.x, a1.y + b1.y + c1.y,
                  a1.z + b1.z + c1.z, a1.w + b1.w + c1.w};
    union { unsigned short us[8]; uint4 u; } H, L;
#pragma unroll
    for (int i = 0; i < 8; i++) split2(v[i], H.us[i], L.us[i]);
    *(uint4*)(g_py_hi + (size_t)row * DM + t * 8) = H.u;
    *(uint4*)(g_py_lo + (size_t)row * DM + t * 8) = L.u;
}

// ---------------------------------------------------------------------------
// Split-K reduce for out: out = part0 + part1   (2M floats)
// ---------------------------------------------------------------------------
__global__ void reduce_out_kernel(float* __restrict__ out) {
    const size_t i = ((size_t)blockIdx.x * 256 + threadIdx.x) * 4;
    float4 a = *(const float4*)(g_part + i);
    float4 b = *(const float4*)(g_part + i + (size_t)BB * SEQ * DM);
    *(float4*)(out + i) = make_float4(a.x + b.x, a.y + b.y, a.z + b.z, a.w + b.w);
}

// ---------------------------------------------------------------------------
// Masked softmax in-place + fused bf16 hi/lo split
// ---------------------------------------------------------------------------
__global__ void softmax_mask_split(float* __restrict__ a,
                                   const int* __restrict__ x) {
    const int row = blockIdx.x;          // b*SEQ + s
    const int b = row / SEQ;
    float* p = a + (size_t)row * SRC;
    const int* xb = x + b * SRC;
    const int t = threadIdx.x;

    float v[4];
    float mx = -1e30f;
#pragma unroll
    for (int i = 0; i < 4; i++) {
        const int col = t + i * 256;
        float val = p[col];
        if (__ldg(&xb[col]) == 0) val -= 1e9f;
        v[i] = val;
        mx = fmaxf(mx, val);
    }
    __shared__ float red[256];
    red[t] = mx; __syncthreads();
#pragma unroll
    for (int s = 128; s > 0; s >>= 1) {
        if (t < s) red[t] = fmaxf(red[t], red[t + s]);
        __syncthreads();
    }
    mx = red[0]; __syncthreads();

    float sum = 0.f;
#pragma unroll
    for (int i = 0; i < 4; i++) { v[i] = __expf(v[i] - mx); sum += v[i]; }
    red[t] = sum; __syncthreads();
#pragma unroll
    for (int s = 128; s > 0; s >>= 1) {
        if (t < s) red[t] += red[t + s];
        __syncthreads();
    }
    const float inv = 1.0f / red[0];
    unsigned short* ah = (unsigned short*)g_a_hi + (size_t)row * SRC;
    unsigned short* al = (unsigned short*)g_a_lo + (size_t)row * SRC;
#pragma unroll
    for (int i = 0; i < 4; i++) {
        const int col = t + i * 256;
        const float val = v[i] * inv;
        p[col] = val;
        unsigned short h, l;
        split2(val, h, l);
        ah[col] = h; al[col] = l;
    }
}

// ---------------------------------------------------------------------------
extern "C" void kernel_launch(void* const* d_in, const int* in_sizes, int n_in,
                              void* d_out, int out_size) {
    const int*   x   = (const int*)  d_in[0];   // [32, 1024]
    const int*   yc  = (const int*)  d_in[1];   // [32, 640]
    const float* F   = (const float*)d_in[2];   // [32000, 512]
    const float* G   = (const float*)d_in[3];   // [32000, 512]
    const float* Pw  = (const float*)d_in[4];   // [2560, 512]
    const float* Pb  = (const float*)d_in[5];   // [512]

    float* out   = (float*)d_out;                       // [32,128,512]
    float* a_out = out + (size_t)BB * SEQ * DM;         // [32,128,1024]

    constexpr int SMEM_NT = STAGES * (ATILE_B + 2 * BTILE_NT);   // 92160
    constexpr int SMEM_TR = STAGES * (ATILE_B + 2 * BTILE_TR);   // 82944
    cudaFuncSetAttribute(mma_gemm_kernel<KPY, false>,
                         cudaFuncAttributeMaxDynamicSharedMemorySize, SMEM_NT);
    cudaFuncSetAttribute(mma_gemm_kernel<DM, false>,
                         cudaFuncAttributeMaxDynamicSharedMemorySize, SMEM_NT);
    cudaFuncSetAttribute(mma_gemm_kernel<SRC, true>,
                         cudaFuncAttributeMaxDynamicSharedMemorySize, SMEM_TR);

    __nv_bfloat16 *xe_hi, *xe_lo, *yce_hi, *yce_lo,
                  *pwt_hi, *pwt_lo, *py_hi, *py_lo, *a_hi, *a_lo;
    float* part;
    cudaGetSymbolAddress((void**)&xe_hi,  g_xe_hi);
    cudaGetSymbolAddress((void**)&xe_lo,  g_xe_lo);
    cudaGetSymbolAddress((void**)&yce_hi, g_yce_hi);
    cudaGetSymbolAddress((void**)&yce_lo, g_yce_lo);
    cudaGetSymbolAddress((void**)&pwt_hi, g_pwt_hi);
    cudaGetSymbolAddress((void**)&pwt_lo, g_pwt_lo);
    cudaGetSymbolAddress((void**)&py_hi,  g_py_hi);
    cudaGetSymbolAddress((void**)&py_lo,  g_py_lo);
    cudaGetSymbolAddress((void**)&a_hi,   g_a_hi);
    cudaGetSymbolAddress((void**)&a_lo,   g_a_lo);
    cudaGetSymbolAddress((void**)&part,   g_part);

    const size_t PART_S = (size_t)BB * SEQ * DM;   // partial-buffer stride

    // 1) gather + split target-context embeddings
    gather_split_yce<<<dim3(BB * SEQ, CTX), 64>>>(yc, G);
    // 2) transpose + split P_w
    split_pwt_kernel<<<dim3(KPY / 64, DM / 64), 256>>>(Pw);
    // 3) py partials (split-K=2) WITH piggybacked xe gather on z==2:
    //    M=4096, N=512, K=2560; z<2 GEMM, z==2 -> 128 gather blocks
    mma_gemm_kernel<KPY, false><<<dim3(DM / 128, (BB * SEQ) / 128, 3), 256, SMEM_NT>>>(
        yce_hi, yce_lo, 0, KPY,
        pwt_hi, pwt_lo, 0, KPY,
        part, 0, DM, 2, PART_S, 2, x, F);
    // 4) reduce + bias + split -> py hi/lo
    reduce_bias_split_py<<<BB * SEQ, 64>>>(Pb);
    // 5) logits a[b,s,x] = py[b,s,:] . xe[b,x,:]   (M=128, N=1024, K=512, batched)
    mma_gemm_kernel<DM, false><<<dim3(SRC / 128, 1, BB), 256, SMEM_NT>>>(
        py_hi, py_lo, (size_t)SEQ * DM, DM,
        xe_hi, xe_lo, (size_t)SRC * DM, DM,
        a_out, (size_t)SEQ * SRC, SRC, 1, 0, BB, nullptr, nullptr);
    // 6) masked softmax + split
    softmax_mask_split<<<BB * SEQ, 256>>>(a_out, x);
    // 7) out partials (split-K=2, trans-B): M=128, N=512, K=1024, batched
    mma_gemm_kernel<SRC, true><<<dim3(DM / 128, 1, BB * 2), 256, SMEM_TR>>>(
        a_hi, a_lo, (size_t)SEQ * SRC, SRC,
        xe_hi, xe_lo, (size_t)SRC * DM, DM,
        part, (size_t)SEQ * DM, DM, 2, PART_S, BB * 2, nullptr, nullptr);
    // 8) reduce partials -> out
    reduce_out_kernel<<<(BB * SEQ * DM) / 1024, 256>>>(out);
}

// round 10
// speedup vs baseline: 3.6649x; 1.0182x over previous
#include <cuda_runtime.h>
#include <cuda_bf16.h>
#include <cstdint>

// Problem constants
#define BB   32
#define SRC  1024
#define SEQ  128
#define CTX  5
#define DM   512
#define KPY  (CTX*DM)   // 2560

// ---------------------------------------------------------------------------
// Scratch (device globals; no allocations allowed)
// ---------------------------------------------------------------------------
__device__ __nv_bfloat16 g_xe_hi [(size_t)BB*SRC*DM];
__device__ __nv_bfloat16 g_xe_lo [(size_t)BB*SRC*DM];
__device__ __nv_bfloat16 g_yce_hi[(size_t)BB*SEQ*KPY];
__device__ __nv_bfloat16 g_yce_lo[(size_t)BB*SEQ*KPY];
__device__ __nv_bfloat16 g_pwt_hi[(size_t)DM*KPY];
__device__ __nv_bfloat16 g_pwt_lo[(size_t)DM*KPY];
__device__ __nv_bfloat16 g_py_hi [(size_t)BB*SEQ*DM];
__device__ __nv_bfloat16 g_py_lo [(size_t)BB*SEQ*DM];
__device__ __nv_bfloat16 g_a_hi  [(size_t)BB*SEQ*SRC];
__device__ __nv_bfloat16 g_a_lo  [(size_t)BB*SEQ*SRC];
__device__ float         g_part  [(size_t)2*BB*SEQ*DM];   // 16MB split-K partials

// ---------------------------------------------------------------------------
// Helpers
// ---------------------------------------------------------------------------
__device__ __forceinline__ uint32_t smem_to_u32(const void* p) {
    uint32_t a;
    asm("{ .reg .u64 t; cvta.to.shared.u64 t, %1; cvt.u32.u64 %0, t; }"
        : "=r"(a) : "l"(p));
    return a;
}

#define CP_ASYNC16(dst, src) \
    asm volatile("cp.async.cg.shared.global [%0], [%1], 16;" \
                 :: "r"(dst), "l"(src) : "memory")
#define CP_COMMIT() asm volatile("cp.async.commit_group;" ::: "memory")
#define CP_WAIT(N)  asm volatile("cp.async.wait_group %0;" :: "n"(N) : "memory")

__device__ __forceinline__ void ldsm_x4(uint32_t r[4], uint32_t addr) {
    asm volatile("ldmatrix.sync.aligned.m8n8.x4.shared.b16 {%0,%1,%2,%3}, [%4];"
                 : "=r"(r[0]), "=r"(r[1]), "=r"(r[2]), "=r"(r[3]) : "r"(addr));
}
__device__ __forceinline__ void ldsm_x4_trans(uint32_t r[4], uint32_t addr) {
    asm volatile("ldmatrix.sync.aligned.m8n8.x4.trans.shared.b16 {%0,%1,%2,%3}, [%4];"
                 : "=r"(r[0]), "=r"(r[1]), "=r"(r[2]), "=r"(r[3]) : "r"(addr));
}

__device__ __forceinline__ void mma16816(float c[4],
                                         uint32_t a0, uint32_t a1, uint32_t a2, uint32_t a3,
                                         uint32_t b0, uint32_t b1) {
    asm volatile("mma.sync.aligned.m16n8k16.row.col.f32.bf16.bf16.f32 "
                 "{%0,%1,%2,%3}, {%4,%5,%6,%7}, {%8,%9}, {%0,%1,%2,%3};"
                 : "+f"(c[0]), "+f"(c[1]), "+f"(c[2]), "+f"(c[3])
                 : "r"(a0), "r"(a1), "r"(a2), "r"(a3), "r"(b0), "r"(b1));
}

// fp32 -> (bf16 hi, bf16 lo) split
__device__ __forceinline__ void split2(float v, unsigned short& h, unsigned short& l) {
    __nv_bfloat16 hb = __float2bfloat16(v);
    __nv_bfloat16 lb = __float2bfloat16(v - __bfloat162float(hb));
    h = __bfloat16_as_ushort(hb);
    l = __bfloat16_as_ushort(lb);
}

// ---------------------------------------------------------------------------
// Fused prep: blocks [0, 5120) gather+split yce; blocks [5120, 5440) pwt.
// 256 threads each.
// ---------------------------------------------------------------------------
#define YCE_BLOCKS (BB * SEQ * CTX / 4)   // 5120 (4 m-rows per block)
#define PWT_BLOCKS ((KPY / 64) * (DM / 64))  // 320

__global__ __launch_bounds__(256)
void prep_fused(const int* __restrict__ yc, const float* __restrict__ G,
                const float* __restrict__ Pw) {
    __shared__ float s[64][65];
    const int bid = blockIdx.x;
    const int t = threadIdx.x;

    if (bid < YCE_BLOCKS) {
        const int c = bid % CTX;
        const int m = (bid / CTX) * 4 + (t >> 6);
        const int col8 = (t & 63) * 8;
        const int tok = __ldg(&yc[m * CTX + c]);
        const float* src = G + (size_t)tok * DM + col8;
        float4 a = __ldg((const float4*)src);
        float4 b = __ldg((const float4*)(src + 4));
        float v[8] = {a.x, a.y, a.z, a.w, b.x, b.y, b.z, b.w};
        union { unsigned short us[8]; uint4 u; } H, L;
#pragma unroll
        for (int i = 0; i < 8; i++) split2(v[i], H.us[i], L.us[i]);
        const size_t off = (size_t)m * KPY + c * DM + col8;
        *(uint4*)(g_yce_hi + off) = H.u;
        *(uint4*)(g_yce_lo + off) = L.u;
    } else {
        const int j = bid - YCE_BLOCKS;
        const int k0 = (j % (KPY / 64)) * 64;
        const int n0 = (j / (KPY / 64)) * 64;
        const int tx = t & 31, ty = t >> 5;
#pragma unroll
        for (int i = 0; i < 8; i++) {
            const int r = ty + i * 8;                       // local k
            float2 v = *(const float2*)(Pw + (size_t)(k0 + r) * DM + n0 + tx * 2);
            s[r][tx * 2] = v.x; s[r][tx * 2 + 1] = v.y;
        }
        __syncthreads();
#pragma unroll
        for (int i = 0; i < 8; i++) {
            const int nr = ty + i * 8;                      // local n
            float v0 = s[tx * 2][nr], v1 = s[tx * 2 + 1][nr];
            unsigned short h0, l0, h1, l1;
            split2(v0, h0, l0); split2(v1, h1, l1);
            const size_t off = (size_t)(n0 + nr) * KPY + k0 + tx * 2;
            *(unsigned*)((unsigned short*)g_pwt_hi + off) = (unsigned)h0 | ((unsigned)h1 << 16);
            *(unsigned*)((unsigned short*)g_pwt_lo + off) = (unsigned)l0 | ((unsigned)l1 << 16);
        }
    }
}

// ---------------------------------------------------------------------------
// mma.sync GEMM, 3-term split with A-reuse pairing (unchanged from R9):
//   phase 1 chunks (c < NC1):  Ahi x (Bhi, Blo);  phase 2: Alo x Bhi
// CTA tile 128x128, BK=32, 8 warps, m16n8k16, 3-stage cp.async.
// Extra z-planes (z >= zmain) run an independent xe gather+split (overlap).
// ---------------------------------------------------------------------------
#define SROW 40                    // A / NT-B smem row stride (halves)
#define BROW 136                   // trans-B smem row stride (halves)
#define ATILE_B (128 * SROW * 2)   // 10240
#define BTILE_NT (128 * SROW * 2)  // 10240
#define BTILE_TR (32 * BROW * 2)   // 8704
#define STAGES 3

template<int K, bool TRANSB>
__global__ __launch_bounds__(256, 2)
void mma_gemm_kernel(const __nv_bfloat16* __restrict__ Ahi, const __nv_bfloat16* __restrict__ Alo,
                     size_t strideA, int lda,
                     const __nv_bfloat16* __restrict__ Bhi, const __nv_bfloat16* __restrict__ Blo,
                     size_t strideB, int ldb,
                     float* __restrict__ C, size_t strideC, int ldc,
                     int ksplit, size_t strideS,
                     int zmain, const int* __restrict__ gx, const float* __restrict__ gF) {
    const int tid = threadIdx.x;
    const int z   = blockIdx.z;

    // ---- piggyback plane: gather + split xe (independent of GEMM inputs) ----
    if (z >= zmain) {
        const int gid  = blockIdx.y * gridDim.x + blockIdx.x;   // 0..127
        const int rsub = tid >> 6;                              // 0..3
        const int col8 = (tid & 63) * 8;                        // 0..504
        const int rbase = gid * 256;
#pragma unroll 4
        for (int rr = 0; rr < 64; rr++) {
            const int row = rbase + rr * 4 + rsub;
            const int tok = __ldg(&gx[row]);
            const float* src = gF + (size_t)tok * DM + col8;
            float4 a = __ldg((const float4*)src);
            float4 b = __ldg((const float4*)(src + 4));
            float v[8] = {a.x, a.y, a.z, a.w, b.x, b.y, b.z, b.w};
            union { unsigned short us[8]; uint4 u; } H, L;
#pragma unroll
            for (int i = 0; i < 8; i++) split2(v[i], H.us[i], L.us[i]);
            *(uint4*)(g_xe_hi + (size_t)row * DM + col8) = H.u;
            *(uint4*)(g_xe_lo + (size_t)row * DM + col8) = L.u;
        }
        return;
    }

    constexpr int BTILE   = TRANSB ? BTILE_TR : BTILE_NT;
    constexpr int STAGE_B = ATILE_B + 2 * BTILE;
    constexpr int NC1 = K / 32;          // paired chunks
    constexpr int NCT = 2 * NC1;         // + phase-2 chunks
    constexpr int SP  = (3 * NC1) / 4;   // split-K balance point

    extern __shared__ __align__(16) unsigned char smbuf[];
    const uint32_t s_base = smem_to_u32(smbuf);
    const uint32_t sA  = s_base;
    const uint32_t sB0 = s_base + ATILE_B;

    const int lane = tid & 31;
    const int wid  = tid >> 5;
    const int wm   = wid & 1;
    const int wn   = wid >> 1;
    const int quad = lane >> 3;
    const int l8   = lane & 7;

    const int m0 = blockIdx.y * 128;
    const int n0 = blockIdx.x * 128;
    const int s_k = (ksplit == 2) ? (z & 1) : 0;
    const size_t bz = (ksplit == 2) ? (z >> 1) : z;

    const __nv_bfloat16* Ah = Ahi + bz * strideA + (size_t)m0 * lda;
    const __nv_bfloat16* Al = Alo + bz * strideA + (size_t)m0 * lda;
    const __nv_bfloat16* Bh;
    const __nv_bfloat16* Bl;
    if (TRANSB) { Bh = Bhi + bz * strideB + n0; Bl = Blo + bz * strideB + n0; }
    else        { Bh = Bhi + bz * strideB + (size_t)n0 * ldb;
                  Bl = Blo + bz * strideB + (size_t)n0 * ldb; }

    const int lrow   = tid >> 2;
    const int lchunk = tid & 3;
    const int tb_row = tid >> 4;
    const int tb_ch  = tid & 15;

    const uint32_t a_addr0 = sA + ((uint32_t)(wm * 64 + (quad & 1) * 8 + l8) * SROW
                                   + (quad >> 1) * 8) * 2;
    const uint32_t b_addr_nt = sB0 + ((uint32_t)(wn * 32 + (quad >> 1) * 8 + l8) * SROW
                                      + (quad & 1) * 8) * 2;
    const uint32_t b_addr_tr = sB0 + ((uint32_t)((quad & 1) * 8 + l8) * BROW
                                      + wn * 32 + (quad >> 1) * 8) * 2;

    float acc[4][4][4];
#pragma unroll
    for (int i = 0; i < 4; i++)
#pragma unroll
        for (int j = 0; j < 4; j++)
#pragma unroll
            for (int r = 0; r < 4; r++) acc[i][j][r] = 0.f;

    const int c0 = (s_k == 0) ? 0 : SP;
    const int c1 = (ksplit == 2) ? ((s_k == 0) ? SP : NCT) : NCT;

    auto load_tiles = [&](int stage, int c) {
        const uint32_t bo = (uint32_t)stage * STAGE_B;
        const bool pair = (c < NC1);
        const int koff = (pair ? c : c - NC1) * 32;
        const __nv_bfloat16* Ap = (pair ? Ah : Al) + koff;
#pragma unroll
        for (int h = 0; h < 2; h++) {
            const int r = lrow + h * 64;
            CP_ASYNC16(sA + bo + ((uint32_t)r * SROW + lchunk * 8) * 2,
                       Ap + (size_t)r * lda + lchunk * 8);
        }
        if (TRANSB) {
            const __nv_bfloat16* B0p = Bh + (size_t)koff * ldb;
#pragma unroll
            for (int h = 0; h < 2; h++) {
                const int r = tb_row + h * 16;
                CP_ASYNC16(sB0 + bo + ((uint32_t)r * BROW + tb_ch * 8) * 2,
                           B0p + (size_t)r * ldb + tb_ch * 8);
            }
            if (pair) {
                const __nv_bfloat16* B1p = Bl + (size_t)koff * ldb;
#pragma unroll
                for (int h = 0; h < 2; h++) {
                    const int r = tb_row + h * 16;
                    CP_ASYNC16(sB0 + BTILE + bo + ((uint32_t)r * BROW + tb_ch * 8) * 2,
                               B1p + (size_t)r * ldb + tb_ch * 8);
                }
            }
        } else {
            const __nv_bfloat16* B0p = Bh + koff;
#pragma unroll
            for (int h = 0; h < 2; h++) {
                const int r = lrow + h * 64;
                CP_ASYNC16(sB0 + bo + ((uint32_t)r * SROW + lchunk * 8) * 2,
                           B0p + (size_t)r * ldb + lchunk * 8);
            }
            if (pair) {
                const __nv_bfloat16* B1p = Bl + koff;
#pragma unroll
                for (int h = 0; h < 2; h++) {
                    const int r = lrow + h * 64;
                    CP_ASYNC16(sB0 + BTILE + bo + ((uint32_t)r * SROW + lchunk * 8) * 2,
                               B1p + (size_t)r * ldb + lchunk * 8);
                }
            }
        }
    };

    load_tiles(0, c0); CP_COMMIT();
    if (c0 + 1 < c1) load_tiles(1, c0 + 1);
    CP_COMMIT();

    int st = 0;
    int ld = 2;
    for (int c = c0; c < c1; c++) {
        CP_WAIT(STAGES - 2);
        __syncthreads();

        const uint32_t bo = (uint32_t)st * STAGE_B;
        const bool pair = (c < NC1);
#pragma unroll
        for (int ks = 0; ks < 2; ks++) {
            uint32_t afr[4][4];
#pragma unroll
            for (int mt = 0; mt < 4; mt++)
                ldsm_x4(afr[mt], a_addr0 + bo + mt * (16 * SROW * 2) + ks * 32);
            uint32_t bfr[2][4];
            if (TRANSB) {
#pragma unroll
                for (int p = 0; p < 2; p++)
                    ldsm_x4_trans(bfr[p], b_addr_tr + bo + ks * (16 * BROW * 2) + p * 32);
            } else {
#pragma unroll
                for (int p = 0; p < 2; p++)
                    ldsm_x4(bfr[p], b_addr_nt + bo + p * (16 * SROW * 2) + ks * 32);
            }
#pragma unroll
            for (int mt = 0; mt < 4; mt++)
#pragma unroll
                for (int nt = 0; nt < 4; nt++)
                    mma16816(acc[mt][nt],
                             afr[mt][0], afr[mt][1], afr[mt][2], afr[mt][3],
                             bfr[nt >> 1][(nt & 1) * 2], bfr[nt >> 1][(nt & 1) * 2 + 1]);
            if (pair) {
                if (TRANSB) {
#pragma unroll
                    for (int p = 0; p < 2; p++)
                        ldsm_x4_trans(bfr[p], b_addr_tr + BTILE + bo + ks * (16 * BROW * 2) + p * 32);
                } else {
#pragma unroll
                    for (int p = 0; p < 2; p++)
                        ldsm_x4(bfr[p], b_addr_nt + BTILE + bo + p * (16 * SROW * 2) + ks * 32);
                }
#pragma unroll
                for (int mt = 0; mt < 4; mt++)
#pragma unroll
                    for (int nt = 0; nt < 4; nt++)
                        mma16816(acc[mt][nt],
                                 afr[mt][0], afr[mt][1], afr[mt][2], afr[mt][3],
                                 bfr[nt >> 1][(nt & 1) * 2], bfr[nt >> 1][(nt & 1) * 2 + 1]);
            }
        }

        const int nxt = c + 2;
        if (nxt < c1) load_tiles(ld, nxt);
        CP_COMMIT();
        st = (st == STAGES - 1) ? 0 : st + 1;
        ld = (ld == STAGES - 1) ? 0 : ld + 1;
    }

    // epilogue (fp32)
    float* Cb = C + (size_t)s_k * strideS + bz * strideC;
    const int mb = m0 + wm * 64;
    const int nb = n0 + wn * 32;
#pragma unroll
    for (int mt = 0; mt < 4; mt++) {
#pragma unroll
        for (int nt = 0; nt < 4; nt++) {
            const int r  = mb + mt * 16 + (lane >> 2);
            const int cc = nb + nt * 8 + (lane & 3) * 2;
            *(float2*)&Cb[(size_t)r * ldc + cc] =
                make_float2(acc[mt][nt][0], acc[mt][nt][1]);
            *(float2*)&Cb[(size_t)(r + 8) * ldc + cc] =
                make_float2(acc[mt][nt][2], acc[mt][nt][3]);
        }
    }
}

// ---------------------------------------------------------------------------
// Split-K reduce for py: py = part0 + part1 + bias -> bf16 hi/lo
// 512 blocks x 256 threads, 16 floats/thread (2 rows' worth of ILP)
// ---------------------------------------------------------------------------
__global__ __launch_bounds__(256)
void reduce_bias_split_py(const float* __restrict__ Pb) {
    const size_t base = ((size_t)blockIdx.x * 256 + threadIdx.x) * 16;
    const float* p0 = g_part + base;
    const float* p1 = p0 + (size_t)BB * SEQ * DM;
    const int nb = (int)(base & (DM - 1));       // bias offset (16-aligned, wraps at 512)
    float4 a[4], b[4], c[4];
#pragma unroll
    for (int i = 0; i < 4; i++) a[i] = *(const float4*)(p0 + i * 4);
#pragma unroll
    for (int i = 0; i < 4; i++) b[i] = *(const float4*)(p1 + i * 4);
#pragma unroll
    for (int i = 0; i < 4; i++) c[i] = __ldg((const float4*)(Pb + nb + i * 4));
#pragma unroll
    for (int i = 0; i < 2; i++) {
        float v[8];
#pragma unroll
        for (int q = 0; q < 2; q++) {
            const int k = i * 2 + q;
            v[q*4+0] = a[k].x + b[k].x + c[k].x;
            v[q*4+1] = a[k].y + b[k].y + c[k].y;
            v[q*4+2] = a[k].z + b[k].z + c[k].z;
            v[q*4+3] = a[k].w + b[k].w + c[k].w;
        }
        union { unsigned short us[8]; uint4 u; } H, L;
#pragma unroll
        for (int q = 0; q < 8; q++) split2(v[q], H.us[q], L.us[q]);
        *(uint4*)(g_py_hi + base + i * 8) = H.u;
        *(uint4*)(g_py_lo + base + i * 8) = L.u;
    }
}

// ---------------------------------------------------------------------------
// Split-K reduce for out: out = part0 + part1   (2M floats)
// ---------------------------------------------------------------------------
__global__ void reduce_out_kernel(float* __restrict__ out) {
    const size_t i = ((size_t)blockIdx.x * 256 + threadIdx.x) * 4;
    float4 a = *(const float4*)(g_part + i);
    float4 b = *(const float4*)(g_part + i + (size_t)BB * SEQ * DM);
    *(float4*)(out + i) = make_float4(a.x + b.x, a.y + b.y, a.z + b.z, a.w + b.w);
}

// ---------------------------------------------------------------------------
// Masked softmax in-place + fused bf16 hi/lo split (shuffle reductions)
// ---------------------------------------------------------------------------
__global__ __launch_bounds__(256)
void softmax_mask_split(float* __restrict__ a,
                        const int* __restrict__ x) {
    const int row = blockIdx.x;          // b*SEQ + s
    const int b = row >> 7;
    float* p = a + (size_t)row * SRC;
    const int* xb = x + b * SRC;
    const int t = threadIdx.x;
    const int lane = t & 31, wid = t >> 5;

    float v[4];
    float mx = -1e30f;
#pragma unroll
    for (int i = 0; i < 4; i++) {
        const int col = t + i * 256;
        float val = p[col];
        if (__ldg(&xb[col]) == 0) val -= 1e9f;
        v[i] = val;
        mx = fmaxf(mx, val);
    }
    __shared__ float wred[16];
#pragma unroll
    for (int off = 16; off > 0; off >>= 1)
        mx = fmaxf(mx, __shfl_xor_sync(0xffffffffu, mx, off));
    if (lane == 0) wred[wid] = mx;
    __syncthreads();
    mx = wred[0];
#pragma unroll
    for (int w = 1; w < 8; w++) mx = fmaxf(mx, wred[w]);

    float sum = 0.f;
#pragma unroll
    for (int i = 0; i < 4; i++) { v[i] = __expf(v[i] - mx); sum += v[i]; }
#pragma unroll
    for (int off = 16; off > 0; off >>= 1)
        sum += __shfl_xor_sync(0xffffffffu, sum, off);
    if (lane == 0) wred[8 + wid] = sum;
    __syncthreads();
    sum = wred[8];
#pragma unroll
    for (int w = 1; w < 8; w++) sum += wred[8 + w];

    const float inv = 1.0f / sum;
    unsigned short* ah = (unsigned short*)g_a_hi + (size_t)row * SRC;
    unsigned short* al = (unsigned short*)g_a_lo + (size_t)row * SRC;
#pragma unroll
    for (int i = 0; i < 4; i++) {
        const int col = t + i * 256;
        const float val = v[i] * inv;
        p[col] = val;
        unsigned short h, l;
        split2(val, h, l);
        ah[col] = h; al[col] = l;
    }
}

// ---------------------------------------------------------------------------
extern "C" void kernel_launch(void* const* d_in, const int* in_sizes, int n_in,
                              void* d_out, int out_size) {
    const int*   x   = (const int*)  d_in[0];   // [32, 1024]
    const int*   yc  = (const int*)  d_in[1];   // [32, 640]
    const float* F   = (const float*)d_in[2];   // [32000, 512]
    const float* G   = (const float*)d_in[3];   // [32000, 512]
    const float* Pw  = (const float*)d_in[4];   // [2560, 512]
    const float* Pb  = (const float*)d_in[5];   // [512]

    float* out   = (float*)d_out;                       // [32,128,512]
    float* a_out = out + (size_t)BB * SEQ * DM;         // [32,128,1024]

    constexpr int SMEM_NT = STAGES * (ATILE_B + 2 * BTILE_NT);   // 92160
    constexpr int SMEM_TR = STAGES * (ATILE_B + 2 * BTILE_TR);   // 82944
    cudaFuncSetAttribute(mma_gemm_kernel<KPY, false>,
                         cudaFuncAttributeMaxDynamicSharedMemorySize, SMEM_NT);
    cudaFuncSetAttribute(mma_gemm_kernel<DM, false>,
                         cudaFuncAttributeMaxDynamicSharedMemorySize, SMEM_NT);
    cudaFuncSetAttribute(mma_gemm_kernel<SRC, true>,
                         cudaFuncAttributeMaxDynamicSharedMemorySize, SMEM_TR);

    __nv_bfloat16 *xe_hi, *xe_lo, *yce_hi, *yce_lo,
                  *pwt_hi, *pwt_lo, *py_hi, *py_lo, *a_hi, *a_lo;
    float* part;
    cudaGetSymbolAddress((void**)&xe_hi,  g_xe_hi);
    cudaGetSymbolAddress((void**)&xe_lo,  g_xe_lo);
    cudaGetSymbolAddress((void**)&yce_hi, g_yce_hi);
    cudaGetSymbolAddress((void**)&yce_lo, g_yce_lo);
    cudaGetSymbolAddress((void**)&pwt_hi, g_pwt_hi);
    cudaGetSymbolAddress((void**)&pwt_lo, g_pwt_lo);
    cudaGetSymbolAddress((void**)&py_hi,  g_py_hi);
    cudaGetSymbolAddress((void**)&py_lo,  g_py_lo);
    cudaGetSymbolAddress((void**)&a_hi,   g_a_hi);
    cudaGetSymbolAddress((void**)&a_lo,   g_a_lo);
    cudaGetSymbolAddress((void**)&part,   g_part);

    const size_t PART_S = (size_t)BB * SEQ * DM;   // partial-buffer stride

    // 1) fused: gather+split yce AND transpose+split P_w
    prep_fused<<<YCE_BLOCKS + PWT_BLOCKS, 256>>>(yc, G, Pw);
    // 2) py partials (split-K=2) WITH piggybacked xe gather on z==2
    mma_gemm_kernel<KPY, false><<<dim3(DM / 128, (BB * SEQ) / 128, 3), 256, SMEM_NT>>>(
        yce_hi, yce_lo, 0, KPY,
        pwt_hi, pwt_lo, 0, KPY,
        part, 0, DM, 2, PART_S, 2, x, F);
    // 3) reduce + bias + split -> py hi/lo
    reduce_bias_split_py<<<(BB * SEQ * DM) / (256 * 16), 256>>>(Pb);
    // 4) logits a[b,s,x] = py[b,s,:] . xe[b,x,:]   (M=128, N=1024, K=512, batched)
    mma_gemm_kernel<DM, false><<<dim3(SRC / 128, 1, BB), 256, SMEM_NT>>>(
        py_hi, py_lo, (size_t)SEQ * DM, DM,
        xe_hi, xe_lo, (size_t)SRC * DM, DM,
        a_out, (size_t)SEQ * SRC, SRC, 1, 0, BB, nullptr, nullptr);
    // 5) masked softmax + split
    softmax_mask_split<<<BB * SEQ, 256>>>(a_out, x);
    // 6) out partials (split-K=2, trans-B): M=128, N=512, K=1024, batched
    mma_gemm_kernel<SRC, true><<<dim3(DM / 128, 1, BB * 2), 256, SMEM_TR>>>(
        a_hi, a_lo, (size_t)SEQ * SRC, SRC,
        xe_hi, xe_lo, (size_t)SRC * DM, DM,
        part, (size_t)SEQ * DM, DM, 2, PART_S, BB * 2, nullptr, nullptr);
    // 7) reduce partials -> out
    reduce_out_kernel<<<(BB * SEQ * DM) / 1024, 256>>>(out);
}

// round 11
// speedup vs baseline: 4.7080x; 1.2846x over previous
#include <cuda_runtime.h>
#include <cuda_bf16.h>
#include <cstdint>

// Problem constants
#define BB   32
#define SRC  1024
#define SEQ  128
#define CTX  5
#define DM   512
#define KPY  (CTX*DM)   // 2560

// ---------------------------------------------------------------------------
// Scratch (device globals; no allocations allowed)
// ---------------------------------------------------------------------------
__device__ __nv_bfloat16 g_xe_hi [(size_t)BB*SRC*DM];
__device__ __nv_bfloat16 g_xe_lo [(size_t)BB*SRC*DM];
__device__ __nv_bfloat16 g_yce_hi[(size_t)BB*SEQ*KPY];
__device__ __nv_bfloat16 g_yce_lo[(size_t)BB*SEQ*KPY];
__device__ __nv_bfloat16 g_pwt_hi[(size_t)DM*KPY];
__device__ __nv_bfloat16 g_pwt_lo[(size_t)DM*KPY];
__device__ __nv_bfloat16 g_py_hi [(size_t)BB*SEQ*DM];
__device__ __nv_bfloat16 g_py_lo [(size_t)BB*SEQ*DM];
__device__ __nv_bfloat16 g_a_hi  [(size_t)BB*SEQ*SRC];
__device__ __nv_bfloat16 g_a_lo  [(size_t)BB*SEQ*SRC];
__device__ float         g_part  [(size_t)2*BB*SEQ*DM];   // 16MB split-K partials

// ---------------------------------------------------------------------------
// Helpers
// ---------------------------------------------------------------------------
__device__ __forceinline__ uint32_t smem_to_u32(const void* p) {
    uint32_t a;
    asm("{ .reg .u64 t; cvta.to.shared.u64 t, %1; cvt.u32.u64 %0, t; }"
        : "=r"(a) : "l"(p));
    return a;
}

#define CP_ASYNC16(dst, src) \
    asm volatile("cp.async.cg.shared.global [%0], [%1], 16;" \
                 :: "r"(dst), "l"(src) : "memory")
#define CP_COMMIT() asm volatile("cp.async.commit_group;" ::: "memory")
#define CP_WAIT(N)  asm volatile("cp.async.wait_group %0;" :: "n"(N) : "memory")

__device__ __forceinline__ void ldsm_x4(uint32_t r[4], uint32_t addr) {
    asm volatile("ldmatrix.sync.aligned.m8n8.x4.shared.b16 {%0,%1,%2,%3}, [%4];"
                 : "=r"(r[0]), "=r"(r[1]), "=r"(r[2]), "=r"(r[3]) : "r"(addr));
}
__device__ __forceinline__ void ldsm_x4_trans(uint32_t r[4], uint32_t addr) {
    asm volatile("ldmatrix.sync.aligned.m8n8.x4.trans.shared.b16 {%0,%1,%2,%3}, [%4];"
                 : "=r"(r[0]), "=r"(r[1]), "=r"(r[2]), "=r"(r[3]) : "r"(addr));
}

__device__ __forceinline__ void mma16816(float c[4],
                                         uint32_t a0, uint32_t a1, uint32_t a2, uint32_t a3,
                                         uint32_t b0, uint32_t b1) {
    asm volatile("mma.sync.aligned.m16n8k16.row.col.f32.bf16.bf16.f32 "
                 "{%0,%1,%2,%3}, {%4,%5,%6,%7}, {%8,%9}, {%0,%1,%2,%3};"
                 : "+f"(c[0]), "+f"(c[1]), "+f"(c[2]), "+f"(c[3])
                 : "r"(a0), "r"(a1), "r"(a2), "r"(a3), "r"(b0), "r"(b1));
}

// fp32 -> (bf16 hi, bf16 lo) split
__device__ __forceinline__ void split2(float v, unsigned short& h, unsigned short& l) {
    __nv_bfloat16 hb = __float2bfloat16(v);
    __nv_bfloat16 lb = __float2bfloat16(v - __bfloat162float(hb));
    h = __bfloat16_as_ushort(hb);
    l = __bfloat16_as_ushort(lb);
}

// ---------------------------------------------------------------------------
// Fused prep: blocks [0, 5120) gather+split yce; blocks [5120, 5440) pwt.
// ---------------------------------------------------------------------------
#define YCE_BLOCKS (BB * SEQ * CTX / 4)      // 5120
#define PWT_BLOCKS ((KPY / 64) * (DM / 64))  // 320

__global__ __launch_bounds__(256)
void prep_fused(const int* __restrict__ yc, const float* __restrict__ G,
                const float* __restrict__ Pw) {
    __shared__ float s[64][65];
    const int bid = blockIdx.x;
    const int t = threadIdx.x;

    if (bid < YCE_BLOCKS) {
        const int c = bid % CTX;
        const int m = (bid / CTX) * 4 + (t >> 6);
        const int col8 = (t & 63) * 8;
        const int tok = __ldg(&yc[m * CTX + c]);
        const float* src = G + (size_t)tok * DM + col8;
        float4 a = __ldg((const float4*)src);
        float4 b = __ldg((const float4*)(src + 4));
        float v[8] = {a.x, a.y, a.z, a.w, b.x, b.y, b.z, b.w};
        union { unsigned short us[8]; uint4 u; } H, L;
#pragma unroll
        for (int i = 0; i < 8; i++) split2(v[i], H.us[i], L.us[i]);
        const size_t off = (size_t)m * KPY + c * DM + col8;
        *(uint4*)(g_yce_hi + off) = H.u;
        *(uint4*)(g_yce_lo + off) = L.u;
    } else {
        const int j = bid - YCE_BLOCKS;
        const int k0 = (j % (KPY / 64)) * 64;
        const int n0 = (j / (KPY / 64)) * 64;
        const int tx = t & 31, ty = t >> 5;
#pragma unroll
        for (int i = 0; i < 8; i++) {
            const int r = ty + i * 8;
            float2 v = *(const float2*)(Pw + (size_t)(k0 + r) * DM + n0 + tx * 2);
            s[r][tx * 2] = v.x; s[r][tx * 2 + 1] = v.y;
        }
        __syncthreads();
#pragma unroll
        for (int i = 0; i < 8; i++) {
            const int nr = ty + i * 8;
            float v0 = s[tx * 2][nr], v1 = s[tx * 2 + 1][nr];
            unsigned short h0, l0, h1, l1;
            split2(v0, h0, l0); split2(v1, h1, l1);
            const size_t off = (size_t)(n0 + nr) * KPY + k0 + tx * 2;
            *(unsigned*)((unsigned short*)g_pwt_hi + off) = (unsigned)h0 | ((unsigned)h1 << 16);
            *(unsigned*)((unsigned short*)g_pwt_lo + off) = (unsigned)l0 | ((unsigned)l1 << 16);
        }
    }
}

// ---------------------------------------------------------------------------
// mma.sync GEMM.
// THREE=true : 3-term split  A' = [Ahi|Ahi|Alo], B' = [Bhi|Blo|Bhi]
//   phase 1 (c < NC1): Ahi x (Bhi, Blo) paired;  phase 2: Alo x Bhi
// THREE=false: 2-term split  Ahi x (Bhi, Blo) only (A effectively bf16)
// CTA tile 128x128, BK=32, 8 warps, m16n8k16, 3-stage cp.async.
// Extra z-planes (z >= zmain) run an independent xe gather+split (overlap).
// ---------------------------------------------------------------------------
#define SROW 40
#define BROW 136
#define ATILE_B (128 * SROW * 2)   // 10240
#define BTILE_NT (128 * SROW * 2)  // 10240
#define BTILE_TR (32 * BROW * 2)   // 8704
#define STAGES 3

template<int K, bool TRANSB, bool THREE>
__global__ __launch_bounds__(256, 2)
void mma_gemm_kernel(const __nv_bfloat16* __restrict__ Ahi, const __nv_bfloat16* __restrict__ Alo,
                     size_t strideA, int lda,
                     const __nv_bfloat16* __restrict__ Bhi, const __nv_bfloat16* __restrict__ Blo,
                     size_t strideB, int ldb,
                     float* __restrict__ C, size_t strideC, int ldc,
                     int ksplit, size_t strideS,
                     int zmain, const int* __restrict__ gx, const float* __restrict__ gF) {
    const int tid = threadIdx.x;
    const int z   = blockIdx.z;

    // ---- piggyback plane: gather + split xe (independent of GEMM inputs) ----
    if (z >= zmain) {
        const int gid  = blockIdx.y * gridDim.x + blockIdx.x;   // 0..127
        const int rsub = tid >> 6;
        const int col8 = (tid & 63) * 8;
        const int rbase = gid * 256;
#pragma unroll 4
        for (int rr = 0; rr < 64; rr++) {
            const int row = rbase + rr * 4 + rsub;
            const int tok = __ldg(&gx[row]);
            const float* src = gF + (size_t)tok * DM + col8;
            float4 a = __ldg((const float4*)src);
            float4 b = __ldg((const float4*)(src + 4));
            float v[8] = {a.x, a.y, a.z, a.w, b.x, b.y, b.z, b.w};
            union { unsigned short us[8]; uint4 u; } H, L;
#pragma unroll
            for (int i = 0; i < 8; i++) split2(v[i], H.us[i], L.us[i]);
            *(uint4*)(g_xe_hi + (size_t)row * DM + col8) = H.u;
            *(uint4*)(g_xe_lo + (size_t)row * DM + col8) = L.u;
        }
        return;
    }

    constexpr int BTILE   = TRANSB ? BTILE_TR : BTILE_NT;
    constexpr int STAGE_B = ATILE_B + 2 * BTILE;
    constexpr int NC1 = K / 32;
    constexpr int NCT = THREE ? 2 * NC1 : NC1;
    constexpr int SP  = THREE ? (3 * NC1) / 4 : NC1 / 2;

    extern __shared__ __align__(16) unsigned char smbuf[];
    const uint32_t s_base = smem_to_u32(smbuf);
    const uint32_t sA  = s_base;
    const uint32_t sB0 = s_base + ATILE_B;

    const int lane = tid & 31;
    const int wid  = tid >> 5;
    const int wm   = wid & 1;
    const int wn   = wid >> 1;
    const int quad = lane >> 3;
    const int l8   = lane & 7;

    const int m0 = blockIdx.y * 128;
    const int n0 = blockIdx.x * 128;
    const int s_k = (ksplit == 2) ? (z & 1) : 0;
    const size_t bz = (ksplit == 2) ? (z >> 1) : z;

    const __nv_bfloat16* Ah = Ahi + bz * strideA + (size_t)m0 * lda;
    const __nv_bfloat16* Al = Alo + bz * strideA + (size_t)m0 * lda;
    const __nv_bfloat16* Bh;
    const __nv_bfloat16* Bl;
    if (TRANSB) { Bh = Bhi + bz * strideB + n0; Bl = Blo + bz * strideB + n0; }
    else        { Bh = Bhi + bz * strideB + (size_t)n0 * ldb;
                  Bl = Blo + bz * strideB + (size_t)n0 * ldb; }

    const int lrow   = tid >> 2;
    const int lchunk = tid & 3;
    const int tb_row = tid >> 4;
    const int tb_ch  = tid & 15;

    const uint32_t a_addr0 = sA + ((uint32_t)(wm * 64 + (quad & 1) * 8 + l8) * SROW
                                   + (quad >> 1) * 8) * 2;
    const uint32_t b_addr_nt = sB0 + ((uint32_t)(wn * 32 + (quad >> 1) * 8 + l8) * SROW
                                      + (quad & 1) * 8) * 2;
    const uint32_t b_addr_tr = sB0 + ((uint32_t)((quad & 1) * 8 + l8) * BROW
                                      + wn * 32 + (quad >> 1) * 8) * 2;

    float acc[4][4][4];
#pragma unroll
    for (int i = 0; i < 4; i++)
#pragma unroll
        for (int j = 0; j < 4; j++)
#pragma unroll
            for (int r = 0; r < 4; r++) acc[i][j][r] = 0.f;

    const int c0 = (s_k == 0) ? 0 : SP;
    const int c1 = (ksplit == 2) ? ((s_k == 0) ? SP : NCT) : NCT;

    auto load_tiles = [&](int stage, int c) {
        const uint32_t bo = (uint32_t)stage * STAGE_B;
        const bool pair = !THREE || (c < NC1);
        const int koff = (pair ? c : c - NC1) * 32;
        const __nv_bfloat16* Ap = (pair ? Ah : Al) + koff;
#pragma unroll
        for (int h = 0; h < 2; h++) {
            const int r = lrow + h * 64;
            CP_ASYNC16(sA + bo + ((uint32_t)r * SROW + lchunk * 8) * 2,
                       Ap + (size_t)r * lda + lchunk * 8);
        }
        if (TRANSB) {
            const __nv_bfloat16* B0p = Bh + (size_t)koff * ldb;
#pragma unroll
            for (int h = 0; h < 2; h++) {
                const int r = tb_row + h * 16;
                CP_ASYNC16(sB0 + bo + ((uint32_t)r * BROW + tb_ch * 8) * 2,
                           B0p + (size_t)r * ldb + tb_ch * 8);
            }
            if (pair) {
                const __nv_bfloat16* B1p = Bl + (size_t)koff * ldb;
#pragma unroll
                for (int h = 0; h < 2; h++) {
                    const int r = tb_row + h * 16;
                    CP_ASYNC16(sB0 + BTILE + bo + ((uint32_t)r * BROW + tb_ch * 8) * 2,
                               B1p + (size_t)r * ldb + tb_ch * 8);
                }
            }
        } else {
            const __nv_bfloat16* B0p = Bh + koff;
#pragma unroll
            for (int h = 0; h < 2; h++) {
                const int r = lrow + h * 64;
                CP_ASYNC16(sB0 + bo + ((uint32_t)r * SROW + lchunk * 8) * 2,
                           B0p + (size_t)r * ldb + lchunk * 8);
            }
            if (pair) {
                const __nv_bfloat16* B1p = Bl + koff;
#pragma unroll
                for (int h = 0; h < 2; h++) {
                    const int r = lrow + h * 64;
                    CP_ASYNC16(sB0 + BTILE + bo + ((uint32_t)r * SROW + lchunk * 8) * 2,
                               B1p + (size_t)r * ldb + lchunk * 8);
                }
            }
        }
    };

    load_tiles(0, c0); CP_COMMIT();
    if (c0 + 1 < c1) load_tiles(1, c0 + 1);
    CP_COMMIT();

    int st = 0;
    int ld = 2;
    for (int c = c0; c < c1; c++) {
        CP_WAIT(STAGES - 2);
        __syncthreads();

        const uint32_t bo = (uint32_t)st * STAGE_B;
        const bool pair = !THREE || (c < NC1);
#pragma unroll
        for (int ks = 0; ks < 2; ks++) {
            uint32_t afr[4][4];
#pragma unroll
            for (int mt = 0; mt < 4; mt++)
                ldsm_x4(afr[mt], a_addr0 + bo + mt * (16 * SROW * 2) + ks * 32);
            uint32_t bfr[2][4];
            if (TRANSB) {
#pragma unroll
                for (int p = 0; p < 2; p++)
                    ldsm_x4_trans(bfr[p], b_addr_tr + bo + ks * (16 * BROW * 2) + p * 32);
            } else {
#pragma unroll
                for (int p = 0; p < 2; p++)
                    ldsm_x4(bfr[p], b_addr_nt + bo + p * (16 * SROW * 2) + ks * 32);
            }
#pragma unroll
            for (int mt = 0; mt < 4; mt++)
#pragma unroll
                for (int nt = 0; nt < 4; nt++)
                    mma16816(acc[mt][nt],
                             afr[mt][0], afr[mt][1], afr[mt][2], afr[mt][3],
                             bfr[nt >> 1][(nt & 1) * 2], bfr[nt >> 1][(nt & 1) * 2 + 1]);
            if (pair) {
                if (TRANSB) {
#pragma unroll
                    for (int p = 0; p < 2; p++)
                        ldsm_x4_trans(bfr[p], b_addr_tr + BTILE + bo + ks * (16 * BROW * 2) + p * 32);
                } else {
#pragma unroll
                    for (int p = 0; p < 2; p++)
                        ldsm_x4(bfr[p], b_addr_nt + BTILE + bo + p * (16 * SROW * 2) + ks * 32);
                }
#pragma unroll
                for (int mt = 0; mt < 4; mt++)
#pragma unroll
                    for (int nt = 0; nt < 4; nt++)
                        mma16816(acc[mt][nt],
                                 afr[mt][0], afr[mt][1], afr[mt][2], afr[mt][3],
                                 bfr[nt >> 1][(nt & 1) * 2], bfr[nt >> 1][(nt & 1) * 2 + 1]);
            }
        }

        const int nxt = c + 2;
        if (nxt < c1) load_tiles(ld, nxt);
        CP_COMMIT();
        st = (st == STAGES - 1) ? 0 : st + 1;
        ld = (ld == STAGES - 1) ? 0 : ld + 1;
    }

    // epilogue (fp32)
    float* Cb = C + (size_t)s_k * strideS + bz * strideC;
    const int mb = m0 + wm * 64;
    const int nb = n0 + wn * 32;
#pragma unroll
    for (int mt = 0; mt < 4; mt++) {
#pragma unroll
        for (int nt = 0; nt < 4; nt++) {
            const int r  = mb + mt * 16 + (lane >> 2);
            const int cc = nb + nt * 8 + (lane & 3) * 2;
            *(float2*)&Cb[(size_t)r * ldc + cc] =
                make_float2(acc[mt][nt][0], acc[mt][nt][1]);
            *(float2*)&Cb[(size_t)(r + 8) * ldc + cc] =
                make_float2(acc[mt][nt][2], acc[mt][nt][3]);
        }
    }
}

// ---------------------------------------------------------------------------
// Split-K reduce for py: py = part0 + part1 + bias -> bf16 hi/lo
// ---------------------------------------------------------------------------
__global__ __launch_bounds__(256)
void reduce_bias_split_py(const float* __restrict__ Pb) {
    const size_t base = ((size_t)blockIdx.x * 256 + threadIdx.x) * 16;
    const float* p0 = g_part + base;
    const float* p1 = p0 + (size_t)BB * SEQ * DM;
    const int nb = (int)(base & (DM - 1));
    float4 a[4], b[4], c[4];
#pragma unroll
    for (int i = 0; i < 4; i++) a[i] = *(const float4*)(p0 + i * 4);
#pragma unroll
    for (int i = 0; i < 4; i++) b[i] = *(const float4*)(p1 + i * 4);
#pragma unroll
    for (int i = 0; i < 4; i++) c[i] = __ldg((const float4*)(Pb + nb + i * 4));
#pragma unroll
    for (int i = 0; i < 2; i++) {
        float v[8];
#pragma unroll
        for (int q = 0; q < 2; q++) {
            const int k = i * 2 + q;
            v[q*4+0] = a[k].x + b[k].x + c[k].x;
            v[q*4+1] = a[k].y + b[k].y + c[k].y;
            v[q*4+2] = a[k].z + b[k].z + c[k].z;
            v[q*4+3] = a[k].w + b[k].w + c[k].w;
        }
        union { unsigned short us[8]; uint4 u; } H, L;
#pragma unroll
        for (int q = 0; q < 8; q++) split2(v[q], H.us[q], L.us[q]);
        *(uint4*)(g_py_hi + base + i * 8) = H.u;
        *(uint4*)(g_py_lo + base + i * 8) = L.u;
    }
}

// ---------------------------------------------------------------------------
// Split-K reduce for out: out = part0 + part1
// ---------------------------------------------------------------------------
__global__ void reduce_out_kernel(float* __restrict__ out) {
    const size_t i = ((size_t)blockIdx.x * 256 + threadIdx.x) * 4;
    float4 a = *(const float4*)(g_part + i);
    float4 b = *(const float4*)(g_part + i + (size_t)BB * SEQ * DM);
    *(float4*)(out + i) = make_float4(a.x + b.x, a.y + b.y, a.z + b.z, a.w + b.w);
}

// ---------------------------------------------------------------------------
// Masked softmax in-place + fused bf16 hi/lo split (shuffle reductions)
// ---------------------------------------------------------------------------
__global__ __launch_bounds__(256)
void softmax_mask_split(float* __restrict__ a,
                        const int* __restrict__ x) {
    const int row = blockIdx.x;
    const int b = row >> 7;
    float* p = a + (size_t)row * SRC;
    const int* xb = x + b * SRC;
    const int t = threadIdx.x;
    const int lane = t & 31, wid = t >> 5;

    float v[4];
    float mx = -1e30f;
#pragma unroll
    for (int i = 0; i < 4; i++) {
        const int col = t + i * 256;
        float val = p[col];
        if (__ldg(&xb[col]) == 0) val -= 1e9f;
        v[i] = val;
        mx = fmaxf(mx, val);
    }
    __shared__ float wred[16];
#pragma unroll
    for (int off = 16; off > 0; off >>= 1)
        mx = fmaxf(mx, __shfl_xor_sync(0xffffffffu, mx, off));
    if (lane == 0) wred[wid] = mx;
    __syncthreads();
    mx = wred[0];
#pragma unroll
    for (int w = 1; w < 8; w++) mx = fmaxf(mx, wred[w]);

    float sum = 0.f;
#pragma unroll
    for (int i = 0; i < 4; i++) { v[i] = __expf(v[i] - mx); sum += v[i]; }
#pragma unroll
    for (int off = 16; off > 0; off >>= 1)
        sum += __shfl_xor_sync(0xffffffffu, sum, off);
    if (lane == 0) wred[8 + wid] = sum;
    __syncthreads();
    sum = wred[8];
#pragma unroll
    for (int w = 1; w < 8; w++) sum += wred[8 + w];

    const float inv = 1.0f / sum;
    unsigned short* ah = (unsigned short*)g_a_hi + (size_t)row * SRC;
    unsigned short* al = (unsigned short*)g_a_lo + (size_t)row * SRC;
#pragma unroll
    for (int i = 0; i < 4; i++) {
        const int col = t + i * 256;
        const float val = v[i] * inv;
        p[col] = val;
        unsigned short h, l;
        split2(val, h, l);
        ah[col] = h; al[col] = l;
    }
}

// ---------------------------------------------------------------------------
extern "C" void kernel_launch(void* const* d_in, const int* in_sizes, int n_in,
                              void* d_out, int out_size) {
    const int*   x   = (const int*)  d_in[0];   // [32, 1024]
    const int*   yc  = (const int*)  d_in[1];   // [32, 640]
    const float* F   = (const float*)d_in[2];   // [32000, 512]
    const float* G   = (const float*)d_in[3];   // [32000, 512]
    const float* Pw  = (const float*)d_in[4];   // [2560, 512]
    const float* Pb  = (const float*)d_in[5];   // [512]

    float* out   = (float*)d_out;                       // [32,128,512]
    float* a_out = out + (size_t)BB * SEQ * DM;         // [32,128,1024]

    constexpr int SMEM_NT = STAGES * (ATILE_B + 2 * BTILE_NT);   // 92160
    constexpr int SMEM_TR = STAGES * (ATILE_B + 2 * BTILE_TR);   // 82944
    cudaFuncSetAttribute(mma_gemm_kernel<KPY, false, false>,
                         cudaFuncAttributeMaxDynamicSharedMemorySize, SMEM_NT);
    cudaFuncSetAttribute(mma_gemm_kernel<DM, false, false>,
                         cudaFuncAttributeMaxDynamicSharedMemorySize, SMEM_NT);
    cudaFuncSetAttribute(mma_gemm_kernel<SRC, true, true>,
                         cudaFuncAttributeMaxDynamicSharedMemorySize, SMEM_TR);

    __nv_bfloat16 *xe_hi, *xe_lo, *yce_hi, *yce_lo,
                  *pwt_hi, *pwt_lo, *py_hi, *py_lo, *a_hi, *a_lo;
    float* part;
    cudaGetSymbolAddress((void**)&xe_hi,  g_xe_hi);
    cudaGetSymbolAddress((void**)&xe_lo,  g_xe_lo);
    cudaGetSymbolAddress((void**)&yce_hi, g_yce_hi);
    cudaGetSymbolAddress((void**)&yce_lo, g_yce_lo);
    cudaGetSymbolAddress((void**)&pwt_hi, g_pwt_hi);
    cudaGetSymbolAddress((void**)&pwt_lo, g_pwt_lo);
    cudaGetSymbolAddress((void**)&py_hi,  g_py_hi);
    cudaGetSymbolAddress((void**)&py_lo,  g_py_lo);
    cudaGetSymbolAddress((void**)&a_hi,   g_a_hi);
    cudaGetSymbolAddress((void**)&a_lo,   g_a_lo);
    cudaGetSymbolAddress((void**)&part,   g_part);

    const size_t PART_S = (size_t)BB * SEQ * DM;   // partial-buffer stride

    // 1) fused: gather+split yce AND transpose+split P_w
    prep_fused<<<YCE_BLOCKS + PWT_BLOCKS, 256>>>(yc, G, Pw);
    // 2) py partials (2-term, split-K=2) + piggybacked xe gather on z==2
    mma_gemm_kernel<KPY, false, false><<<dim3(DM / 128, (BB * SEQ) / 128, 3), 256, SMEM_NT>>>(
        yce_hi, yce_lo, 0, KPY,
        pwt_hi, pwt_lo, 0, KPY,
        part, 0, DM, 2, PART_S, 2, x, F);
    // 3) reduce + bias + split -> py hi/lo
    reduce_bias_split_py<<<(BB * SEQ * DM) / (256 * 16), 256>>>(Pb);
    // 4) logits (2-term): a[b,s,x] = py[b,s,:] . xe[b,x,:]   (M=128, N=1024, K=512)
    mma_gemm_kernel<DM, false, false><<<dim3(SRC / 128, 1, BB), 256, SMEM_NT>>>(
        py_hi, py_lo, (size_t)SEQ * DM, DM,
        xe_hi, xe_lo, (size_t)SRC * DM, DM,
        a_out, (size_t)SEQ * SRC, SRC, 1, 0, BB, nullptr, nullptr);
    // 5) masked softmax + split
    softmax_mask_split<<<BB * SEQ, 256>>>(a_out, x);
    // 6) out partials (3-term, split-K=2, trans-B): M=128, N=512, K=1024
    mma_gemm_kernel<SRC, true, true><<<dim3(DM / 128, 1, BB * 2), 256, SMEM_TR>>>(
        a_hi, a_lo, (size_t)SEQ * SRC, SRC,
        xe_hi, xe_lo, (size_t)SRC * DM, DM,
        part, (size_t)SEQ * DM, DM, 2, PART_S, BB * 2, nullptr, nullptr);
    // 7) reduce partials -> out
    reduce_out_kernel<<<(BB * SEQ * DM) / 1024, 256>>>(out);
}

// round 12
// speedup vs baseline: 4.7194x; 1.0024x over previous
#include <cuda_runtime.h>
#include <cuda_bf16.h>
#include <cstdint>

// Problem constants
#define BB   32
#define SRC  1024
#define SEQ  128
#define CTX  5
#define DM   512
#define KPY  (CTX*DM)   // 2560

// ---------------------------------------------------------------------------
// Scratch (device globals; no allocations allowed)
// ---------------------------------------------------------------------------
__device__ __nv_bfloat16 g_xe_hi [(size_t)BB*SRC*DM];
__device__ __nv_bfloat16 g_xe_lo [(size_t)BB*SRC*DM];
__device__ __nv_bfloat16 g_yce_hi[(size_t)BB*SEQ*KPY];
__device__ __nv_bfloat16 g_pwt_hi[(size_t)DM*KPY];
__device__ __nv_bfloat16 g_pwt_lo[(size_t)DM*KPY];
__device__ __nv_bfloat16 g_py_hi [(size_t)BB*SEQ*DM];
__device__ __nv_bfloat16 g_a_hi  [(size_t)BB*SEQ*SRC];
__device__ __nv_bfloat16 g_a_lo  [(size_t)BB*SEQ*SRC];
__device__ float         g_part  [(size_t)2*BB*SEQ*DM];   // split-K partials (py)

// ---------------------------------------------------------------------------
// Helpers
// ---------------------------------------------------------------------------
__device__ __forceinline__ uint32_t smem_to_u32(const void* p) {
    uint32_t a;
    asm("{ .reg .u64 t; cvta.to.shared.u64 t, %1; cvt.u32.u64 %0, t; }"
        : "=r"(a) : "l"(p));
    return a;
}

#define CP_ASYNC16(dst, src) \
    asm volatile("cp.async.cg.shared.global [%0], [%1], 16;" \
                 :: "r"(dst), "l"(src) : "memory")
#define CP_COMMIT() asm volatile("cp.async.commit_group;" ::: "memory")
#define CP_WAIT(N)  asm volatile("cp.async.wait_group %0;" :: "n"(N) : "memory")

#define REDG_ADD_F32(addr, val) \
    asm volatile("red.global.add.f32 [%0], %1;" :: "l"(addr), "f"(val) : "memory")

__device__ __forceinline__ void ldsm_x4(uint32_t r[4], uint32_t addr) {
    asm volatile("ldmatrix.sync.aligned.m8n8.x4.shared.b16 {%0,%1,%2,%3}, [%4];"
                 : "=r"(r[0]), "=r"(r[1]), "=r"(r[2]), "=r"(r[3]) : "r"(addr));
}
__device__ __forceinline__ void ldsm_x4_trans(uint32_t r[4], uint32_t addr) {
    asm volatile("ldmatrix.sync.aligned.m8n8.x4.trans.shared.b16 {%0,%1,%2,%3}, [%4];"
                 : "=r"(r[0]), "=r"(r[1]), "=r"(r[2]), "=r"(r[3]) : "r"(addr));
}

__device__ __forceinline__ void mma16816(float c[4],
                                         uint32_t a0, uint32_t a1, uint32_t a2, uint32_t a3,
                                         uint32_t b0, uint32_t b1) {
    asm volatile("mma.sync.aligned.m16n8k16.row.col.f32.bf16.bf16.f32 "
                 "{%0,%1,%2,%3}, {%4,%5,%6,%7}, {%8,%9}, {%0,%1,%2,%3};"
                 : "+f"(c[0]), "+f"(c[1]), "+f"(c[2]), "+f"(c[3])
                 : "r"(a0), "r"(a1), "r"(a2), "r"(a3), "r"(b0), "r"(b1));
}

// fp32 -> (bf16 hi, bf16 lo) split
__device__ __forceinline__ void split2(float v, unsigned short& h, unsigned short& l) {
    __nv_bfloat16 hb = __float2bfloat16(v);
    __nv_bfloat16 lb = __float2bfloat16(v - __bfloat162float(hb));
    h = __bfloat16_as_ushort(hb);
    l = __bfloat16_as_ushort(lb);
}

// ---------------------------------------------------------------------------
// Fused prep: [0, YCE) gather+split-hi yce; [YCE, YCE+PWT) pwt transpose+split;
// [YCE+PWT, YCE+PWT+ZOUT) zero-init d_out's out region (for RED accumulation).
// ---------------------------------------------------------------------------
#define YCE_BLOCKS (BB * SEQ * CTX / 4)      // 5120
#define PWT_BLOCKS ((KPY / 64) * (DM / 64))  // 320
#define ZOUT_BLOCKS ((BB * SEQ * DM) / 4096) // 512

__global__ __launch_bounds__(256)
void prep_fused(const int* __restrict__ yc, const float* __restrict__ G,
                const float* __restrict__ Pw, float* __restrict__ out_zero) {
    __shared__ float s[64][65];
    const int bid = blockIdx.x;
    const int t = threadIdx.x;

    if (bid < YCE_BLOCKS) {
        const int c = bid % CTX;
        const int m = (bid / CTX) * 4 + (t >> 6);
        const int col8 = (t & 63) * 8;
        const int tok = __ldg(&yc[m * CTX + c]);
        const float* src = G + (size_t)tok * DM + col8;
        float4 a = __ldg((const float4*)src);
        float4 b = __ldg((const float4*)(src + 4));
        float v[8] = {a.x, a.y, a.z, a.w, b.x, b.y, b.z, b.w};
        union { unsigned short us[8]; uint4 u; } H;
#pragma unroll
        for (int i = 0; i < 8; i++)
            H.us[i] = __bfloat16_as_ushort(__float2bfloat16(v[i]));
        *(uint4*)(g_yce_hi + (size_t)m * KPY + c * DM + col8) = H.u;
    } else if (bid < YCE_BLOCKS + PWT_BLOCKS) {
        const int j = bid - YCE_BLOCKS;
        const int k0 = (j % (KPY / 64)) * 64;
        const int n0 = (j / (KPY / 64)) * 64;
        const int tx = t & 31, ty = t >> 5;
#pragma unroll
        for (int i = 0; i < 8; i++) {
            const int r = ty + i * 8;
            float2 v = *(const float2*)(Pw + (size_t)(k0 + r) * DM + n0 + tx * 2);
            s[r][tx * 2] = v.x; s[r][tx * 2 + 1] = v.y;
        }
        __syncthreads();
#pragma unroll
        for (int i = 0; i < 8; i++) {
            const int nr = ty + i * 8;
            float v0 = s[tx * 2][nr], v1 = s[tx * 2 + 1][nr];
            unsigned short h0, l0, h1, l1;
            split2(v0, h0, l0); split2(v1, h1, l1);
            const size_t off = (size_t)(n0 + nr) * KPY + k0 + tx * 2;
            *(unsigned*)((unsigned short*)g_pwt_hi + off) = (unsigned)h0 | ((unsigned)h1 << 16);
            *(unsigned*)((unsigned short*)g_pwt_lo + off) = (unsigned)l0 | ((unsigned)l1 << 16);
        }
    } else {
        const int j = bid - YCE_BLOCKS - PWT_BLOCKS;
        float* p = out_zero + (size_t)j * 4096 + t * 16;
        const uint4 z = make_uint4(0u, 0u, 0u, 0u);
#pragma unroll
        for (int q = 0; q < 4; q++) *(uint4*)(p + q * 4) = z;
    }
}

// ---------------------------------------------------------------------------
// mma.sync GEMM.
// THREE=true : 3-term split  A' = [Ahi|Ahi|Alo], B' = [Bhi|Blo|Bhi]
// THREE=false: 2-term split  Ahi x (Bhi, Blo) only (A effectively bf16)
// REDC=true  : epilogue accumulates into C via red.global.add.f32 (C pre-zeroed)
// CTA tile 128x128, BK=32, 8 warps, m16n8k16, 3-stage cp.async.
// Extra z-planes (z >= zmain) run an independent xe gather+split (overlap).
// ---------------------------------------------------------------------------
#define SROW 40
#define BROW 136
#define ATILE_B (128 * SROW * 2)   // 10240
#define BTILE_NT (128 * SROW * 2)  // 10240
#define BTILE_TR (32 * BROW * 2)   // 8704
#define STAGES 3

template<int K, bool TRANSB, bool THREE, bool REDC>
__global__ __launch_bounds__(256, 2)
void mma_gemm_kernel(const __nv_bfloat16* __restrict__ Ahi, const __nv_bfloat16* __restrict__ Alo,
                     size_t strideA, int lda,
                     const __nv_bfloat16* __restrict__ Bhi, const __nv_bfloat16* __restrict__ Blo,
                     size_t strideB, int ldb,
                     float* __restrict__ C, size_t strideC, int ldc,
                     int ksplit, size_t strideS,
                     int zmain, const int* __restrict__ gx, const float* __restrict__ gF) {
    const int tid = threadIdx.x;
    const int z   = blockIdx.z;

    // ---- piggyback plane: gather + split xe (independent of GEMM inputs) ----
    if (z >= zmain) {
        const int gid  = blockIdx.y * gridDim.x + blockIdx.x;   // 0..127
        const int rsub = tid >> 6;
        const int col8 = (tid & 63) * 8;
        const int rbase = gid * 256;
#pragma unroll 4
        for (int rr = 0; rr < 64; rr++) {
            const int row = rbase + rr * 4 + rsub;
            const int tok = __ldg(&gx[row]);
            const float* src = gF + (size_t)tok * DM + col8;
            float4 a = __ldg((const float4*)src);
            float4 b = __ldg((const float4*)(src + 4));
            float v[8] = {a.x, a.y, a.z, a.w, b.x, b.y, b.z, b.w};
            union { unsigned short us[8]; uint4 u; } H, L;
#pragma unroll
            for (int i = 0; i < 8; i++) split2(v[i], H.us[i], L.us[i]);
            *(uint4*)(g_xe_hi + (size_t)row * DM + col8) = H.u;
            *(uint4*)(g_xe_lo + (size_t)row * DM + col8) = L.u;
        }
        return;
    }

    constexpr int BTILE   = TRANSB ? BTILE_TR : BTILE_NT;
    constexpr int STAGE_B = ATILE_B + 2 * BTILE;
    constexpr int NC1 = K / 32;
    constexpr int NCT = THREE ? 2 * NC1 : NC1;
    constexpr int SP  = THREE ? (3 * NC1) / 4 : NC1 / 2;

    extern __shared__ __align__(16) unsigned char smbuf[];
    const uint32_t s_base = smem_to_u32(smbuf);
    const uint32_t sA  = s_base;
    const uint32_t sB0 = s_base + ATILE_B;

    const int lane = tid & 31;
    const int wid  = tid >> 5;
    const int wm   = wid & 1;
    const int wn   = wid >> 1;
    const int quad = lane >> 3;
    const int l8   = lane & 7;

    const int m0 = blockIdx.y * 128;
    const int n0 = blockIdx.x * 128;
    const int s_k = (ksplit == 2) ? (z & 1) : 0;
    const size_t bz = (ksplit == 2) ? (z >> 1) : z;

    const __nv_bfloat16* Ah = Ahi + bz * strideA + (size_t)m0 * lda;
    const __nv_bfloat16* Al = Alo + bz * strideA + (size_t)m0 * lda;
    const __nv_bfloat16* Bh;
    const __nv_bfloat16* Bl;
    if (TRANSB) { Bh = Bhi + bz * strideB + n0; Bl = Blo + bz * strideB + n0; }
    else        { Bh = Bhi + bz * strideB + (size_t)n0 * ldb;
                  Bl = Blo + bz * strideB + (size_t)n0 * ldb; }

    const int lrow   = tid >> 2;
    const int lchunk = tid & 3;
    const int tb_row = tid >> 4;
    const int tb_ch  = tid & 15;

    const uint32_t a_addr0 = sA + ((uint32_t)(wm * 64 + (quad & 1) * 8 + l8) * SROW
                                   + (quad >> 1) * 8) * 2;
    const uint32_t b_addr_nt = sB0 + ((uint32_t)(wn * 32 + (quad >> 1) * 8 + l8) * SROW
                                      + (quad & 1) * 8) * 2;
    const uint32_t b_addr_tr = sB0 + ((uint32_t)((quad & 1) * 8 + l8) * BROW
                                      + wn * 32 + (quad >> 1) * 8) * 2;

    float acc[4][4][4];
#pragma unroll
    for (int i = 0; i < 4; i++)
#pragma unroll
        for (int j = 0; j < 4; j++)
#pragma unroll
            for (int r = 0; r < 4; r++) acc[i][j][r] = 0.f;

    const int c0 = (s_k == 0) ? 0 : SP;
    const int c1 = (ksplit == 2) ? ((s_k == 0) ? SP : NCT) : NCT;

    auto load_tiles = [&](int stage, int c) {
        const uint32_t bo = (uint32_t)stage * STAGE_B;
        const bool pair = !THREE || (c < NC1);
        const int koff = (pair ? c : c - NC1) * 32;
        const __nv_bfloat16* Ap = (pair ? Ah : Al) + koff;
#pragma unroll
        for (int h = 0; h < 2; h++) {
            const int r = lrow + h * 64;
            CP_ASYNC16(sA + bo + ((uint32_t)r * SROW + lchunk * 8) * 2,
                       Ap + (size_t)r * lda + lchunk * 8);
        }
        if (TRANSB) {
            const __nv_bfloat16* B0p = Bh + (size_t)koff * ldb;
#pragma unroll
            for (int h = 0; h < 2; h++) {
                const int r = tb_row + h * 16;
                CP_ASYNC16(sB0 + bo + ((uint32_t)r * BROW + tb_ch * 8) * 2,
                           B0p + (size_t)r * ldb + tb_ch * 8);
            }
            if (pair) {
                const __nv_bfloat16* B1p = Bl + (size_t)koff * ldb;
#pragma unroll
                for (int h = 0; h < 2; h++) {
                    const int r = tb_row + h * 16;
                    CP_ASYNC16(sB0 + BTILE + bo + ((uint32_t)r * BROW + tb_ch * 8) * 2,
                               B1p + (size_t)r * ldb + tb_ch * 8);
                }
            }
        } else {
            const __nv_bfloat16* B0p = Bh + koff;
#pragma unroll
            for (int h = 0; h < 2; h++) {
                const int r = lrow + h * 64;
                CP_ASYNC16(sB0 + bo + ((uint32_t)r * SROW + lchunk * 8) * 2,
                           B0p + (size_t)r * ldb + lchunk * 8);
            }
            if (pair) {
                const __nv_bfloat16* B1p = Bl + koff;
#pragma unroll
                for (int h = 0; h < 2; h++) {
                    const int r = lrow + h * 64;
                    CP_ASYNC16(sB0 + BTILE + bo + ((uint32_t)r * SROW + lchunk * 8) * 2,
                               B1p + (size_t)r * ldb + lchunk * 8);
                }
            }
        }
    };

    load_tiles(0, c0); CP_COMMIT();
    if (c0 + 1 < c1) load_tiles(1, c0 + 1);
    CP_COMMIT();

    int st = 0;
    int ld = 2;
    for (int c = c0; c < c1; c++) {
        CP_WAIT(STAGES - 2);
        __syncthreads();

        const uint32_t bo = (uint32_t)st * STAGE_B;
        const bool pair = !THREE || (c < NC1);
#pragma unroll
        for (int ks = 0; ks < 2; ks++) {
            uint32_t afr[4][4];
#pragma unroll
            for (int mt = 0; mt < 4; mt++)
                ldsm_x4(afr[mt], a_addr0 + bo + mt * (16 * SROW * 2) + ks * 32);
            uint32_t bfr[2][4];
            if (TRANSB) {
#pragma unroll
                for (int p = 0; p < 2; p++)
                    ldsm_x4_trans(bfr[p], b_addr_tr + bo + ks * (16 * BROW * 2) + p * 32);
            } else {
#pragma unroll
                for (int p = 0; p < 2; p++)
                    ldsm_x4(bfr[p], b_addr_nt + bo + p * (16 * SROW * 2) + ks * 32);
            }
#pragma unroll
            for (int mt = 0; mt < 4; mt++)
#pragma unroll
                for (int nt = 0; nt < 4; nt++)
                    mma16816(acc[mt][nt],
                             afr[mt][0], afr[mt][1], afr[mt][2], afr[mt][3],
                             bfr[nt >> 1][(nt & 1) * 2], bfr[nt >> 1][(nt & 1) * 2 + 1]);
            if (pair) {
                if (TRANSB) {
#pragma unroll
                    for (int p = 0; p < 2; p++)
                        ldsm_x4_trans(bfr[p], b_addr_tr + BTILE + bo + ks * (16 * BROW * 2) + p * 32);
                } else {
#pragma unroll
                    for (int p = 0; p < 2; p++)
                        ldsm_x4(bfr[p], b_addr_nt + BTILE + bo + p * (16 * SROW * 2) + ks * 32);
                }
#pragma unroll
                for (int mt = 0; mt < 4; mt++)
#pragma unroll
                    for (int nt = 0; nt < 4; nt++)
                        mma16816(acc[mt][nt],
                                 afr[mt][0], afr[mt][1], afr[mt][2], afr[mt][3],
                                 bfr[nt >> 1][(nt & 1) * 2], bfr[nt >> 1][(nt & 1) * 2 + 1]);
            }
        }

        const int nxt = c + 2;
        if (nxt < c1) load_tiles(ld, nxt);
        CP_COMMIT();
        st = (st == STAGES - 1) ? 0 : st + 1;
        ld = (ld == STAGES - 1) ? 0 : ld + 1;
    }

    // epilogue
    float* Cb = C + (size_t)s_k * strideS + bz * strideC;
    const int mb = m0 + wm * 64;
    const int nb = n0 + wn * 32;
#pragma unroll
    for (int mt = 0; mt < 4; mt++) {
#pragma unroll
        for (int nt = 0; nt < 4; nt++) {
            const int r  = mb + mt * 16 + (lane >> 2);
            const int cc = nb + nt * 8 + (lane & 3) * 2;
            if (REDC) {
                float* p0 = &Cb[(size_t)r * ldc + cc];
                float* p1 = &Cb[(size_t)(r + 8) * ldc + cc];
                REDG_ADD_F32(p0,     acc[mt][nt][0]);
                REDG_ADD_F32(p0 + 1, acc[mt][nt][1]);
                REDG_ADD_F32(p1,     acc[mt][nt][2]);
                REDG_ADD_F32(p1 + 1, acc[mt][nt][3]);
            } else {
                *(float2*)&Cb[(size_t)r * ldc + cc] =
                    make_float2(acc[mt][nt][0], acc[mt][nt][1]);
                *(float2*)&Cb[(size_t)(r + 8) * ldc + cc] =
                    make_float2(acc[mt][nt][2], acc[mt][nt][3]);
            }
        }
    }
}

// ---------------------------------------------------------------------------
// Split-K reduce for py: py = part0 + part1 + bias -> bf16 hi only
// ---------------------------------------------------------------------------
__global__ __launch_bounds__(256)
void reduce_bias_split_py(const float* __restrict__ Pb) {
    const size_t base = ((size_t)blockIdx.x * 256 + threadIdx.x) * 16;
    const float* p0 = g_part + base;
    const float* p1 = p0 + (size_t)BB * SEQ * DM;
    const int nb = (int)(base & (DM - 1));
    float4 a[4], b[4], c[4];
#pragma unroll
    for (int i = 0; i < 4; i++) a[i] = *(const float4*)(p0 + i * 4);
#pragma unroll
    for (int i = 0; i < 4; i++) b[i] = *(const float4*)(p1 + i * 4);
#pragma unroll
    for (int i = 0; i < 4; i++) c[i] = __ldg((const float4*)(Pb + nb + i * 4));
#pragma unroll
    for (int i = 0; i < 2; i++) {
        union { unsigned short us[8]; uint4 u; } H;
#pragma unroll
        for (int q = 0; q < 2; q++) {
            const int k = i * 2 + q;
            H.us[q*4+0] = __bfloat16_as_ushort(__float2bfloat16(a[k].x + b[k].x + c[k].x));
            H.us[q*4+1] = __bfloat16_as_ushort(__float2bfloat16(a[k].y + b[k].y + c[k].y));
            H.us[q*4+2] = __bfloat16_as_ushort(__float2bfloat16(a[k].z + b[k].z + c[k].z));
            H.us[q*4+3] = __bfloat16_as_ushort(__float2bfloat16(a[k].w + b[k].w + c[k].w));
        }
        *(uint4*)(g_py_hi + base + i * 8) = H.u;
    }
}

// ---------------------------------------------------------------------------
// Masked softmax in-place + fused bf16 hi/lo split (shuffle reductions)
// ---------------------------------------------------------------------------
__global__ __launch_bounds__(256)
void softmax_mask_split(float* __restrict__ a,
                        const int* __restrict__ x) {
    const int row = blockIdx.x;
    const int b = row >> 7;
    float* p = a + (size_t)row * SRC;
    const int* xb = x + b * SRC;
    const int t = threadIdx.x;
    const int lane = t & 31, wid = t >> 5;

    float v[4];
    float mx = -1e30f;
#pragma unroll
    for (int i = 0; i < 4; i++) {
        const int col = t + i * 256;
        float val = p[col];
        if (__ldg(&xb[col]) == 0) val -= 1e9f;
        v[i] = val;
        mx = fmaxf(mx, val);
    }
    __shared__ float wred[16];
#pragma unroll
    for (int off = 16; off > 0; off >>= 1)
        mx = fmaxf(mx, __shfl_xor_sync(0xffffffffu, mx, off));
    if (lane == 0) wred[wid] = mx;
    __syncthreads();
    mx = wred[0];
#pragma unroll
    for (int w = 1; w < 8; w++) mx = fmaxf(mx, wred[w]);

    float sum = 0.f;
#pragma unroll
    for (int i = 0; i < 4; i++) { v[i] = __expf(v[i] - mx); sum += v[i]; }
#pragma unroll
    for (int off = 16; off > 0; off >>= 1)
        sum += __shfl_xor_sync(0xffffffffu, sum, off);
    if (lane == 0) wred[8 + wid] = sum;
    __syncthreads();
    sum = wred[8];
#pragma unroll
    for (int w = 1; w < 8; w++) sum += wred[8 + w];

    const float inv = 1.0f / sum;
    unsigned short* ah = (unsigned short*)g_a_hi + (size_t)row * SRC;
    unsigned short* al = (unsigned short*)g_a_lo + (size_t)row * SRC;
#pragma unroll
    for (int i = 0; i < 4; i++) {
        const int col = t + i * 256;
        const float val = v[i] * inv;
        p[col] = val;
        unsigned short h, l;
        split2(val, h, l);
        ah[col] = h; al[col] = l;
    }
}

// ---------------------------------------------------------------------------
extern "C" void kernel_launch(void* const* d_in, const int* in_sizes, int n_in,
                              void* d_out, int out_size) {
    const int*   x   = (const int*)  d_in[0];   // [32, 1024]
    const int*   yc  = (const int*)  d_in[1];   // [32, 640]
    const float* F   = (const float*)d_in[2];   // [32000, 512]
    const float* G   = (const float*)d_in[3];   // [32000, 512]
    const float* Pw  = (const float*)d_in[4];   // [2560, 512]
    const float* Pb  = (const float*)d_in[5];   // [512]

    float* out   = (float*)d_out;                       // [32,128,512]
    float* a_out = out + (size_t)BB * SEQ * DM;         // [32,128,1024]

    constexpr int SMEM_NT = STAGES * (ATILE_B + 2 * BTILE_NT);   // 92160
    constexpr int SMEM_TR = STAGES * (ATILE_B + 2 * BTILE_TR);   // 82944
    cudaFuncSetAttribute(mma_gemm_kernel<KPY, false, false, false>,
                         cudaFuncAttributeMaxDynamicSharedMemorySize, SMEM_NT);
    cudaFuncSetAttribute(mma_gemm_kernel<DM, false, false, false>,
                         cudaFuncAttributeMaxDynamicSharedMemorySize, SMEM_NT);
    cudaFuncSetAttribute(mma_gemm_kernel<SRC, true, true, true>,
                         cudaFuncAttributeMaxDynamicSharedMemorySize, SMEM_TR);

    __nv_bfloat16 *xe_hi, *xe_lo, *yce_hi, *pwt_hi, *pwt_lo, *py_hi, *a_hi, *a_lo;
    float* part;
    cudaGetSymbolAddress((void**)&xe_hi,  g_xe_hi);
    cudaGetSymbolAddress((void**)&xe_lo,  g_xe_lo);
    cudaGetSymbolAddress((void**)&yce_hi, g_yce_hi);
    cudaGetSymbolAddress((void**)&pwt_hi, g_pwt_hi);
    cudaGetSymbolAddress((void**)&pwt_lo, g_pwt_lo);
    cudaGetSymbolAddress((void**)&py_hi,  g_py_hi);
    cudaGetSymbolAddress((void**)&a_hi,   g_a_hi);
    cudaGetSymbolAddress((void**)&a_lo,   g_a_lo);
    cudaGetSymbolAddress((void**)&part,   g_part);

    const size_t PART_S = (size_t)BB * SEQ * DM;

    // 1) fused: gather+split-hi yce, transpose+split P_w, zero-init out region
    prep_fused<<<YCE_BLOCKS + PWT_BLOCKS + ZOUT_BLOCKS, 256>>>(yc, G, Pw, out);
    // 2) py partials (2-term, split-K=2) + piggybacked xe gather on z==2
    mma_gemm_kernel<KPY, false, false, false><<<dim3(DM / 128, (BB * SEQ) / 128, 3), 256, SMEM_NT>>>(
        yce_hi, yce_hi, 0, KPY,
        pwt_hi, pwt_lo, 0, KPY,
        part, 0, DM, 2, PART_S, 2, x, F);
    // 3) reduce + bias + split -> py hi
    reduce_bias_split_py<<<(BB * SEQ * DM) / (256 * 16), 256>>>(Pb);
    // 4) logits (2-term): a[b,s,x] = py[b,s,:] . xe[b,x,:]   (M=128, N=1024, K=512)
    mma_gemm_kernel<DM, false, false, false><<<dim3(SRC / 128, 1, BB), 256, SMEM_NT>>>(
        py_hi, py_hi, (size_t)SEQ * DM, DM,
        xe_hi, xe_lo, (size_t)SRC * DM, DM,
        a_out, (size_t)SEQ * SRC, SRC, 1, 0, BB, nullptr, nullptr);
    // 5) masked softmax + split
    softmax_mask_split<<<BB * SEQ, 256>>>(a_out, x);
    // 6) out (3-term, split-K=2 via RED accumulation, trans-B): M=128, N=512, K=1024
    mma_gemm_kernel<SRC, true, true, true><<<dim3(DM / 128, 1, BB * 2), 256, SMEM_TR>>>(
        a_hi, a_lo, (size_t)SEQ * SRC, SRC,
        xe_hi, xe_lo, (size_t)SRC * DM, DM,
        out, (size_t)SEQ * DM, DM, 2, 0, BB * 2, nullptr, nullptr);
}

// round 13
// speedup vs baseline: 5.4879x; 1.1628x over previous
#include <cuda_runtime.h>
#include <cuda_bf16.h>
#include <cstdint>

// Problem constants
#define BB   32
#define SRC  1024
#define SEQ  128
#define CTX  5
#define DM   512
#define KPY  (CTX*DM)   // 2560

// ---------------------------------------------------------------------------
// Scratch (device globals; no allocations allowed)
// ---------------------------------------------------------------------------
__device__ __nv_bfloat16 g_xe_hi [(size_t)BB*SRC*DM];
__device__ __nv_bfloat16 g_xe_lo [(size_t)BB*SRC*DM];
__device__ __nv_bfloat16 g_yce_hi[(size_t)BB*SEQ*KPY];
__device__ __nv_bfloat16 g_pwt_hi[(size_t)DM*KPY];
__device__ __nv_bfloat16 g_py_hi [(size_t)BB*SEQ*DM];
__device__ __nv_bfloat16 g_a_hi  [(size_t)BB*SEQ*SRC];
__device__ __nv_bfloat16 g_a_lo  [(size_t)BB*SEQ*SRC];
__device__ float         g_part  [(size_t)2*BB*SEQ*DM];   // split-K partials (py)

// ---------------------------------------------------------------------------
// Helpers
// ---------------------------------------------------------------------------
__device__ __forceinline__ uint32_t smem_to_u32(const void* p) {
    uint32_t a;
    asm("{ .reg .u64 t; cvta.to.shared.u64 t, %1; cvt.u32.u64 %0, t; }"
        : "=r"(a) : "l"(p));
    return a;
}

#define CP_ASYNC16(dst, src) \
    asm volatile("cp.async.cg.shared.global [%0], [%1], 16;" \
                 :: "r"(dst), "l"(src) : "memory")
#define CP_COMMIT() asm volatile("cp.async.commit_group;" ::: "memory")
#define CP_WAIT(N)  asm volatile("cp.async.wait_group %0;" :: "n"(N) : "memory")

#define REDG_ADD_F32(addr, val) \
    asm volatile("red.global.add.f32 [%0], %1;" :: "l"(addr), "f"(val) : "memory")

__device__ __forceinline__ void ldsm_x4(uint32_t r[4], uint32_t addr) {
    asm volatile("ldmatrix.sync.aligned.m8n8.x4.shared.b16 {%0,%1,%2,%3}, [%4];"
                 : "=r"(r[0]), "=r"(r[1]), "=r"(r[2]), "=r"(r[3]) : "r"(addr));
}
__device__ __forceinline__ void ldsm_x4_trans(uint32_t r[4], uint32_t addr) {
    asm volatile("ldmatrix.sync.aligned.m8n8.x4.trans.shared.b16 {%0,%1,%2,%3}, [%4];"
                 : "=r"(r[0]), "=r"(r[1]), "=r"(r[2]), "=r"(r[3]) : "r"(addr));
}

__device__ __forceinline__ void mma16816(float c[4],
                                         uint32_t a0, uint32_t a1, uint32_t a2, uint32_t a3,
                                         uint32_t b0, uint32_t b1) {
    asm volatile("mma.sync.aligned.m16n8k16.row.col.f32.bf16.bf16.f32 "
                 "{%0,%1,%2,%3}, {%4,%5,%6,%7}, {%8,%9}, {%0,%1,%2,%3};"
                 : "+f"(c[0]), "+f"(c[1]), "+f"(c[2]), "+f"(c[3])
                 : "r"(a0), "r"(a1), "r"(a2), "r"(a3), "r"(b0), "r"(b1));
}

// fp32 -> (bf16 hi, bf16 lo) split
__device__ __forceinline__ void split2(float v, unsigned short& h, unsigned short& l) {
    __nv_bfloat16 hb = __float2bfloat16(v);
    __nv_bfloat16 lb = __float2bfloat16(v - __bfloat162float(hb));
    h = __bfloat16_as_ushort(hb);
    l = __bfloat16_as_ushort(lb);
}

// ---------------------------------------------------------------------------
// Fused prep: [0, YCE) gather+bf16 yce; [YCE, YCE+PWT) pwt transpose (hi only);
// [YCE+PWT, +ZOUT) zero-init d_out's out region (for RED accumulation).
// ---------------------------------------------------------------------------
#define YCE_BLOCKS (BB * SEQ * CTX / 4)      // 5120
#define PWT_BLOCKS ((KPY / 64) * (DM / 64))  // 320
#define ZOUT_BLOCKS ((BB * SEQ * DM) / 4096) // 512

__global__ __launch_bounds__(256)
void prep_fused(const int* __restrict__ yc, const float* __restrict__ G,
                const float* __restrict__ Pw, float* __restrict__ out_zero) {
    __shared__ float s[64][65];
    const int bid = blockIdx.x;
    const int t = threadIdx.x;

    if (bid < YCE_BLOCKS) {
        const int c = bid % CTX;
        const int m = (bid / CTX) * 4 + (t >> 6);
        const int col8 = (t & 63) * 8;
        const int tok = __ldg(&yc[m * CTX + c]);
        const float* src = G + (size_t)tok * DM + col8;
        float4 a = __ldg((const float4*)src);
        float4 b = __ldg((const float4*)(src + 4));
        float v[8] = {a.x, a.y, a.z, a.w, b.x, b.y, b.z, b.w};
        union { unsigned short us[8]; uint4 u; } H;
#pragma unroll
        for (int i = 0; i < 8; i++)
            H.us[i] = __bfloat16_as_ushort(__float2bfloat16(v[i]));
        *(uint4*)(g_yce_hi + (size_t)m * KPY + c * DM + col8) = H.u;
    } else if (bid < YCE_BLOCKS + PWT_BLOCKS) {
        const int j = bid - YCE_BLOCKS;
        const int k0 = (j % (KPY / 64)) * 64;
        const int n0 = (j / (KPY / 64)) * 64;
        const int tx = t & 31, ty = t >> 5;
#pragma unroll
        for (int i = 0; i < 8; i++) {
            const int r = ty + i * 8;
            float2 v = *(const float2*)(Pw + (size_t)(k0 + r) * DM + n0 + tx * 2);
            s[r][tx * 2] = v.x; s[r][tx * 2 + 1] = v.y;
        }
        __syncthreads();
#pragma unroll
        for (int i = 0; i < 8; i++) {
            const int nr = ty + i * 8;
            unsigned short h0 = __bfloat16_as_ushort(__float2bfloat16(s[tx * 2][nr]));
            unsigned short h1 = __bfloat16_as_ushort(__float2bfloat16(s[tx * 2 + 1][nr]));
            const size_t off = (size_t)(n0 + nr) * KPY + k0 + tx * 2;
            *(unsigned*)((unsigned short*)g_pwt_hi + off) = (unsigned)h0 | ((unsigned)h1 << 16);
        }
    } else {
        const int j = bid - YCE_BLOCKS - PWT_BLOCKS;
        float* p = out_zero + (size_t)j * 4096 + t * 16;
        const uint4 z = make_uint4(0u, 0u, 0u, 0u);
#pragma unroll
        for (int q = 0; q < 4; q++) *(uint4*)(p + q * 4) = z;
    }
}

// ---------------------------------------------------------------------------
// mma.sync GEMM.
// MODE 1: 1-term  A_hi x B_hi  (both effectively bf16)
// MODE 3: 3-term  A' = [Ahi|Ahi|Alo], B' = [Bhi|Blo|Bhi]
// REDC=true: epilogue accumulates into C via red.global.add.f32 (C pre-zeroed)
// CTA tile 128x128, BK=32, 8 warps, m16n8k16, 3-stage cp.async.
// Extra z-planes (z >= zmain) run an independent xe gather+split (overlap).
// ---------------------------------------------------------------------------
#define SROW 40
#define BROW 136
#define ATILE_B (128 * SROW * 2)   // 10240
#define BTILE_NT (128 * SROW * 2)  // 10240
#define BTILE_TR (32 * BROW * 2)   // 8704
#define STAGES 3

template<int K, bool TRANSB, int MODE, bool REDC>
__global__ __launch_bounds__(256, 2)
void mma_gemm_kernel(const __nv_bfloat16* __restrict__ Ahi, const __nv_bfloat16* __restrict__ Alo,
                     size_t strideA, int lda,
                     const __nv_bfloat16* __restrict__ Bhi, const __nv_bfloat16* __restrict__ Blo,
                     size_t strideB, int ldb,
                     float* __restrict__ C, size_t strideC, int ldc,
                     int ksplit, size_t strideS,
                     int zmain, const int* __restrict__ gx, const float* __restrict__ gF) {
    const int tid = threadIdx.x;
    const int z   = blockIdx.z;

    // ---- piggyback plane: gather + split xe (independent of GEMM inputs) ----
    if (z >= zmain) {
        const int gid  = blockIdx.y * gridDim.x + blockIdx.x;   // 0..127
        const int rsub = tid >> 6;
        const int col8 = (tid & 63) * 8;
        const int rbase = gid * 256;
#pragma unroll 4
        for (int rr = 0; rr < 64; rr++) {
            const int row = rbase + rr * 4 + rsub;
            const int tok = __ldg(&gx[row]);
            const float* src = gF + (size_t)tok * DM + col8;
            float4 a = __ldg((const float4*)src);
            float4 b = __ldg((const float4*)(src + 4));
            float v[8] = {a.x, a.y, a.z, a.w, b.x, b.y, b.z, b.w};
            union { unsigned short us[8]; uint4 u; } H, L;
#pragma unroll
            for (int i = 0; i < 8; i++) split2(v[i], H.us[i], L.us[i]);
            *(uint4*)(g_xe_hi + (size_t)row * DM + col8) = H.u;
            *(uint4*)(g_xe_lo + (size_t)row * DM + col8) = L.u;
        }
        return;
    }

    constexpr int BTILE   = TRANSB ? BTILE_TR : BTILE_NT;
    constexpr int BSLOTS  = (MODE == 1) ? 1 : 2;
    constexpr int STAGE_B = ATILE_B + BSLOTS * BTILE;
    constexpr int NC1 = K / 32;
    constexpr int NCT = (MODE == 3) ? 2 * NC1 : NC1;
    constexpr int SP  = (MODE == 3) ? (3 * NC1) / 4 : NC1 / 2;

    extern __shared__ __align__(16) unsigned char smbuf[];
    const uint32_t s_base = smem_to_u32(smbuf);
    const uint32_t sA  = s_base;
    const uint32_t sB0 = s_base + ATILE_B;

    const int lane = tid & 31;
    const int wid  = tid >> 5;
    const int wm   = wid & 1;
    const int wn   = wid >> 1;
    const int quad = lane >> 3;
    const int l8   = lane & 7;

    const int m0 = blockIdx.y * 128;
    const int n0 = blockIdx.x * 128;
    const int s_k = (ksplit == 2) ? (z & 1) : 0;
    const size_t bz = (ksplit == 2) ? (z >> 1) : z;

    const __nv_bfloat16* Ah = Ahi + bz * strideA + (size_t)m0 * lda;
    const __nv_bfloat16* Al = Alo + bz * strideA + (size_t)m0 * lda;
    const __nv_bfloat16* Bh;
    const __nv_bfloat16* Bl;
    if (TRANSB) { Bh = Bhi + bz * strideB + n0; Bl = Blo + bz * strideB + n0; }
    else        { Bh = Bhi + bz * strideB + (size_t)n0 * ldb;
                  Bl = Blo + bz * strideB + (size_t)n0 * ldb; }

    const int lrow   = tid >> 2;
    const int lchunk = tid & 3;
    const int tb_row = tid >> 4;
    const int tb_ch  = tid & 15;

    const uint32_t a_addr0 = sA + ((uint32_t)(wm * 64 + (quad & 1) * 8 + l8) * SROW
                                   + (quad >> 1) * 8) * 2;
    const uint32_t b_addr_nt = sB0 + ((uint32_t)(wn * 32 + (quad >> 1) * 8 + l8) * SROW
                                      + (quad & 1) * 8) * 2;
    const uint32_t b_addr_tr = sB0 + ((uint32_t)((quad & 1) * 8 + l8) * BROW
                                      + wn * 32 + (quad >> 1) * 8) * 2;

    float acc[4][4][4];
#pragma unroll
    for (int i = 0; i < 4; i++)
#pragma unroll
        for (int j = 0; j < 4; j++)
#pragma unroll
            for (int r = 0; r < 4; r++) acc[i][j][r] = 0.f;

    const int c0 = (s_k == 0) ? 0 : SP;
    const int c1 = (ksplit == 2) ? ((s_k == 0) ? SP : NCT) : NCT;

    auto load_tiles = [&](int stage, int c) {
        const uint32_t bo = (uint32_t)stage * STAGE_B;
        const bool pair = (MODE == 3) && (c < NC1);        // B_lo slot active?
        const bool useAlo = (MODE == 3) && (c >= NC1);
        const int koff = ((MODE == 3 && c >= NC1) ? c - NC1 : c) * 32;
        const __nv_bfloat16* Ap = (useAlo ? Al : Ah) + koff;
#pragma unroll
        for (int h = 0; h < 2; h++) {
            const int r = lrow + h * 64;
            CP_ASYNC16(sA + bo + ((uint32_t)r * SROW + lchunk * 8) * 2,
                       Ap + (size_t)r * lda + lchunk * 8);
        }
        if (TRANSB) {
            const __nv_bfloat16* B0p = Bh + (size_t)koff * ldb;
#pragma unroll
            for (int h = 0; h < 2; h++) {
                const int r = tb_row + h * 16;
                CP_ASYNC16(sB0 + bo + ((uint32_t)r * BROW + tb_ch * 8) * 2,
                           B0p + (size_t)r * ldb + tb_ch * 8);
            }
            if (pair) {
                const __nv_bfloat16* B1p = Bl + (size_t)koff * ldb;
#pragma unroll
                for (int h = 0; h < 2; h++) {
                    const int r = tb_row + h * 16;
                    CP_ASYNC16(sB0 + BTILE + bo + ((uint32_t)r * BROW + tb_ch * 8) * 2,
                               B1p + (size_t)r * ldb + tb_ch * 8);
                }
            }
        } else {
            const __nv_bfloat16* B0p = Bh + koff;
#pragma unroll
            for (int h = 0; h < 2; h++) {
                const int r = lrow + h * 64;
                CP_ASYNC16(sB0 + bo + ((uint32_t)r * SROW + lchunk * 8) * 2,
                           B0p + (size_t)r * ldb + lchunk * 8);
            }
            if (pair) {
                const __nv_bfloat16* B1p = Bl + koff;
#pragma unroll
                for (int h = 0; h < 2; h++) {
                    const int r = lrow + h * 64;
                    CP_ASYNC16(sB0 + BTILE + bo + ((uint32_t)r * SROW + lchunk * 8) * 2,
                               B1p + (size_t)r * ldb + lchunk * 8);
                }
            }
        }
    };

    load_tiles(0, c0); CP_COMMIT();
    if (c0 + 1 < c1) load_tiles(1, c0 + 1);
    CP_COMMIT();

    int st = 0;
    int ld = 2;
    for (int c = c0; c < c1; c++) {
        CP_WAIT(STAGES - 2);
        __syncthreads();

        const uint32_t bo = (uint32_t)st * STAGE_B;
        const bool pair = (MODE == 3) && (c < NC1);
#pragma unroll
        for (int ks = 0; ks < 2; ks++) {
            uint32_t afr[4][4];
#pragma unroll
            for (int mt = 0; mt < 4; mt++)
                ldsm_x4(afr[mt], a_addr0 + bo + mt * (16 * SROW * 2) + ks * 32);
            uint32_t bfr[2][4];
            if (TRANSB) {
#pragma unroll
                for (int p = 0; p < 2; p++)
                    ldsm_x4_trans(bfr[p], b_addr_tr + bo + ks * (16 * BROW * 2) + p * 32);
            } else {
#pragma unroll
                for (int p = 0; p < 2; p++)
                    ldsm_x4(bfr[p], b_addr_nt + bo + p * (16 * SROW * 2) + ks * 32);
            }
#pragma unroll
            for (int mt = 0; mt < 4; mt++)
#pragma unroll
                for (int nt = 0; nt < 4; nt++)
                    mma16816(acc[mt][nt],
                             afr[mt][0], afr[mt][1], afr[mt][2], afr[mt][3],
                             bfr[nt >> 1][(nt & 1) * 2], bfr[nt >> 1][(nt & 1) * 2 + 1]);
            if (pair) {
                if (TRANSB) {
#pragma unroll
                    for (int p = 0; p < 2; p++)
                        ldsm_x4_trans(bfr[p], b_addr_tr + BTILE + bo + ks * (16 * BROW * 2) + p * 32);
                } else {
#pragma unroll
                    for (int p = 0; p < 2; p++)
                        ldsm_x4(bfr[p], b_addr_nt + BTILE + bo + p * (16 * SROW * 2) + ks * 32);
                }
#pragma unroll
                for (int mt = 0; mt < 4; mt++)
#pragma unroll
                    for (int nt = 0; nt < 4; nt++)
                        mma16816(acc[mt][nt],
                                 afr[mt][0], afr[mt][1], afr[mt][2], afr[mt][3],
                                 bfr[nt >> 1][(nt & 1) * 2], bfr[nt >> 1][(nt & 1) * 2 + 1]);
            }
        }

        const int nxt = c + 2;
        if (nxt < c1) load_tiles(ld, nxt);
        CP_COMMIT();
        st = (st == STAGES - 1) ? 0 : st + 1;
        ld = (ld == STAGES - 1) ? 0 : ld + 1;
    }

    // epilogue
    float* Cb = C + (size_t)s_k * strideS + bz * strideC;
    const int mb = m0 + wm * 64;
    const int nb = n0 + wn * 32;
#pragma unroll
    for (int mt = 0; mt < 4; mt++) {
#pragma unroll
        for (int nt = 0; nt < 4; nt++) {
            const int r  = mb + mt * 16 + (lane >> 2);
            const int cc = nb + nt * 8 + (lane & 3) * 2;
            if (REDC) {
                float* p0 = &Cb[(size_t)r * ldc + cc];
                float* p1 = &Cb[(size_t)(r + 8) * ldc + cc];
                REDG_ADD_F32(p0,     acc[mt][nt][0]);
                REDG_ADD_F32(p0 + 1, acc[mt][nt][1]);
                REDG_ADD_F32(p1,     acc[mt][nt][2]);
                REDG_ADD_F32(p1 + 1, acc[mt][nt][3]);
            } else {
                *(float2*)&Cb[(size_t)r * ldc + cc] =
                    make_float2(acc[mt][nt][0], acc[mt][nt][1]);
                *(float2*)&Cb[(size_t)(r + 8) * ldc + cc] =
                    make_float2(acc[mt][nt][2], acc[mt][nt][3]);
            }
        }
    }
}

// ---------------------------------------------------------------------------
// Split-K reduce for py: py = part0 + part1 + bias -> bf16 hi only
// ---------------------------------------------------------------------------
__global__ __launch_bounds__(256)
void reduce_bias_split_py(const float* __restrict__ Pb) {
    const size_t base = ((size_t)blockIdx.x * 256 + threadIdx.x) * 16;
    const float* p0 = g_part + base;
    const float* p1 = p0 + (size_t)BB * SEQ * DM;
    const int nb = (int)(base & (DM - 1));
    float4 a[4], b[4], c[4];
#pragma unroll
    for (int i = 0; i < 4; i++) a[i] = *(const float4*)(p0 + i * 4);
#pragma unroll
    for (int i = 0; i < 4; i++) b[i] = *(const float4*)(p1 + i * 4);
#pragma unroll
    for (int i = 0; i < 4; i++) c[i] = __ldg((const float4*)(Pb + nb + i * 4));
#pragma unroll
    for (int i = 0; i < 2; i++) {
        union { unsigned short us[8]; uint4 u; } H;
#pragma unroll
        for (int q = 0; q < 2; q++) {
            const int k = i * 2 + q;
            H.us[q*4+0] = __bfloat16_as_ushort(__float2bfloat16(a[k].x + b[k].x + c[k].x));
            H.us[q*4+1] = __bfloat16_as_ushort(__float2bfloat16(a[k].y + b[k].y + c[k].y));
            H.us[q*4+2] = __bfloat16_as_ushort(__float2bfloat16(a[k].z + b[k].z + c[k].z));
            H.us[q*4+3] = __bfloat16_as_ushort(__float2bfloat16(a[k].w + b[k].w + c[k].w));
        }
        *(uint4*)(g_py_hi + base + i * 8) = H.u;
    }
}

// ---------------------------------------------------------------------------
// Masked softmax in-place + fused bf16 hi/lo split (shuffle reductions)
// ---------------------------------------------------------------------------
__global__ __launch_bounds__(256)
void softmax_mask_split(float* __restrict__ a,
                        const int* __restrict__ x) {
    const int row = blockIdx.x;
    const int b = row >> 7;
    float* p = a + (size_t)row * SRC;
    const int* xb = x + b * SRC;
    const int t = threadIdx.x;
    const int lane = t & 31, wid = t >> 5;

    float v[4];
    float mx = -1e30f;
#pragma unroll
    for (int i = 0; i < 4; i++) {
        const int col = t + i * 256;
        float val = p[col];
        if (__ldg(&xb[col]) == 0) val -= 1e9f;
        v[i] = val;
        mx = fmaxf(mx, val);
    }
    __shared__ float wred[16];
#pragma unroll
    for (int off = 16; off > 0; off >>= 1)
        mx = fmaxf(mx, __shfl_xor_sync(0xffffffffu, mx, off));
    if (lane == 0) wred[wid] = mx;
    __syncthreads();
    mx = wred[0];
#pragma unroll
    for (int w = 1; w < 8; w++) mx = fmaxf(mx, wred[w]);

    float sum = 0.f;
#pragma unroll
    for (int i = 0; i < 4; i++) { v[i] = __expf(v[i] - mx); sum += v[i]; }
#pragma unroll
    for (int off = 16; off > 0; off >>= 1)
        sum += __shfl_xor_sync(0xffffffffu, sum, off);
    if (lane == 0) wred[8 + wid] = sum;
    __syncthreads();
    sum = wred[8];
#pragma unroll
    for (int w = 1; w < 8; w++) sum += wred[8 + w];

    const float inv = 1.0f / sum;
    unsigned short* ah = (unsigned short*)g_a_hi + (size_t)row * SRC;
    unsigned short* al = (unsigned short*)g_a_lo + (size_t)row * SRC;
#pragma unroll
    for (int i = 0; i < 4; i++) {
        const int col = t + i * 256;
        const float val = v[i] * inv;
        p[col] = val;
        unsigned short h, l;
        split2(val, h, l);
        ah[col] = h; al[col] = l;
    }
}

// ---------------------------------------------------------------------------
extern "C" void kernel_launch(void* const* d_in, const int* in_sizes, int n_in,
                              void* d_out, int out_size) {
    const int*   x   = (const int*)  d_in[0];   // [32, 1024]
    const int*   yc  = (const int*)  d_in[1];   // [32, 640]
    const float* F   = (const float*)d_in[2];   // [32000, 512]
    const float* G   = (const float*)d_in[3];   // [32000, 512]
    const float* Pw  = (const float*)d_in[4];   // [2560, 512]
    const float* Pb  = (const float*)d_in[5];   // [512]

    float* out   = (float*)d_out;                       // [32,128,512]
    float* a_out = out + (size_t)BB * SEQ * DM;         // [32,128,1024]

    constexpr int SMEM_NT1 = STAGES * (ATILE_B + BTILE_NT);      // 61440 (1-term)
    constexpr int SMEM_TR3 = STAGES * (ATILE_B + 2 * BTILE_TR);  // 82944 (3-term)
    cudaFuncSetAttribute(mma_gemm_kernel<KPY, false, 1, false>,
                         cudaFuncAttributeMaxDynamicSharedMemorySize, SMEM_NT1);
    cudaFuncSetAttribute(mma_gemm_kernel<DM, false, 1, false>,
                         cudaFuncAttributeMaxDynamicSharedMemorySize, SMEM_NT1);
    cudaFuncSetAttribute(mma_gemm_kernel<SRC, true, 3, true>,
                         cudaFuncAttributeMaxDynamicSharedMemorySize, SMEM_TR3);

    __nv_bfloat16 *xe_hi, *xe_lo, *yce_hi, *pwt_hi, *py_hi, *a_hi, *a_lo;
    float* part;
    cudaGetSymbolAddress((void**)&xe_hi,  g_xe_hi);
    cudaGetSymbolAddress((void**)&xe_lo,  g_xe_lo);
    cudaGetSymbolAddress((void**)&yce_hi, g_yce_hi);
    cudaGetSymbolAddress((void**)&pwt_hi, g_pwt_hi);
    cudaGetSymbolAddress((void**)&py_hi,  g_py_hi);
    cudaGetSymbolAddress((void**)&a_hi,   g_a_hi);
    cudaGetSymbolAddress((void**)&a_lo,   g_a_lo);
    cudaGetSymbolAddress((void**)&part,   g_part);

    const size_t PART_S = (size_t)BB * SEQ * DM;

    // 1) fused: gather+bf16 yce, transpose+bf16 P_w, zero-init out region
    prep_fused<<<YCE_BLOCKS + PWT_BLOCKS + ZOUT_BLOCKS, 256>>>(yc, G, Pw, out);
    // 2) py partials (1-term, split-K=2) + piggybacked xe gather on z==2
    mma_gemm_kernel<KPY, false, 1, false><<<dim3(DM / 128, (BB * SEQ) / 128, 3), 256, SMEM_NT1>>>(
        yce_hi, yce_hi, 0, KPY,
        pwt_hi, pwt_hi, 0, KPY,
        part, 0, DM, 2, PART_S, 2, x, F);
    // 3) reduce + bias -> py bf16
    reduce_bias_split_py<<<(BB * SEQ * DM) / (256 * 16), 256>>>(Pb);
    // 4) logits (1-term): a[b,s,x] = py[b,s,:] . xe[b,x,:]   (M=128, N=1024, K=512)
    mma_gemm_kernel<DM, false, 1, false><<<dim3(SRC / 128, 1, BB), 256, SMEM_NT1>>>(
        py_hi, py_hi, (size_t)SEQ * DM, DM,
        xe_hi, xe_hi, (size_t)SRC * DM, DM,
        a_out, (size_t)SEQ * SRC, SRC, 1, 0, BB, nullptr, nullptr);
    // 5) masked softmax + split
    softmax_mask_split<<<BB * SEQ, 256>>>(a_out, x);
    // 6) out (3-term, split-K=2 via RED accumulation, trans-B): M=128, N=512, K=1024
    mma_gemm_kernel<SRC, true, 3, true><<<dim3(DM / 128, 1, BB * 2), 256, SMEM_TR3>>>(
        a_hi, a_lo, (size_t)SEQ * SRC, SRC,
        xe_hi, xe_lo, (size_t)SRC * DM, DM,
        out, (size_t)SEQ * DM, DM, 2, 0, BB * 2, nullptr, nullptr);
}